// round 11
// baseline (speedup 1.0000x reference)
#include <cuda_runtime.h>
#include <math.h>
#include <limits.h>

#define MAXT 700000
#define MAXRUNS 64
#define NWALK (2*MAXRUNS)
#define CANDW 2048
#define MAXPK 16384
#define MAXOPS 8192
#define MAXC 256
#define MAXW 400
#define MS 4096
#define WIN 960
#define WTW 512
#define CEPS 1e-4f
#define GRID(n,b) (((n)+(b)-1)/(b))

__device__ float g_f0[MAXT];
__device__ float g_f0s[MAXT];
__device__ unsigned g_absbits;
__device__ int g_anygate;
__device__ unsigned g_minbits;
__device__ float g_median;
__device__ float g_factor32, g_mshift32;

__device__ int g_st0[MAXRUNS], g_en0[MAXRUNS], g_st1[MAXRUNS], g_en1[MAXRUNS];
__device__ int g_cs0, g_ce0, g_cs1, g_ce1;
__device__ int g_runL0[MAXRUNS], g_runR0[MAXRUNS], g_nruns0;
__device__ int g_runL1[MAXRUNS], g_runR1[MAXRUNS], g_nruns1;
__device__ int g_tail, g_copy;
__device__ int g_backup[MAXRUNS];

__device__ int g_wci[NWALK*CANDW];
__device__ int g_wcw[NWALK*CANDW];
__device__ int g_wcnt[NWALK];
__device__ int g_lastApp[MAXRUNS];

__device__ int g_cand[MAXPK];
__device__ int g_ncand, g_npk;
__device__ int g_peaks[MAXPK];

__device__ int g_opd[MAXOPS], g_opsrc[MAXOPS], g_opl[MAXOPS], g_opn[MAXOPS];
__device__ int g_nops;

__device__ __forceinline__ int pyslen(long start, long stop, long n) {
    if (start < 0) start += n; if (start < 0) start = 0; if (start > n) start = n;
    if (stop  < 0) stop  += n; if (stop  < 0) stop  = 0; if (stop  > n) stop  = n;
    long L = stop - start; return L > 0 ? (int)L : 0;
}
__device__ __forceinline__ int dev_lb(const int* a, int n, int v) {
    int lo = 0, hi = n;
    while (lo < hi) { int m = (lo+hi)>>1; if (a[m] < v) lo = m+1; else hi = m; }
    return lo;
}

// numpy FLOAT_pairwise_sum of squares, 4-lane cooperative, bit-exact.
// All 4 lanes of an aligned group call with identical (a, n); result valid on lane 0 of group.
__device__ float np_psq4(const float* a, int n, int lane) {
    if (n < 8) {
        float r = 0.f;
        for (int i = 0; i < n; i++) r = __fadd_rn(r, __fmul_rn(a[i], a[i]));
        return r;
    }
    if (n <= 128) {
        int nb = n - (n % 8);
        int c0 = 2*lane, c1 = 2*lane + 1;
        float ra = __fmul_rn(a[c0], a[c0]);
        float rb = __fmul_rn(a[c1], a[c1]);
        for (int i = 8; i < nb; i += 8) {
            ra = __fadd_rn(ra, __fmul_rn(a[i+c0], a[i+c0]));
            rb = __fadd_rn(rb, __fmul_rn(a[i+c1], a[i+c1]));
        }
        float u = __fadd_rn(ra, rb);
        float u1 = __shfl_down_sync(0xFFFFFFFFu, u, 1, 4);
        float t  = __fadd_rn(u, u1);
        float t2 = __shfl_down_sync(0xFFFFFFFFu, t, 2, 4);
        float res = __fadd_rn(t, t2);
        for (int i = nb; i < n; i++) res = __fadd_rn(res, __fmul_rn(a[i], a[i]));
        return res;
    }
    int n2 = n / 2; n2 -= n2 % 8;
    float L = np_psq4(a, n2, lane);
    float R = np_psq4(a + n2, n - n2, lane);
    return __fadd_rn(L, R);
}

__global__ void K_init() {
    int t = threadIdx.x;
    if (t == 0) {
        g_absbits = 0u; g_anygate = 0; g_minbits = 0xFFFFFFFFu; g_median = 0.f;
        g_cs0 = g_ce0 = g_cs1 = g_ce1 = 0; g_nruns0 = g_nruns1 = 0;
        g_tail = 0; g_copy = 0; g_ncand = 0; g_npk = 0; g_nops = 0;
    }
    for (int i = t; i < NWALK; i += blockDim.x) g_wcnt[i] = 0;
    for (int i = t; i < MAXRUNS; i += blockDim.x) g_lastApp[i] = INT_MIN;
}

__global__ void K_zero(float* out, int T) {
    int t = blockIdx.x*blockDim.x + threadIdx.x;
    if (t < T) out[t] = 0.f;
}

__global__ void K_absmax(const float* __restrict__ x, int T) {
    float m = 0.f;
    for (int i = blockIdx.x*blockDim.x + threadIdx.x; i < T; i += gridDim.x*blockDim.x)
        m = fmaxf(m, fabsf(x[i]));
    for (int o = 16; o; o >>= 1) m = fmaxf(m, __shfl_down_sync(0xFFFFFFFFu, m, o));
    if ((threadIdx.x & 31) == 0) atomicMax(&g_absbits, __float_as_uint(m));
}

__global__ void K_median(const float* __restrict__ p, int S, const int* __restrict__ stepsPtr) {
    __shared__ float buf[MS];
    __shared__ int sh_np, sh_any;
    int tid = threadIdx.x;
    if (tid == 0) { sh_np = 0; sh_any = 0; }
    __syncthreads();
    int cany = 0;
    for (int j = tid; j < S && j < MS; j += 512) {
        float v = p[j];
        if (v > 0.f) { int idx = atomicAdd(&sh_np, 1); buf[idx] = v; }
        if (v > 1e-5f) cany = 1;
    }
    if (cany) atomicOr(&sh_any, 1);
    __syncthreads();
    int npos = sh_np;
    for (int i = npos + tid; i < MS; i += 512) buf[i] = INFINITY;
    __syncthreads();
    for (int k = 2; k <= MS; k <<= 1) {
        for (int j = k >> 1; j > 0; j >>= 1) {
            for (int i = tid; i < MS; i += 512) {
                int ixj = i ^ j;
                if (ixj > i) {
                    float a = buf[i], b = buf[ixj];
                    bool up = ((i & k) == 0);
                    if ((a > b) == up) { buf[i] = b; buf[ixj] = a; }
                }
            }
            __syncthreads();
        }
    }
    if (tid == 0) {
        g_anygate = sh_any;
        double fac = pow(2.0, (double)stepsPtr[0] / 12.0);
        g_factor32 = (float)fac;
        if (npos > 0) g_median = buf[(npos - 1) >> 1];
        g_mshift32 = (float)((double)g_median * fac);
    }
}

__global__ void K_interp(const float* __restrict__ p, int S, int T) {
    int t = blockIdx.x*blockDim.x + threadIdx.x;
    if (t >= T) return;
    double scale = (double)S / (double)T;
    double x = __dadd_rn(__dmul_rn(__dadd_rn((double)t, 0.5), scale), -0.5);
    if (x < 0.0) x = 0.0;
    double hi = (double)(S - 1);
    if (x > hi) x = hi;
    long i0 = (long)floor(x);
    long i1 = i0 + 1; if (i1 > (long)(S-1)) i1 = S - 1;
    float f = (float)__dsub_rn(x, (double)i0);
    g_f0[t] = __fadd_rn(__fmul_rn(p[i0], __fsub_rn(1.0f, f)), __fmul_rn(p[i1], f));
}

__global__ void K_shift(const float* __restrict__ prp, int T) {
    int t = blockIdx.x*blockDim.x + threadIdx.x;
    float res = 0.f;
    if (t < T) {
        float fs = __fmul_rn(g_f0[t], g_factor32);
        float m = g_mshift32;
        if (fs > 0.f) res = __fadd_rn(m, __fmul_rn(__fsub_rn(fs, m), prp[0]));
        g_f0s[t] = res;
    }
    unsigned mb = (t < T && res > 0.f) ? __float_as_uint(res) : 0xFFFFFFFFu;
    for (int o = 16; o; o >>= 1) mb = min(mb, __shfl_down_sync(0xFFFFFFFFu, mb, o));
    if ((threadIdx.x & 31) == 0 && mb != 0xFFFFFFFFu) atomicMin(&g_minbits, mb);
}

__global__ void K_mark(int T) {
    int t = blockIdx.x*blockDim.x + threadIdx.x;
    if (t >= T) return;
    if (g_f0[t] > 0.f) {
        bool pr = (t > 0) && (g_f0[t-1] > 0.f);
        bool nx = (t < T-1) && (g_f0[t+1] > 0.f);
        if (!pr) { int i = atomicAdd(&g_cs0,1); if (i < MAXRUNS) g_st0[i] = t; }
        if (!nx) { int i = atomicAdd(&g_ce0,1); if (i < MAXRUNS) g_en0[i] = t+1; }
    }
    if (g_f0s[t] > 0.f) {
        bool pr = (t > 0) && (g_f0s[t-1] > 0.f);
        bool nx = (t < T-1) && (g_f0s[t+1] > 0.f);
        if (!pr) { int i = atomicAdd(&g_cs1,1); if (i < MAXRUNS) g_st1[i] = t; }
        if (!nx) { int i = atomicAdd(&g_ce1,1); if (i < MAXRUNS) g_en1[i] = t+1; }
    }
}

__device__ void sort_small(int* a, int n) {
    for (int i = 1; i < n; i++) {
        int v = a[i], j = i-1;
        while (j >= 0 && a[j] > v) { a[j+1] = a[j]; j--; }
        a[j+1] = v;
    }
}

__global__ void K_sortruns() {
    if (threadIdx.x || blockIdx.x) return;
    {
        int ns = min(g_cs0, MAXRUNS), ne = min(g_ce0, MAXRUNS);
        sort_small(g_st0, ns); sort_small(g_en0, ne);
        int n = min(ns, ne), off = 0;
        if (n > 0 && g_st0[0] == 0) { g_st0[0] = 1; if (g_st0[0] >= g_en0[0]) off = 1; }
        int m = 0;
        for (int k = off; k < n; k++) { g_runL0[m] = g_st0[k]; g_runR0[m] = g_en0[k]; m++; }
        g_nruns0 = m;
    }
    {
        int ns = min(g_cs1, MAXRUNS), ne = min(g_ce1, MAXRUNS);
        sort_small(g_st1, ns); sort_small(g_en1, ne);
        int n = min(ns, ne), off = 0;
        if (n > 0 && g_st1[0] == 0) { g_st1[0] = 1; if (g_st1[0] >= g_en1[0]) off = 1; }
        int m = 0;
        for (int k = off; k < n; k++) { g_runL1[m] = g_st1[k]; g_runR1[m] = g_en1[k]; m++; }
        g_nruns1 = m;
    }
}

__global__ void K_backup(const float* __restrict__ sig, int T) {
    int run = blockIdx.x;
    if (run >= g_nruns0 || threadIdx.x != 0) return;
    int left = g_runL0[run], right = g_runR0[run];
    int middle = (left + right) / 2;
    double wd = __ddiv_rn(22050.0, (double)g_f0[middle]);
    long w = (wd > 2.0e9) ? 2000000000L : (long)wd;
    long s = (long)middle - w/2; if (s < 0) s = 0;
    long len = w; if (s + len > T) len = T - s;
    float mn = INFINITY, mx = -INFINITY; long imn = 0, imx = 0;
    for (long k = 0; k < len; k++) {
        float v = sig[s+k];
        if (v < mn) { mn = v; imn = k; }
        if (v > mx) { mx = v; imx = k; }
    }
    g_backup[run] = (mn == mx) ? middle
                  : (int)(s + ((fabs((double)mn) > fabs((double)mx)) ? imn : imx));
}

// Merged walk with contender-filtered exact correlation (warp-uniform pass 2).
__global__ __launch_bounds__(WTW) void K_walk(const float* __restrict__ sig, int T) {
    __shared__ float win[WIN];
    __shared__ float s_b[MAXW];
    __shared__ float s_q[MAXC], s_ma[MAXC], s_na[MAXC];
    __shared__ int   s_cl[MAXC];
    __shared__ int   sM;
    __shared__ float s_pv[WTW/32];
    __shared__ int   s_pi[WTW/32];
    __shared__ float sBV;
    __shared__ int sI, sStop;
    int b = blockIdx.x;
    int dir = (b < MAXRUNS) ? 1 : 0;
    int run = dir ? b : (b - MAXRUNS);
    if (run >= g_nruns0) return;
    int tid = threadIdx.x, lane4 = tid & 3, grp = tid >> 2, wrp = tid >> 5, wl = tid & 31;
    int left = g_runL0[run], right = g_runR0[run];
    double gp = (double)__uint_as_float(g_absbits);
    long base = (long)b * CANDW;
    int cnt = 0, lastApp = INT_MIN;
    if (tid == 0) { sI = g_backup[run]; sStop = 0; }
    __syncthreads();
    while (true) {
        int i = sI;
        double f0i = (double)g_f0[i];
        double fm = f0i > 60.0 ? f0i : 60.0;
        int w = (int)__ddiv_rn(22050.0, fm);
        int s = i - w/2; if (s < 0) s = 0;
        int cl, cr;
        if (dir) {
            cl = (int)__dadd_rn((double)i, __dmul_rn(0.3,  (double)w));
            cr = (int)__dadd_rn((double)i, __dmul_rn(0.75, (double)w));
        } else {
            int a1 = (int)__dsub_rn((double)i, __dmul_rn(1.75, (double)w)); cl = a1 > 0 ? a1 : 0;
            int a2 = (int)__dsub_rn((double)i, __dmul_rn(1.3,  (double)w)); cr = a2 > 0 ? a2 : 0;
        }
        int valid = 0, nc = 0, base0 = 0;
        if (!(cl == cr || (T - cl) < w)) {
            long hi = (long)cr + w; if (hi > T) hi = T;
            nc = (int)(hi - cl - w + 1);
            valid = (nc >= 1 && nc <= MAXC && w <= MAXW && s + w <= T);
        }
        if (valid) {
            base0 = min(s, cl);
            int e1 = s + w, e2 = cl + nc - 1 + w;
            int WL = (e1 > e2 ? e1 : e2) - base0;
            if (WL > WIN) valid = 0;
            else {
                if (tid == 0) sM = 0;
                for (int k = tid; k < WL; k += WTW) win[k] = sig[base0 + k];
                __syncthreads();
                if (wrp == 0) {
                    const float* rp = win + (s - base0);
                    float psq = np_psq4(rp, w, lane4);
                    float nb = __shfl_sync(0xFFFFFFFFu, psq, 0);
                    nb = fmaxf(__fsqrt_rn(nb), 1e-12f);
                    for (int k = wl; k < w; k += 32) s_b[k] = __fdiv_rn(rp[k], nb);
                }
                __syncthreads();
                const float* cb = win + (cl - base0);
                int w4 = w & ~3;
                // ---- pass 1: divide-free approx corr + na + maxabs (all lanes execute) ----
                for (int c0 = 0; c0 < nc; c0 += WTW/4) {
                    int c = c0 + grp;
                    int cc = c < nc ? c : nc - 1;
                    const float* ap = cb + cc;
                    float psq = np_psq4(ap, w, lane4);
                    float na = 0.f;
                    if (lane4 == 0) na = fmaxf(__fsqrt_rn(psq), 1e-12f);
                    float acc = 0.f, ma = 0.f;
                    for (int k = lane4; k < w4; k += 4) {
                        float v = ap[k];
                        ma = fmaxf(ma, fabsf(v));
                        acc = fmaf(v, s_b[k], acc);
                    }
                    float a1 = __shfl_down_sync(0xFFFFFFFFu, acc, 1, 4);
                    float ssum = __fadd_rn(acc, a1);
                    float a2 = __shfl_down_sync(0xFFFFFFFFu, ssum, 2, 4);
                    float res = __fadd_rn(ssum, a2);
                    float m1 = __shfl_down_sync(0xFFFFFFFFu, ma, 1, 4);
                    ma = fmaxf(ma, m1);
                    float m2 = __shfl_down_sync(0xFFFFFFFFu, ma, 2, 4);
                    ma = fmaxf(ma, m2);
                    if (lane4 == 0 && c < nc) {
                        for (int k = w4; k < w; k++) {
                            float v = ap[k];
                            ma = fmaxf(ma, fabsf(v));
                            res = fmaf(v, s_b[k], res);
                        }
                        s_q[cc] = __fdiv_rn(res, na);
                        s_ma[cc] = ma; s_na[cc] = na;
                    }
                }
                __syncthreads();
                // ---- max approx value ----
                {
                    float v = (tid < nc) ? s_q[tid] : -INFINITY;
                    for (int o = 16; o; o >>= 1)
                        v = fmaxf(v, __shfl_down_sync(0xFFFFFFFFu, v, o));
                    if (wl == 0) s_pv[wrp] = v;
                }
                __syncthreads();
                if (tid == 0) {
                    float bv = s_pv[0];
                    for (int q = 1; q < WTW/32; q++) bv = fmaxf(bv, s_pv[q]);
                    sBV = bv;
                }
                __syncthreads();
                // ---- compact contender list; demote non-contenders ----
                for (int c = tid; c < nc; c += WTW) {
                    if (s_q[c] >= sBV - CEPS) {
                        int sl = atomicAdd(&sM, 1);
                        s_cl[sl] = c;
                    } else {
                        s_q[c] = -INFINITY;
                    }
                }
                __syncthreads();
                int m = sM;
                // ---- pass 2: bit-exact corr for contenders; warp-uniform activation ----
                for (int j0 = 0; j0 < m; j0 += WTW/4) {
                    if (j0 + (wrp << 3) < m) {     // uniform across the warp
                        int ji = j0 + grp;
                        int jj = ji < m ? ji : m - 1;
                        int c = s_cl[jj];
                        const float* ap = cb + c;
                        float na = s_na[c];
                        float acc = 0.f;
                        for (int k = lane4; k < w4; k += 4)
                            acc = fmaf(__fdiv_rn(ap[k], na), s_b[k], acc);
                        float a1 = __shfl_down_sync(0xFFFFFFFFu, acc, 1, 4);
                        float ssum = __fadd_rn(acc, a1);
                        float a2 = __shfl_down_sync(0xFFFFFFFFu, ssum, 2, 4);
                        float res = __fadd_rn(ssum, a2);
                        if (lane4 == 0 && ji < m) {
                            for (int k = w4; k < w; k++)
                                res = fmaf(__fdiv_rn(ap[k], na), s_b[k], res);
                            s_q[c] = res;
                        }
                    }
                }
                __syncthreads();
                // ---- final argmax over exact values, first-occurrence ties ----
                {
                    float v = (tid < nc) ? s_q[tid] : -INFINITY;
                    int idx = tid;
                    for (int o = 16; o; o >>= 1) {
                        float vo = __shfl_down_sync(0xFFFFFFFFu, v, o);
                        int   io = __shfl_down_sync(0xFFFFFFFFu, idx, o);
                        if (vo > v || (vo == v && io < idx)) { v = vo; idx = io; }
                    }
                    if (wl == 0) { s_pv[wrp] = v; s_pi[wrp] = idx; }
                }
                __syncthreads();
            }
        }
        if (tid == 0) {
            double corr = -1.0, peak = 0.0;
            int stop = 0;
            if (valid) {
                float bv = s_pv[0]; int br = s_pi[0];
                for (int q = 1; q < WTW/32; q++)
                    if (s_pv[q] > bv || (s_pv[q] == bv && s_pi[q] < br)) { bv = s_pv[q]; br = s_pi[q]; }
                corr = (double)s_q[br];
                peak = (double)s_ma[br];
                i = i + (br + cl) - s;
            }
            bool neg1 = (corr == -1.0);
            if (dir) {
                if (neg1) i += w;
                if (i >= right) {
                    if (corr > 0.7 && peak > __dmul_rn(0.023333, gp)) {
                        if (cnt < CANDW) g_wci[base+cnt] = i;
                        cnt++; lastApp = i;
                    }
                    stop = 1;
                } else if (corr > 0.3 && (peak == 0.0 || peak > __dmul_rn(0.01, gp))) {
                    if (cnt < CANDW) g_wci[base+cnt] = i;
                    cnt++; lastApp = i;
                }
            } else {
                if (neg1) i -= w;
                if (i < left) {
                    if (corr > 0.7 && peak > __dmul_rn(0.023333, gp)) {
                        if (cnt < CANDW) { g_wci[base+cnt] = i; g_wcw[base+cnt] = w; }
                        cnt++;
                    }
                    stop = 1;
                } else if (corr > 0.3 && (peak == 0.0 || peak > __dmul_rn(0.01, gp))) {
                    if (cnt < CANDW) { g_wci[base+cnt] = i; g_wcw[base+cnt] = w; }
                    cnt++;
                }
            }
            sI = i; sStop = stop;
        }
        __syncthreads();
        if (sStop) break;
    }
    if (tid == 0) {
        g_wcnt[b] = min(cnt, CANDW);
        if (dir) g_lastApp[run] = lastApp;
    }
}

__global__ void K_filter() {
    __shared__ double sAR[MAXRUNS];
    int tid = threadIdx.x;
    int nr = g_nruns0;
    if (tid == 0) {
        double cur = -1e308;
        for (int r = 0; r < nr; r++) {
            sAR[r] = cur;
            if (g_lastApp[r] != INT_MIN) cur = (double)g_lastApp[r];
        }
    }
    __syncthreads();
    if (tid < nr) {
        long base = (long)(MAXRUNS + tid) * CANDW;
        int c = g_wcnt[MAXRUNS + tid], m = 0;
        double AR = sAR[tid];
        for (int j = 0; j < c; j++) {
            int i = g_wci[base + j], w = g_wcw[base + j];
            if (__dsub_rn((double)i, AR) > __dmul_rn(0.8, (double)w)) {
                g_wci[base + m] = i; m++;
            }
        }
        g_wcnt[MAXRUNS + tid] = m;
    }
}

__global__ void K_collect() {
    __shared__ int s_off[NWALK];
    int tid = threadIdx.x;
    if (tid == 0) {
        int acc = 0;
        for (int sl = 0; sl < NWALK; sl++) { s_off[sl] = acc; acc += g_wcnt[sl]; }
        g_ncand = min(acc, MAXPK);
    }
    __syncthreads();
    for (int sl = 0; sl < NWALK; sl++) {
        int c = g_wcnt[sl], o = s_off[sl];
        for (int j = tid; j < c; j += blockDim.x)
            if (o + j < MAXPK) g_cand[o+j] = g_wci[(long)sl*CANDW + j];
    }
}

__global__ void K_rank(int T) {
    int N = g_ncand;
    for (int j = blockIdx.x*blockDim.x + threadIdx.x; j < N; j += gridDim.x*blockDim.x) {
        int v = g_cand[j], rk = 0;
        for (int k = 0; k < N; k++) {
            int u = g_cand[k];
            rk += (u < v) || (u == v && k < j);
        }
        int cv = v; if (cv < 0) cv = 0; if (cv > T-1) cv = T-1;
        g_peaks[rk] = cv;
    }
    if (blockIdx.x == 0 && threadIdx.x == 0) g_npk = N;
}

__device__ int plan_run(int r, int T, double max_w, int write, int base) {
    int left_v = g_runL1[r], right_v = g_runR1[r];
    int prevR = (r == 0) ? 0 : g_runR1[r-1];
    int cnt = 0, npk = g_npk;
    if (prevR < left_v) {
        if (write && base+cnt < MAXOPS) {
            g_opd[base+cnt] = prevR; g_opsrc[base+cnt] = prevR;
            g_opl[base+cnt] = left_v - prevR; g_opn[base+cnt] = left_v - prevR;
        }
        cnt++;
    }
    while (left_v < right_v) {
        int q = dev_lb(g_peaks, npk, left_v), p;
        if (q == 0) p = 0;
        else if (q >= npk) p = dev_lb(g_peaks, npk, g_peaks[npk-1]);
        else {
            long d1 = (long)left_v - g_peaks[q-1], d2 = (long)g_peaks[q] - left_v;
            p = (d1 <= d2) ? dev_lb(g_peaks, npk, g_peaks[q-1]) : q;
        }
        double fv = (double)g_f0s[left_v];
        int period = (int)__ddiv_rn(22050.0, fv > 60.0 ? fv : 60.0);
        int left_w = period/2, right_w = period/2;
        if (p > 0) {
            long d = (long)g_peaks[p] - g_peaks[p-1];
            if ((double)d <= max_w) left_w = min((int)d, left_w);
        }
        if (p < npk-1) {
            long d = (long)g_peaks[p+1] - g_peaks[p];
            if ((double)d <= max_w) right_w = min((int)d, right_w);
        }
        int left_i = g_peaks[p] - left_w; if (left_i < 0) left_i = 0;
        int right_i = g_peaks[p] + right_w;
        int ival = (right_i - left_i) / 2;
        if (ival <= 0) break;
        long a = (long)left_v - ival;
        int seglen = min(pyslen(a, (long)left_v + ival, T),
                         pyslen(left_i, (long)left_i + 2L*ival, T));
        int Ld = pyslen(a, a + seglen, T);
        int Ls = pyslen(left_i, (long)left_i + seglen, T);
        int L = min(min(Ld, Ls), seglen);
        if (write && base+cnt < MAXOPS) {
            long as_ = a < 0 ? a + T : a;
            g_opd[base+cnt] = (int)as_; g_opsrc[base+cnt] = left_i;
            g_opl[base+cnt] = L; g_opn[base+cnt] = 2*ival;
        }
        cnt++;
        left_v += ival * 2;
    }
    return cnt;
}

__global__ void K_plan(int T) {
    __shared__ int s_cnt[MAXRUNS];
    __shared__ double s_maxw;
    int tid = threadIdx.x;
    if (tid == 0) {
        g_copy = (!g_anygate || g_npk == 0) ? 1 : 0;
        float mp = __uint_as_float(g_minbits);
        s_maxw = __ddiv_rn(27562.5, (double)mp);
        g_tail = 0; g_nops = 0;
    }
    __syncthreads();
    if (g_copy) return;
    int nr = g_nruns1;
    if (tid == 0 && nr > 0) g_tail = g_runR1[nr-1];
    if (tid < nr) s_cnt[tid] = plan_run(tid, T, s_maxw, 0, 0);
    __syncthreads();
    if (tid == 0) {
        int acc = 0;
        for (int r = 0; r < nr; r++) { int c = s_cnt[r]; s_cnt[r] = acc; acc += c; }
        g_nops = min(acc, MAXOPS);
    }
    __syncthreads();
    if (tid < nr) plan_run(tid, T, s_maxw, 1, s_cnt[tid]);
}

__global__ void K_apply(const float* __restrict__ snd, float* __restrict__ out, int T) {
    for (int b = blockIdx.x; b < g_nops; b += gridDim.x) {
        int d0 = g_opd[b], s0 = g_opsrc[b], L = g_opl[b], n = g_opn[b];
        for (int k = threadIdx.x; k < L; k += blockDim.x) {
            double ang = __ddiv_rn(__dmul_rn(6.283185307179586, (double)k), (double)n);
            float wf = (float)__dsub_rn(0.5, __dmul_rn(0.5, cos(ang)));
            atomicAdd(out + d0 + k, __fmul_rn(wf, snd[s0 + k]));
        }
    }
}

__global__ void K_tail(const float* __restrict__ snd, float* __restrict__ out, int T) {
    int t = blockIdx.x*blockDim.x + threadIdx.x;
    if (t >= T) return;
    if (g_copy || t >= g_tail) out[t] = snd[t];
}

extern "C" void kernel_launch(void* const* d_in, const int* in_sizes, int n_in,
                              void* d_out, int out_size) {
    const float* snd   = (const float*)d_in[0];
    const float* pitch = (const float*)d_in[1];
    const int*   steps = (const int*)d_in[2];
    const float* prng  = (const float*)d_in[3];
    float* out = (float*)d_out;
    int T = in_sizes[0];
    int S = in_sizes[1];

    K_init<<<1,256>>>();
    K_zero<<<GRID(T,256),256>>>(out, T);
    K_absmax<<<512,256>>>(snd, T);
    K_median<<<1,512>>>(pitch, S, steps);
    K_interp<<<GRID(T,256),256>>>(pitch, S, T);
    K_shift<<<GRID(T,256),256>>>(prng, T);
    K_mark<<<GRID(T,256),256>>>(T);
    K_sortruns<<<1,1>>>();
    K_backup<<<MAXRUNS,1>>>(snd, T);
    K_walk<<<NWALK,WTW>>>(snd, T);
    K_filter<<<1,64>>>();
    K_collect<<<1,256>>>();
    K_rank<<<64,256>>>(T);
    K_plan<<<1,64>>>(T);
    K_apply<<<2048,128>>>(snd, out, T);
    K_tail<<<GRID(T,256),256>>>(snd, out, T);
}

// round 12
// speedup vs baseline: 1.0108x; 1.0108x over previous
#include <cuda_runtime.h>
#include <math.h>
#include <limits.h>

#define MAXT 700000
#define MAXRUNS 64
#define NWALK (2*MAXRUNS)
#define CANDW 2048
#define MAXPK 16384
#define MAXOPS 8192
#define MAXC 256
#define MAXW 400
#define MS 4096
#define WIN 960
#define WTW 512
#define CEPS 1e-4f
#define GRID(n,b) (((n)+(b)-1)/(b))

__device__ float g_f0[MAXT];
__device__ float g_f0s[MAXT];
__device__ unsigned g_absbits;
__device__ int g_anygate;
__device__ unsigned g_minbits;
__device__ float g_median;
__device__ float g_factor32, g_mshift32;

__device__ int g_st0[MAXRUNS], g_en0[MAXRUNS], g_st1[MAXRUNS], g_en1[MAXRUNS];
__device__ int g_cs0, g_ce0, g_cs1, g_ce1;
__device__ int g_runL0[MAXRUNS], g_runR0[MAXRUNS], g_nruns0;
__device__ int g_runL1[MAXRUNS], g_runR1[MAXRUNS], g_nruns1;
__device__ int g_tail, g_copy;
__device__ int g_backup[MAXRUNS];

__device__ int g_wci[NWALK*CANDW];
__device__ int g_wcw[NWALK*CANDW];
__device__ int g_wcnt[NWALK];
__device__ int g_lastApp[MAXRUNS];

__device__ int g_cand[MAXPK];
__device__ int g_ncand, g_npk;
__device__ int g_peaks[MAXPK];

__device__ int g_opd[MAXOPS], g_opsrc[MAXOPS], g_opl[MAXOPS], g_opn[MAXOPS];
__device__ int g_nops;

__device__ __forceinline__ int pyslen(long start, long stop, long n) {
    if (start < 0) start += n; if (start < 0) start = 0; if (start > n) start = n;
    if (stop  < 0) stop  += n; if (stop  < 0) stop  = 0; if (stop  > n) stop  = n;
    long L = stop - start; return L > 0 ? (int)L : 0;
}
__device__ __forceinline__ int dev_lb(const int* a, int n, int v) {
    int lo = 0, hi = n;
    while (lo < hi) { int m = (lo+hi)>>1; if (a[m] < v) lo = m+1; else hi = m; }
    return lo;
}

// numpy FLOAT_pairwise_sum of squares, 4-lane cooperative, bit-exact.
__device__ float np_psq4(const float* a, int n, int lane) {
    if (n < 8) {
        float r = 0.f;
        for (int i = 0; i < n; i++) r = __fadd_rn(r, __fmul_rn(a[i], a[i]));
        return r;
    }
    if (n <= 128) {
        int nb = n - (n % 8);
        int c0 = 2*lane, c1 = 2*lane + 1;
        float ra = __fmul_rn(a[c0], a[c0]);
        float rb = __fmul_rn(a[c1], a[c1]);
        for (int i = 8; i < nb; i += 8) {
            ra = __fadd_rn(ra, __fmul_rn(a[i+c0], a[i+c0]));
            rb = __fadd_rn(rb, __fmul_rn(a[i+c1], a[i+c1]));
        }
        float u = __fadd_rn(ra, rb);
        float u1 = __shfl_down_sync(0xFFFFFFFFu, u, 1, 4);
        float t  = __fadd_rn(u, u1);
        float t2 = __shfl_down_sync(0xFFFFFFFFu, t, 2, 4);
        float res = __fadd_rn(t, t2);
        for (int i = nb; i < n; i++) res = __fadd_rn(res, __fmul_rn(a[i], a[i]));
        return res;
    }
    int n2 = n / 2; n2 -= n2 % 8;
    float L = np_psq4(a, n2, lane);
    float R = np_psq4(a + n2, n - n2, lane);
    return __fadd_rn(L, R);
}

__global__ void K_init() {
    int t = threadIdx.x;
    if (t == 0) {
        g_absbits = 0u; g_anygate = 0; g_minbits = 0xFFFFFFFFu; g_median = 0.f;
        g_cs0 = g_ce0 = g_cs1 = g_ce1 = 0; g_nruns0 = g_nruns1 = 0;
        g_tail = 0; g_copy = 0; g_ncand = 0; g_npk = 0; g_nops = 0;
    }
    for (int i = t; i < NWALK; i += blockDim.x) g_wcnt[i] = 0;
    for (int i = t; i < MAXRUNS; i += blockDim.x) g_lastApp[i] = INT_MIN;
}

__global__ void K_zero(float* out, int T) {
    int t = blockIdx.x*blockDim.x + threadIdx.x;
    if (t < T) out[t] = 0.f;
}

__global__ void K_absmax(const float* __restrict__ x, int T) {
    float m = 0.f;
    for (int i = blockIdx.x*blockDim.x + threadIdx.x; i < T; i += gridDim.x*blockDim.x)
        m = fmaxf(m, fabsf(x[i]));
    for (int o = 16; o; o >>= 1) m = fmaxf(m, __shfl_down_sync(0xFFFFFFFFu, m, o));
    if ((threadIdx.x & 31) == 0) atomicMax(&g_absbits, __float_as_uint(m));
}

__global__ void K_median(const float* __restrict__ p, int S, const int* __restrict__ stepsPtr) {
    __shared__ float buf[MS];
    __shared__ int sh_np, sh_any;
    int tid = threadIdx.x;
    if (tid == 0) { sh_np = 0; sh_any = 0; }
    __syncthreads();
    int cany = 0;
    for (int j = tid; j < S && j < MS; j += 512) {
        float v = p[j];
        if (v > 0.f) { int idx = atomicAdd(&sh_np, 1); buf[idx] = v; }
        if (v > 1e-5f) cany = 1;
    }
    if (cany) atomicOr(&sh_any, 1);
    __syncthreads();
    int npos = sh_np;
    for (int i = npos + tid; i < MS; i += 512) buf[i] = INFINITY;
    __syncthreads();
    for (int k = 2; k <= MS; k <<= 1) {
        for (int j = k >> 1; j > 0; j >>= 1) {
            for (int i = tid; i < MS; i += 512) {
                int ixj = i ^ j;
                if (ixj > i) {
                    float a = buf[i], b = buf[ixj];
                    bool up = ((i & k) == 0);
                    if ((a > b) == up) { buf[i] = b; buf[ixj] = a; }
                }
            }
            __syncthreads();
        }
    }
    if (tid == 0) {
        g_anygate = sh_any;
        double fac = pow(2.0, (double)stepsPtr[0] / 12.0);
        g_factor32 = (float)fac;
        if (npos > 0) g_median = buf[(npos - 1) >> 1];
        g_mshift32 = (float)((double)g_median * fac);
    }
}

__global__ void K_interp(const float* __restrict__ p, int S, int T) {
    int t = blockIdx.x*blockDim.x + threadIdx.x;
    if (t >= T) return;
    double scale = (double)S / (double)T;
    double x = __dadd_rn(__dmul_rn(__dadd_rn((double)t, 0.5), scale), -0.5);
    if (x < 0.0) x = 0.0;
    double hi = (double)(S - 1);
    if (x > hi) x = hi;
    long i0 = (long)floor(x);
    long i1 = i0 + 1; if (i1 > (long)(S-1)) i1 = S - 1;
    float f = (float)__dsub_rn(x, (double)i0);
    g_f0[t] = __fadd_rn(__fmul_rn(p[i0], __fsub_rn(1.0f, f)), __fmul_rn(p[i1], f));
}

__global__ void K_shift(const float* __restrict__ prp, int T) {
    int t = blockIdx.x*blockDim.x + threadIdx.x;
    float res = 0.f;
    if (t < T) {
        float fs = __fmul_rn(g_f0[t], g_factor32);
        float m = g_mshift32;
        if (fs > 0.f) res = __fadd_rn(m, __fmul_rn(__fsub_rn(fs, m), prp[0]));
        g_f0s[t] = res;
    }
    unsigned mb = (t < T && res > 0.f) ? __float_as_uint(res) : 0xFFFFFFFFu;
    for (int o = 16; o; o >>= 1) mb = min(mb, __shfl_down_sync(0xFFFFFFFFu, mb, o));
    if ((threadIdx.x & 31) == 0 && mb != 0xFFFFFFFFu) atomicMin(&g_minbits, mb);
}

__global__ void K_mark(int T) {
    int t = blockIdx.x*blockDim.x + threadIdx.x;
    if (t >= T) return;
    if (g_f0[t] > 0.f) {
        bool pr = (t > 0) && (g_f0[t-1] > 0.f);
        bool nx = (t < T-1) && (g_f0[t+1] > 0.f);
        if (!pr) { int i = atomicAdd(&g_cs0,1); if (i < MAXRUNS) g_st0[i] = t; }
        if (!nx) { int i = atomicAdd(&g_ce0,1); if (i < MAXRUNS) g_en0[i] = t+1; }
    }
    if (g_f0s[t] > 0.f) {
        bool pr = (t > 0) && (g_f0s[t-1] > 0.f);
        bool nx = (t < T-1) && (g_f0s[t+1] > 0.f);
        if (!pr) { int i = atomicAdd(&g_cs1,1); if (i < MAXRUNS) g_st1[i] = t; }
        if (!nx) { int i = atomicAdd(&g_ce1,1); if (i < MAXRUNS) g_en1[i] = t+1; }
    }
}

__device__ void sort_small(int* a, int n) {
    for (int i = 1; i < n; i++) {
        int v = a[i], j = i-1;
        while (j >= 0 && a[j] > v) { a[j+1] = a[j]; j--; }
        a[j+1] = v;
    }
}

__global__ void K_sortruns() {
    if (threadIdx.x || blockIdx.x) return;
    {
        int ns = min(g_cs0, MAXRUNS), ne = min(g_ce0, MAXRUNS);
        sort_small(g_st0, ns); sort_small(g_en0, ne);
        int n = min(ns, ne), off = 0;
        if (n > 0 && g_st0[0] == 0) { g_st0[0] = 1; if (g_st0[0] >= g_en0[0]) off = 1; }
        int m = 0;
        for (int k = off; k < n; k++) { g_runL0[m] = g_st0[k]; g_runR0[m] = g_en0[k]; m++; }
        g_nruns0 = m;
    }
    {
        int ns = min(g_cs1, MAXRUNS), ne = min(g_ce1, MAXRUNS);
        sort_small(g_st1, ns); sort_small(g_en1, ne);
        int n = min(ns, ne), off = 0;
        if (n > 0 && g_st1[0] == 0) { g_st1[0] = 1; if (g_st1[0] >= g_en1[0]) off = 1; }
        int m = 0;
        for (int k = off; k < n; k++) { g_runL1[m] = g_st1[k]; g_runR1[m] = g_en1[k]; m++; }
        g_nruns1 = m;
    }
}

__global__ void K_backup(const float* __restrict__ sig, int T) {
    int run = blockIdx.x;
    if (run >= g_nruns0 || threadIdx.x != 0) return;
    int left = g_runL0[run], right = g_runR0[run];
    int middle = (left + right) / 2;
    double wd = __ddiv_rn(22050.0, (double)g_f0[middle]);
    long w = (wd > 2.0e9) ? 2000000000L : (long)wd;
    long s = (long)middle - w/2; if (s < 0) s = 0;
    long len = w; if (s + len > T) len = T - s;
    float mn = INFINITY, mx = -INFINITY; long imn = 0, imx = 0;
    for (long k = 0; k < len; k++) {
        float v = sig[s+k];
        if (v < mn) { mn = v; imn = k; }
        if (v > mx) { mx = v; imx = k; }
    }
    g_backup[run] = (mn == mx) ? middle
                  : (int)(s + ((fabs((double)mn) > fabs((double)mx)) ? imn : imx));
}

// Merged walk; geometry (f64) on thread 0 ONLY, broadcast via smem.
__global__ __launch_bounds__(WTW) void K_walk(const float* __restrict__ sig, int T) {
    __shared__ float win[WIN];
    __shared__ float s_b[MAXW];
    __shared__ float s_q[MAXC], s_ma[MAXC], s_na[MAXC];
    __shared__ int   s_cl[MAXC];
    __shared__ int   sM;
    __shared__ float s_pv[WTW/32];
    __shared__ int   s_pi[WTW/32];
    __shared__ float sBV;
    __shared__ int sGeo[8];   // 0:w 1:s 2:cl 3:nc 4:valid 5:base0 6:WL 7:stop
    int b = blockIdx.x;
    int dir = (b < MAXRUNS) ? 1 : 0;
    int run = dir ? b : (b - MAXRUNS);
    if (run >= g_nruns0) return;
    int tid = threadIdx.x, lane4 = tid & 3, grp = tid >> 2, wrp = tid >> 5, wl = tid & 31;
    int left = g_runL0[run], right = g_runR0[run];
    double gp = (double)__uint_as_float(g_absbits);
    long base = (long)b * CANDW;
    int cnt = 0, lastApp = INT_MIN;
    int i = 0;                      // authoritative only on thread 0
    if (tid == 0) i = g_backup[run];
    while (true) {
        // ---- geometry: thread 0 only (all the f64) ----
        if (tid == 0) {
            double f0i = (double)g_f0[i];
            double fm = f0i > 60.0 ? f0i : 60.0;
            int w = (int)__ddiv_rn(22050.0, fm);
            int s = i - w/2; if (s < 0) s = 0;
            int cl, cr;
            if (dir) {
                cl = (int)__dadd_rn((double)i, __dmul_rn(0.3,  (double)w));
                cr = (int)__dadd_rn((double)i, __dmul_rn(0.75, (double)w));
            } else {
                int a1 = (int)__dsub_rn((double)i, __dmul_rn(1.75, (double)w)); cl = a1 > 0 ? a1 : 0;
                int a2 = (int)__dsub_rn((double)i, __dmul_rn(1.3,  (double)w)); cr = a2 > 0 ? a2 : 0;
            }
            int valid = 0, nc = 0, base0 = 0, WL = 0;
            if (!(cl == cr || (T - cl) < w)) {
                long hi = (long)cr + w; if (hi > T) hi = T;
                nc = (int)(hi - cl - w + 1);
                valid = (nc >= 1 && nc <= MAXC && w <= MAXW && s + w <= T);
            }
            if (valid) {
                base0 = min(s, cl);
                int e1 = s + w, e2 = cl + nc - 1 + w;
                WL = (e1 > e2 ? e1 : e2) - base0;
                if (WL > WIN) valid = 0;
            }
            sGeo[0]=w; sGeo[1]=s; sGeo[2]=cl; sGeo[3]=nc; sGeo[4]=valid;
            sGeo[5]=base0; sGeo[6]=WL;
            sM = 0;
        }
        __syncthreads();
        int w = sGeo[0], s = sGeo[1], cl = sGeo[2], nc = sGeo[3];
        int valid = sGeo[4], base0 = sGeo[5], WL = sGeo[6];
        if (valid) {
            for (int k = tid; k < WL; k += WTW) win[k] = sig[base0 + k];
            __syncthreads();
            if (wrp == 0) {
                const float* rp = win + (s - base0);
                float psq = np_psq4(rp, w, lane4);
                float nb = __shfl_sync(0xFFFFFFFFu, psq, 0);
                nb = fmaxf(__fsqrt_rn(nb), 1e-12f);
                for (int k = wl; k < w; k += 32) s_b[k] = __fdiv_rn(rp[k], nb);
            }
            __syncthreads();
            const float* cb = win + (cl - base0);
            int w4 = w & ~3;
            // ---- pass 1: divide-free approx corr + na + maxabs ----
            for (int c0 = 0; c0 < nc; c0 += WTW/4) {
                int c = c0 + grp;
                int cc = c < nc ? c : nc - 1;
                const float* ap = cb + cc;
                float psq = np_psq4(ap, w, lane4);
                float na = 0.f;
                if (lane4 == 0) na = fmaxf(__fsqrt_rn(psq), 1e-12f);
                float acc = 0.f, ma = 0.f;
                for (int k = lane4; k < w4; k += 4) {
                    float v = ap[k];
                    ma = fmaxf(ma, fabsf(v));
                    acc = fmaf(v, s_b[k], acc);
                }
                float a1 = __shfl_down_sync(0xFFFFFFFFu, acc, 1, 4);
                float ssum = __fadd_rn(acc, a1);
                float a2 = __shfl_down_sync(0xFFFFFFFFu, ssum, 2, 4);
                float res = __fadd_rn(ssum, a2);
                float m1 = __shfl_down_sync(0xFFFFFFFFu, ma, 1, 4);
                ma = fmaxf(ma, m1);
                float m2 = __shfl_down_sync(0xFFFFFFFFu, ma, 2, 4);
                ma = fmaxf(ma, m2);
                if (lane4 == 0 && c < nc) {
                    for (int k = w4; k < w; k++) {
                        float v = ap[k];
                        ma = fmaxf(ma, fabsf(v));
                        res = fmaf(v, s_b[k], res);
                    }
                    s_q[cc] = __fdiv_rn(res, na);
                    s_ma[cc] = ma; s_na[cc] = na;
                }
            }
            __syncthreads();
            // ---- max approx value ----
            {
                float v = (tid < nc) ? s_q[tid] : -INFINITY;
                for (int o = 16; o; o >>= 1)
                    v = fmaxf(v, __shfl_down_sync(0xFFFFFFFFu, v, o));
                if (wl == 0) s_pv[wrp] = v;
            }
            __syncthreads();
            if (tid == 0) {
                float bv = s_pv[0];
                for (int q = 1; q < WTW/32; q++) bv = fmaxf(bv, s_pv[q]);
                sBV = bv;
            }
            __syncthreads();
            // ---- compact contender list; demote non-contenders ----
            for (int c = tid; c < nc; c += WTW) {
                if (s_q[c] >= sBV - CEPS) {
                    int sl = atomicAdd(&sM, 1);
                    s_cl[sl] = c;
                } else {
                    s_q[c] = -INFINITY;
                }
            }
            __syncthreads();
            int m = sM;
            // ---- pass 2: bit-exact corr for contenders; warp-uniform activation ----
            for (int j0 = 0; j0 < m; j0 += WTW/4) {
                if (j0 + (wrp << 3) < m) {
                    int ji = j0 + grp;
                    int jj = ji < m ? ji : m - 1;
                    int c = s_cl[jj];
                    const float* ap = cb + c;
                    float na = s_na[c];
                    float acc = 0.f;
                    for (int k = lane4; k < w4; k += 4)
                        acc = fmaf(__fdiv_rn(ap[k], na), s_b[k], acc);
                    float a1 = __shfl_down_sync(0xFFFFFFFFu, acc, 1, 4);
                    float ssum = __fadd_rn(acc, a1);
                    float a2 = __shfl_down_sync(0xFFFFFFFFu, ssum, 2, 4);
                    float res = __fadd_rn(ssum, a2);
                    if (lane4 == 0 && ji < m) {
                        for (int k = w4; k < w; k++)
                            res = fmaf(__fdiv_rn(ap[k], na), s_b[k], res);
                        s_q[c] = res;
                    }
                }
            }
            __syncthreads();
            // ---- final argmax, first-occurrence ties ----
            {
                float v = (tid < nc) ? s_q[tid] : -INFINITY;
                int idx = tid;
                for (int o = 16; o; o >>= 1) {
                    float vo = __shfl_down_sync(0xFFFFFFFFu, v, o);
                    int   io = __shfl_down_sync(0xFFFFFFFFu, idx, o);
                    if (vo > v || (vo == v && io < idx)) { v = vo; idx = io; }
                }
                if (wl == 0) { s_pv[wrp] = v; s_pi[wrp] = idx; }
            }
            __syncthreads();
        }
        if (tid == 0) {
            double corr = -1.0, peak = 0.0;
            int stop = 0;
            if (valid) {
                float bv = s_pv[0]; int br = s_pi[0];
                for (int q = 1; q < WTW/32; q++)
                    if (s_pv[q] > bv || (s_pv[q] == bv && s_pi[q] < br)) { bv = s_pv[q]; br = s_pi[q]; }
                corr = (double)s_q[br];
                peak = (double)s_ma[br];
                i = i + (br + cl) - s;
            }
            bool neg1 = (corr == -1.0);
            if (dir) {
                if (neg1) i += w;
                if (i >= right) {
                    if (corr > 0.7 && peak > __dmul_rn(0.023333, gp)) {
                        if (cnt < CANDW) g_wci[base+cnt] = i;
                        cnt++; lastApp = i;
                    }
                    stop = 1;
                } else if (corr > 0.3 && (peak == 0.0 || peak > __dmul_rn(0.01, gp))) {
                    if (cnt < CANDW) g_wci[base+cnt] = i;
                    cnt++; lastApp = i;
                }
            } else {
                if (neg1) i -= w;
                if (i < left) {
                    if (corr > 0.7 && peak > __dmul_rn(0.023333, gp)) {
                        if (cnt < CANDW) { g_wci[base+cnt] = i; g_wcw[base+cnt] = w; }
                        cnt++;
                    }
                    stop = 1;
                } else if (corr > 0.3 && (peak == 0.0 || peak > __dmul_rn(0.01, gp))) {
                    if (cnt < CANDW) { g_wci[base+cnt] = i; g_wcw[base+cnt] = w; }
                    cnt++;
                }
            }
            sGeo[7] = stop;
        }
        __syncthreads();
        if (sGeo[7]) break;
    }
    if (tid == 0) {
        g_wcnt[b] = min(cnt, CANDW);
        if (dir) g_lastApp[run] = lastApp;
    }
}

__global__ void K_filter() {
    __shared__ double sAR[MAXRUNS];
    int tid = threadIdx.x;
    int nr = g_nruns0;
    if (tid == 0) {
        double cur = -1e308;
        for (int r = 0; r < nr; r++) {
            sAR[r] = cur;
            if (g_lastApp[r] != INT_MIN) cur = (double)g_lastApp[r];
        }
    }
    __syncthreads();
    if (tid < nr) {
        long base = (long)(MAXRUNS + tid) * CANDW;
        int c = g_wcnt[MAXRUNS + tid], m = 0;
        double AR = sAR[tid];
        for (int j = 0; j < c; j++) {
            int i = g_wci[base + j], w = g_wcw[base + j];
            if (__dsub_rn((double)i, AR) > __dmul_rn(0.8, (double)w)) {
                g_wci[base + m] = i; m++;
            }
        }
        g_wcnt[MAXRUNS + tid] = m;
    }
}

__global__ void K_collect() {
    __shared__ int s_off[NWALK];
    int tid = threadIdx.x;
    if (tid == 0) {
        int acc = 0;
        for (int sl = 0; sl < NWALK; sl++) { s_off[sl] = acc; acc += g_wcnt[sl]; }
        g_ncand = min(acc, MAXPK);
    }
    __syncthreads();
    for (int sl = 0; sl < NWALK; sl++) {
        int c = g_wcnt[sl], o = s_off[sl];
        for (int j = tid; j < c; j += blockDim.x)
            if (o + j < MAXPK) g_cand[o+j] = g_wci[(long)sl*CANDW + j];
    }
}

__global__ void K_rank(int T) {
    int N = g_ncand;
    for (int j = blockIdx.x*blockDim.x + threadIdx.x; j < N; j += gridDim.x*blockDim.x) {
        int v = g_cand[j], rk = 0;
        for (int k = 0; k < N; k++) {
            int u = g_cand[k];
            rk += (u < v) || (u == v && k < j);
        }
        int cv = v; if (cv < 0) cv = 0; if (cv > T-1) cv = T-1;
        g_peaks[rk] = cv;
    }
    if (blockIdx.x == 0 && threadIdx.x == 0) g_npk = N;
}

__device__ int plan_run(int r, int T, double max_w, int write, int base) {
    int left_v = g_runL1[r], right_v = g_runR1[r];
    int prevR = (r == 0) ? 0 : g_runR1[r-1];
    int cnt = 0, npk = g_npk;
    if (prevR < left_v) {
        if (write && base+cnt < MAXOPS) {
            g_opd[base+cnt] = prevR; g_opsrc[base+cnt] = prevR;
            g_opl[base+cnt] = left_v - prevR; g_opn[base+cnt] = left_v - prevR;
        }
        cnt++;
    }
    while (left_v < right_v) {
        int q = dev_lb(g_peaks, npk, left_v), p;
        if (q == 0) p = 0;
        else if (q >= npk) p = dev_lb(g_peaks, npk, g_peaks[npk-1]);
        else {
            long d1 = (long)left_v - g_peaks[q-1], d2 = (long)g_peaks[q] - left_v;
            p = (d1 <= d2) ? dev_lb(g_peaks, npk, g_peaks[q-1]) : q;
        }
        double fv = (double)g_f0s[left_v];
        int period = (int)__ddiv_rn(22050.0, fv > 60.0 ? fv : 60.0);
        int left_w = period/2, right_w = period/2;
        if (p > 0) {
            long d = (long)g_peaks[p] - g_peaks[p-1];
            if ((double)d <= max_w) left_w = min((int)d, left_w);
        }
        if (p < npk-1) {
            long d = (long)g_peaks[p+1] - g_peaks[p];
            if ((double)d <= max_w) right_w = min((int)d, right_w);
        }
        int left_i = g_peaks[p] - left_w; if (left_i < 0) left_i = 0;
        int right_i = g_peaks[p] + right_w;
        int ival = (right_i - left_i) / 2;
        if (ival <= 0) break;
        long a = (long)left_v - ival;
        int seglen = min(pyslen(a, (long)left_v + ival, T),
                         pyslen(left_i, (long)left_i + 2L*ival, T));
        int Ld = pyslen(a, a + seglen, T);
        int Ls = pyslen(left_i, (long)left_i + seglen, T);
        int L = min(min(Ld, Ls), seglen);
        if (write && base+cnt < MAXOPS) {
            long as_ = a < 0 ? a + T : a;
            g_opd[base+cnt] = (int)as_; g_opsrc[base+cnt] = left_i;
            g_opl[base+cnt] = L; g_opn[base+cnt] = 2*ival;
        }
        cnt++;
        left_v += ival * 2;
    }
    return cnt;
}

__global__ void K_plan(int T) {
    __shared__ int s_cnt[MAXRUNS];
    __shared__ double s_maxw;
    int tid = threadIdx.x;
    if (tid == 0) {
        g_copy = (!g_anygate || g_npk == 0) ? 1 : 0;
        float mp = __uint_as_float(g_minbits);
        s_maxw = __ddiv_rn(27562.5, (double)mp);
        g_tail = 0; g_nops = 0;
    }
    __syncthreads();
    if (g_copy) return;
    int nr = g_nruns1;
    if (tid == 0 && nr > 0) g_tail = g_runR1[nr-1];
    if (tid < nr) s_cnt[tid] = plan_run(tid, T, s_maxw, 0, 0);
    __syncthreads();
    if (tid == 0) {
        int acc = 0;
        for (int r = 0; r < nr; r++) { int c = s_cnt[r]; s_cnt[r] = acc; acc += c; }
        g_nops = min(acc, MAXOPS);
    }
    __syncthreads();
    if (tid < nr) plan_run(tid, T, s_maxw, 1, s_cnt[tid]);
}

__global__ void K_apply(const float* __restrict__ snd, float* __restrict__ out, int T) {
    for (int b = blockIdx.x; b < g_nops; b += gridDim.x) {
        int d0 = g_opd[b], s0 = g_opsrc[b], L = g_opl[b], n = g_opn[b];
        for (int k = threadIdx.x; k < L; k += blockDim.x) {
            double ang = __ddiv_rn(__dmul_rn(6.283185307179586, (double)k), (double)n);
            float wf = (float)__dsub_rn(0.5, __dmul_rn(0.5, cos(ang)));
            atomicAdd(out + d0 + k, __fmul_rn(wf, snd[s0 + k]));
        }
    }
}

__global__ void K_tail(const float* __restrict__ snd, float* __restrict__ out, int T) {
    int t = blockIdx.x*blockDim.x + threadIdx.x;
    if (t >= T) return;
    if (g_copy || t >= g_tail) out[t] = snd[t];
}

extern "C" void kernel_launch(void* const* d_in, const int* in_sizes, int n_in,
                              void* d_out, int out_size) {
    const float* snd   = (const float*)d_in[0];
    const float* pitch = (const float*)d_in[1];
    const int*   steps = (const int*)d_in[2];
    const float* prng  = (const float*)d_in[3];
    float* out = (float*)d_out;
    int T = in_sizes[0];
    int S = in_sizes[1];

    K_init<<<1,256>>>();
    K_zero<<<GRID(T,256),256>>>(out, T);
    K_absmax<<<512,256>>>(snd, T);
    K_median<<<1,512>>>(pitch, S, steps);
    K_interp<<<GRID(T,256),256>>>(pitch, S, T);
    K_shift<<<GRID(T,256),256>>>(prng, T);
    K_mark<<<GRID(T,256),256>>>(T);
    K_sortruns<<<1,1>>>();
    K_backup<<<MAXRUNS,1>>>(snd, T);
    K_walk<<<NWALK,WTW>>>(snd, T);
    K_filter<<<1,64>>>();
    K_collect<<<1,256>>>();
    K_rank<<<64,256>>>(T);
    K_plan<<<1,64>>>(T);
    K_apply<<<2048,128>>>(snd, out, T);
    K_tail<<<GRID(T,256),256>>>(snd, out, T);
}

// round 13
// speedup vs baseline: 1.0233x; 1.0124x over previous
#include <cuda_runtime.h>
#include <math.h>
#include <limits.h>

#define MAXT 700000
#define MAXRUNS 64
#define NWALK (2*MAXRUNS)
#define CANDW 2048
#define MAXPK 16384
#define MAXOPS 8192
#define MAXC 256
#define MAXW 400
#define MS 4096
#define WIN 960
#define WTW 512
#define CEPS 1e-4f
#define GRID(n,b) (((n)+(b)-1)/(b))

__device__ float g_f0[MAXT];
__device__ float g_f0s[MAXT];
__device__ double g_scale;
__device__ unsigned g_absbits;
__device__ int g_anygate;
__device__ unsigned g_minbits;
__device__ float g_median;
__device__ float g_factor32, g_mshift32;

__device__ int g_st0[MAXRUNS], g_en0[MAXRUNS], g_st1[MAXRUNS], g_en1[MAXRUNS];
__device__ int g_cs0, g_ce0, g_cs1, g_ce1;
__device__ int g_runL0[MAXRUNS], g_runR0[MAXRUNS], g_nruns0;
__device__ int g_runL1[MAXRUNS], g_runR1[MAXRUNS], g_nruns1;
__device__ int g_tail, g_copy;
__device__ int g_backup[MAXRUNS];

__device__ int g_wci[NWALK*CANDW];
__device__ int g_wcw[NWALK*CANDW];
__device__ int g_wcnt[NWALK];
__device__ int g_lastApp[MAXRUNS];

__device__ int g_cand[MAXPK];
__device__ int g_ncand, g_npk;
__device__ int g_peaks[MAXPK];

__device__ int g_opd[MAXOPS], g_opsrc[MAXOPS], g_opl[MAXOPS], g_opn[MAXOPS];
__device__ int g_nops;

__device__ __forceinline__ int pyslen(long start, long stop, long n) {
    if (start < 0) start += n; if (start < 0) start = 0; if (start > n) start = n;
    if (stop  < 0) stop  += n; if (stop  < 0) stop  = 0; if (stop  > n) stop  = n;
    long L = stop - start; return L > 0 ? (int)L : 0;
}
__device__ __forceinline__ int dev_lb(const int* a, int n, int v) {
    int lo = 0, hi = n;
    while (lo < hi) { int m = (lo+hi)>>1; if (a[m] < v) lo = m+1; else hi = m; }
    return lo;
}

// exact test p*f <= 22050 (real arithmetic) via f32 TwoProd; p < 2^24
__device__ __forceinline__ bool pmul_le(int p, float f) {
    float pf = (float)p;
    float hi = __fmul_rn(pf, f);
    float lo = __fmaf_rn(pf, f, -hi);
    return (hi < 22050.f) || (hi == 22050.f && lo <= 0.f);
}
// floor(22050 / fm) over reals, no FP64
__device__ __forceinline__ int floor_div_22050(float fm) {
    int p = (int)(22050.f / fm);
    while (p > 0 && !pmul_le(p, fm)) p--;
    while (pmul_le(p + 1, fm)) p++;
    return p;
}
// exact test d * mp <= 27562.5 (real) via TwoProd; d < 2^24
__device__ __forceinline__ bool dmul_le_maxw(long d, float mp) {
    float df = (float)d;
    float hi = __fmul_rn(df, mp);
    float lo = __fmaf_rn(df, mp, -hi);
    return (hi < 27562.5f) || (hi == 27562.5f && lo <= 0.f);
}

// numpy FLOAT_pairwise_sum of squares, 4-lane cooperative, bit-exact.
__device__ float np_psq4(const float* a, int n, int lane) {
    if (n < 8) {
        float r = 0.f;
        for (int i = 0; i < n; i++) r = __fadd_rn(r, __fmul_rn(a[i], a[i]));
        return r;
    }
    if (n <= 128) {
        int nb = n - (n % 8);
        int c0 = 2*lane, c1 = 2*lane + 1;
        float ra = __fmul_rn(a[c0], a[c0]);
        float rb = __fmul_rn(a[c1], a[c1]);
        for (int i = 8; i < nb; i += 8) {
            ra = __fadd_rn(ra, __fmul_rn(a[i+c0], a[i+c0]));
            rb = __fadd_rn(rb, __fmul_rn(a[i+c1], a[i+c1]));
        }
        float u = __fadd_rn(ra, rb);
        float u1 = __shfl_down_sync(0xFFFFFFFFu, u, 1, 4);
        float t  = __fadd_rn(u, u1);
        float t2 = __shfl_down_sync(0xFFFFFFFFu, t, 2, 4);
        float res = __fadd_rn(t, t2);
        for (int i = nb; i < n; i++) res = __fadd_rn(res, __fmul_rn(a[i], a[i]));
        return res;
    }
    int n2 = n / 2; n2 -= n2 % 8;
    float L = np_psq4(a, n2, lane);
    float R = np_psq4(a + n2, n - n2, lane);
    return __fadd_rn(L, R);
}

__global__ void K_init(int S, int T) {
    int t = threadIdx.x;
    if (t == 0) {
        g_absbits = 0u; g_anygate = 0; g_minbits = 0xFFFFFFFFu; g_median = 0.f;
        g_cs0 = g_ce0 = g_cs1 = g_ce1 = 0; g_nruns0 = g_nruns1 = 0;
        g_tail = 0; g_copy = 0; g_ncand = 0; g_npk = 0; g_nops = 0;
        g_scale = __ddiv_rn((double)S, (double)T);
    }
    for (int i = t; i < NWALK; i += blockDim.x) g_wcnt[i] = 0;
    for (int i = t; i < MAXRUNS; i += blockDim.x) g_lastApp[i] = INT_MIN;
}

__global__ void K_zero(float* out, int T) {
    int t = blockIdx.x*blockDim.x + threadIdx.x;
    if (t < T) out[t] = 0.f;
}

__global__ void K_absmax(const float* __restrict__ x, int T) {
    float m = 0.f;
    for (int i = blockIdx.x*blockDim.x + threadIdx.x; i < T; i += gridDim.x*blockDim.x)
        m = fmaxf(m, fabsf(x[i]));
    for (int o = 16; o; o >>= 1) m = fmaxf(m, __shfl_down_sync(0xFFFFFFFFu, m, o));
    if ((threadIdx.x & 31) == 0) atomicMax(&g_absbits, __float_as_uint(m));
}

__global__ void K_median(const float* __restrict__ p, int S, const int* __restrict__ stepsPtr) {
    __shared__ float buf[MS];
    __shared__ int sh_np, sh_any;
    int tid = threadIdx.x;
    if (tid == 0) { sh_np = 0; sh_any = 0; }
    __syncthreads();
    int cany = 0;
    for (int j = tid; j < S && j < MS; j += 512) {
        float v = p[j];
        if (v > 0.f) { int idx = atomicAdd(&sh_np, 1); buf[idx] = v; }
        if (v > 1e-5f) cany = 1;
    }
    if (cany) atomicOr(&sh_any, 1);
    __syncthreads();
    int npos = sh_np;
    for (int i = npos + tid; i < MS; i += 512) buf[i] = INFINITY;
    __syncthreads();
    for (int k = 2; k <= MS; k <<= 1) {
        for (int j = k >> 1; j > 0; j >>= 1) {
            for (int i = tid; i < MS; i += 512) {
                int ixj = i ^ j;
                if (ixj > i) {
                    float a = buf[i], b = buf[ixj];
                    bool up = ((i & k) == 0);
                    if ((a > b) == up) { buf[i] = b; buf[ixj] = a; }
                }
            }
            __syncthreads();
        }
    }
    if (tid == 0) {
        g_anygate = sh_any;
        double fac = pow(2.0, (double)stepsPtr[0] / 12.0);
        g_factor32 = (float)fac;
        if (npos > 0) g_median = buf[(npos - 1) >> 1];
        g_mshift32 = (float)((double)g_median * fac);
    }
}

__global__ void K_interp(const float* __restrict__ p, int S, int T) {
    int t = blockIdx.x*blockDim.x + threadIdx.x;
    if (t >= T) return;
    double x = __dadd_rn(__dmul_rn(__dadd_rn((double)t, 0.5), g_scale), -0.5);
    if (x < 0.0) x = 0.0;
    double hi = (double)(S - 1);
    if (x > hi) x = hi;
    long i0 = (long)floor(x);
    long i1 = i0 + 1; if (i1 > (long)(S-1)) i1 = S - 1;
    float f = (float)__dsub_rn(x, (double)i0);
    g_f0[t] = __fadd_rn(__fmul_rn(p[i0], __fsub_rn(1.0f, f)), __fmul_rn(p[i1], f));
}

__global__ void K_shift(const float* __restrict__ prp, int T) {
    int t = blockIdx.x*blockDim.x + threadIdx.x;
    float res = 0.f;
    if (t < T) {
        float fs = __fmul_rn(g_f0[t], g_factor32);
        float m = g_mshift32;
        if (fs > 0.f) res = __fadd_rn(m, __fmul_rn(__fsub_rn(fs, m), prp[0]));
        g_f0s[t] = res;
    }
    unsigned mb = (t < T && res > 0.f) ? __float_as_uint(res) : 0xFFFFFFFFu;
    for (int o = 16; o; o >>= 1) mb = min(mb, __shfl_down_sync(0xFFFFFFFFu, mb, o));
    if ((threadIdx.x & 31) == 0 && mb != 0xFFFFFFFFu) atomicMin(&g_minbits, mb);
}

__global__ void K_mark(int T) {
    int t = blockIdx.x*blockDim.x + threadIdx.x;
    if (t >= T) return;
    if (g_f0[t] > 0.f) {
        bool pr = (t > 0) && (g_f0[t-1] > 0.f);
        bool nx = (t < T-1) && (g_f0[t+1] > 0.f);
        if (!pr) { int i = atomicAdd(&g_cs0,1); if (i < MAXRUNS) g_st0[i] = t; }
        if (!nx) { int i = atomicAdd(&g_ce0,1); if (i < MAXRUNS) g_en0[i] = t+1; }
    }
    if (g_f0s[t] > 0.f) {
        bool pr = (t > 0) && (g_f0s[t-1] > 0.f);
        bool nx = (t < T-1) && (g_f0s[t+1] > 0.f);
        if (!pr) { int i = atomicAdd(&g_cs1,1); if (i < MAXRUNS) g_st1[i] = t; }
        if (!nx) { int i = atomicAdd(&g_ce1,1); if (i < MAXRUNS) g_en1[i] = t+1; }
    }
}

__device__ void sort_small(int* a, int n) {
    for (int i = 1; i < n; i++) {
        int v = a[i], j = i-1;
        while (j >= 0 && a[j] > v) { a[j+1] = a[j]; j--; }
        a[j+1] = v;
    }
}

__global__ void K_sortruns() {
    if (threadIdx.x || blockIdx.x) return;
    {
        int ns = min(g_cs0, MAXRUNS), ne = min(g_ce0, MAXRUNS);
        sort_small(g_st0, ns); sort_small(g_en0, ne);
        int n = min(ns, ne), off = 0;
        if (n > 0 && g_st0[0] == 0) { g_st0[0] = 1; if (g_st0[0] >= g_en0[0]) off = 1; }
        int m = 0;
        for (int k = off; k < n; k++) { g_runL0[m] = g_st0[k]; g_runR0[m] = g_en0[k]; m++; }
        g_nruns0 = m;
    }
    {
        int ns = min(g_cs1, MAXRUNS), ne = min(g_ce1, MAXRUNS);
        sort_small(g_st1, ns); sort_small(g_en1, ne);
        int n = min(ns, ne), off = 0;
        if (n > 0 && g_st1[0] == 0) { g_st1[0] = 1; if (g_st1[0] >= g_en1[0]) off = 1; }
        int m = 0;
        for (int k = off; k < n; k++) { g_runL1[m] = g_st1[k]; g_runR1[m] = g_en1[k]; m++; }
        g_nruns1 = m;
    }
}

__global__ void K_backup(const float* __restrict__ sig, int T) {
    int run = blockIdx.x;
    if (run >= g_nruns0 || threadIdx.x != 0) return;
    int left = g_runL0[run], right = g_runR0[run];
    int middle = (left + right) / 2;
    double wd = __ddiv_rn(22050.0, (double)g_f0[middle]);
    long w = (wd > 2.0e9) ? 2000000000L : (long)wd;
    long s = (long)middle - w/2; if (s < 0) s = 0;
    long len = w; if (s + len > T) len = T - s;
    float mn = INFINITY, mx = -INFINITY; long imn = 0, imx = 0;
    for (long k = 0; k < len; k++) {
        float v = sig[s+k];
        if (v < mn) { mn = v; imn = k; }
        if (v > mx) { mx = v; imx = k; }
    }
    g_backup[run] = (mn == mx) ? middle
                  : (int)(s + ((fabs((double)mn) > fabs((double)mx)) ? imn : imx));
}

// Merged walk; geometry (f64) on thread 0 ONLY, broadcast via smem.
__global__ __launch_bounds__(WTW) void K_walk(const float* __restrict__ sig, int T) {
    __shared__ float win[WIN];
    __shared__ float s_b[MAXW];
    __shared__ float s_q[MAXC], s_ma[MAXC], s_na[MAXC];
    __shared__ int   s_cl[MAXC];
    __shared__ int   sM;
    __shared__ float s_pv[WTW/32];
    __shared__ int   s_pi[WTW/32];
    __shared__ float sBV;
    __shared__ int sGeo[8];
    int b = blockIdx.x;
    int dir = (b < MAXRUNS) ? 1 : 0;
    int run = dir ? b : (b - MAXRUNS);
    if (run >= g_nruns0) return;
    int tid = threadIdx.x, lane4 = tid & 3, grp = tid >> 2, wrp = tid >> 5, wl = tid & 31;
    int left = g_runL0[run], right = g_runR0[run];
    double gp = (double)__uint_as_float(g_absbits);
    long base = (long)b * CANDW;
    int cnt = 0, lastApp = INT_MIN;
    int i = 0;
    if (tid == 0) i = g_backup[run];
    while (true) {
        if (tid == 0) {
            double f0i = (double)g_f0[i];
            double fm = f0i > 60.0 ? f0i : 60.0;
            int w = (int)__ddiv_rn(22050.0, fm);
            int s = i - w/2; if (s < 0) s = 0;
            int cl, cr;
            if (dir) {
                cl = (int)__dadd_rn((double)i, __dmul_rn(0.3,  (double)w));
                cr = (int)__dadd_rn((double)i, __dmul_rn(0.75, (double)w));
            } else {
                int a1 = (int)__dsub_rn((double)i, __dmul_rn(1.75, (double)w)); cl = a1 > 0 ? a1 : 0;
                int a2 = (int)__dsub_rn((double)i, __dmul_rn(1.3,  (double)w)); cr = a2 > 0 ? a2 : 0;
            }
            int valid = 0, nc = 0, base0 = 0, WL = 0;
            if (!(cl == cr || (T - cl) < w)) {
                long hi = (long)cr + w; if (hi > T) hi = T;
                nc = (int)(hi - cl - w + 1);
                valid = (nc >= 1 && nc <= MAXC && w <= MAXW && s + w <= T);
            }
            if (valid) {
                base0 = min(s, cl);
                int e1 = s + w, e2 = cl + nc - 1 + w;
                WL = (e1 > e2 ? e1 : e2) - base0;
                if (WL > WIN) valid = 0;
            }
            sGeo[0]=w; sGeo[1]=s; sGeo[2]=cl; sGeo[3]=nc; sGeo[4]=valid;
            sGeo[5]=base0; sGeo[6]=WL;
            sM = 0;
        }
        __syncthreads();
        int w = sGeo[0], s = sGeo[1], cl = sGeo[2], nc = sGeo[3];
        int valid = sGeo[4], base0 = sGeo[5], WL = sGeo[6];
        if (valid) {
            for (int k = tid; k < WL; k += WTW) win[k] = sig[base0 + k];
            __syncthreads();
            if (wrp == 0) {
                const float* rp = win + (s - base0);
                float psq = np_psq4(rp, w, lane4);
                float nb = __shfl_sync(0xFFFFFFFFu, psq, 0);
                nb = fmaxf(__fsqrt_rn(nb), 1e-12f);
                for (int k = wl; k < w; k += 32) s_b[k] = __fdiv_rn(rp[k], nb);
            }
            __syncthreads();
            const float* cb = win + (cl - base0);
            int w4 = w & ~3;
            for (int c0 = 0; c0 < nc; c0 += WTW/4) {
                int c = c0 + grp;
                int cc = c < nc ? c : nc - 1;
                const float* ap = cb + cc;
                float psq = np_psq4(ap, w, lane4);
                float na = 0.f;
                if (lane4 == 0) na = fmaxf(__fsqrt_rn(psq), 1e-12f);
                float acc = 0.f, ma = 0.f;
                for (int k = lane4; k < w4; k += 4) {
                    float v = ap[k];
                    ma = fmaxf(ma, fabsf(v));
                    acc = fmaf(v, s_b[k], acc);
                }
                float a1 = __shfl_down_sync(0xFFFFFFFFu, acc, 1, 4);
                float ssum = __fadd_rn(acc, a1);
                float a2 = __shfl_down_sync(0xFFFFFFFFu, ssum, 2, 4);
                float res = __fadd_rn(ssum, a2);
                float m1 = __shfl_down_sync(0xFFFFFFFFu, ma, 1, 4);
                ma = fmaxf(ma, m1);
                float m2 = __shfl_down_sync(0xFFFFFFFFu, ma, 2, 4);
                ma = fmaxf(ma, m2);
                if (lane4 == 0 && c < nc) {
                    for (int k = w4; k < w; k++) {
                        float v = ap[k];
                        ma = fmaxf(ma, fabsf(v));
                        res = fmaf(v, s_b[k], res);
                    }
                    s_q[cc] = __fdiv_rn(res, na);
                    s_ma[cc] = ma; s_na[cc] = na;
                }
            }
            __syncthreads();
            {
                float v = (tid < nc) ? s_q[tid] : -INFINITY;
                for (int o = 16; o; o >>= 1)
                    v = fmaxf(v, __shfl_down_sync(0xFFFFFFFFu, v, o));
                if (wl == 0) s_pv[wrp] = v;
            }
            __syncthreads();
            if (tid == 0) {
                float bv = s_pv[0];
                for (int q = 1; q < WTW/32; q++) bv = fmaxf(bv, s_pv[q]);
                sBV = bv;
            }
            __syncthreads();
            for (int c = tid; c < nc; c += WTW) {
                if (s_q[c] >= sBV - CEPS) {
                    int sl = atomicAdd(&sM, 1);
                    s_cl[sl] = c;
                } else {
                    s_q[c] = -INFINITY;
                }
            }
            __syncthreads();
            int m = sM;
            for (int j0 = 0; j0 < m; j0 += WTW/4) {
                if (j0 + (wrp << 3) < m) {
                    int ji = j0 + grp;
                    int jj = ji < m ? ji : m - 1;
                    int c = s_cl[jj];
                    const float* ap = cb + c;
                    float na = s_na[c];
                    float acc = 0.f;
                    for (int k = lane4; k < w4; k += 4)
                        acc = fmaf(__fdiv_rn(ap[k], na), s_b[k], acc);
                    float a1 = __shfl_down_sync(0xFFFFFFFFu, acc, 1, 4);
                    float ssum = __fadd_rn(acc, a1);
                    float a2 = __shfl_down_sync(0xFFFFFFFFu, ssum, 2, 4);
                    float res = __fadd_rn(ssum, a2);
                    if (lane4 == 0 && ji < m) {
                        for (int k = w4; k < w; k++)
                            res = fmaf(__fdiv_rn(ap[k], na), s_b[k], res);
                        s_q[c] = res;
                    }
                }
            }
            __syncthreads();
            {
                float v = (tid < nc) ? s_q[tid] : -INFINITY;
                int idx = tid;
                for (int o = 16; o; o >>= 1) {
                    float vo = __shfl_down_sync(0xFFFFFFFFu, v, o);
                    int   io = __shfl_down_sync(0xFFFFFFFFu, idx, o);
                    if (vo > v || (vo == v && io < idx)) { v = vo; idx = io; }
                }
                if (wl == 0) { s_pv[wrp] = v; s_pi[wrp] = idx; }
            }
            __syncthreads();
        }
        if (tid == 0) {
            double corr = -1.0, peak = 0.0;
            int stop = 0;
            if (valid) {
                float bv = s_pv[0]; int br = s_pi[0];
                for (int q = 1; q < WTW/32; q++)
                    if (s_pv[q] > bv || (s_pv[q] == bv && s_pi[q] < br)) { bv = s_pv[q]; br = s_pi[q]; }
                corr = (double)s_q[br];
                peak = (double)s_ma[br];
                i = i + (br + cl) - s;
            }
            bool neg1 = (corr == -1.0);
            if (dir) {
                if (neg1) i += w;
                if (i >= right) {
                    if (corr > 0.7 && peak > __dmul_rn(0.023333, gp)) {
                        if (cnt < CANDW) g_wci[base+cnt] = i;
                        cnt++; lastApp = i;
                    }
                    stop = 1;
                } else if (corr > 0.3 && (peak == 0.0 || peak > __dmul_rn(0.01, gp))) {
                    if (cnt < CANDW) g_wci[base+cnt] = i;
                    cnt++; lastApp = i;
                }
            } else {
                if (neg1) i -= w;
                if (i < left) {
                    if (corr > 0.7 && peak > __dmul_rn(0.023333, gp)) {
                        if (cnt < CANDW) { g_wci[base+cnt] = i; g_wcw[base+cnt] = w; }
                        cnt++;
                    }
                    stop = 1;
                } else if (corr > 0.3 && (peak == 0.0 || peak > __dmul_rn(0.01, gp))) {
                    if (cnt < CANDW) { g_wci[base+cnt] = i; g_wcw[base+cnt] = w; }
                    cnt++;
                }
            }
            sGeo[7] = stop;
        }
        __syncthreads();
        if (sGeo[7]) break;
    }
    if (tid == 0) {
        g_wcnt[b] = min(cnt, CANDW);
        if (dir) g_lastApp[run] = lastApp;
    }
}

// integer-exact AR filter: i - AR > 0.8*w  <=>  5*(i-AR) > 4*w
__global__ void K_filter() {
    __shared__ long sAR[MAXRUNS];
    int tid = threadIdx.x;
    int nr = g_nruns0;
    if (tid == 0) {
        long cur = LONG_MIN / 4;   // sentinel: always passes
        for (int r = 0; r < nr; r++) {
            sAR[r] = cur;
            if (g_lastApp[r] != INT_MIN) cur = (long)g_lastApp[r];
        }
    }
    __syncthreads();
    if (tid < nr) {
        long base = (long)(MAXRUNS + tid) * CANDW;
        int c = g_wcnt[MAXRUNS + tid], m = 0;
        long AR = sAR[tid];
        for (int j = 0; j < c; j++) {
            int i = g_wci[base + j], w = g_wcw[base + j];
            bool pass;
            if (AR <= LONG_MIN / 8) pass = true;        // -inf sentinel
            else pass = 5L * ((long)i - AR) > 4L * (long)w;
            if (pass) { g_wci[base + m] = i; m++; }
        }
        g_wcnt[MAXRUNS + tid] = m;
    }
}

__global__ void K_collect() {
    __shared__ int s_off[NWALK];
    int tid = threadIdx.x;
    if (tid == 0) {
        int acc = 0;
        for (int sl = 0; sl < NWALK; sl++) { s_off[sl] = acc; acc += g_wcnt[sl]; }
        g_ncand = min(acc, MAXPK);
    }
    __syncthreads();
    for (int sl = 0; sl < NWALK; sl++) {
        int c = g_wcnt[sl], o = s_off[sl];
        for (int j = tid; j < c; j += blockDim.x)
            if (o + j < MAXPK) g_cand[o+j] = g_wci[(long)sl*CANDW + j];
    }
}

__global__ void K_rank(int T) {
    int N = g_ncand;
    for (int j = blockIdx.x*blockDim.x + threadIdx.x; j < N; j += gridDim.x*blockDim.x) {
        int v = g_cand[j], rk = 0;
        for (int k = 0; k < N; k++) {
            int u = g_cand[k];
            rk += (u < v) || (u == v && k < j);
        }
        int cv = v; if (cv < 0) cv = 0; if (cv > T-1) cv = T-1;
        g_peaks[rk] = cv;
    }
    if (blockIdx.x == 0 && threadIdx.x == 0) g_npk = N;
}

__device__ int plan_run(int r, int T, float minpos, int write, int base) {
    int left_v = g_runL1[r], right_v = g_runR1[r];
    int prevR = (r == 0) ? 0 : g_runR1[r-1];
    int cnt = 0, npk = g_npk;
    if (prevR < left_v) {
        if (write && base+cnt < MAXOPS) {
            g_opd[base+cnt] = prevR; g_opsrc[base+cnt] = prevR;
            g_opl[base+cnt] = left_v - prevR; g_opn[base+cnt] = left_v - prevR;
        }
        cnt++;
    }
    while (left_v < right_v) {
        int q = dev_lb(g_peaks, npk, left_v), p;
        if (q == 0) p = 0;
        else if (q >= npk) p = dev_lb(g_peaks, npk, g_peaks[npk-1]);
        else {
            long d1 = (long)left_v - g_peaks[q-1], d2 = (long)g_peaks[q] - left_v;
            p = (d1 <= d2) ? dev_lb(g_peaks, npk, g_peaks[q-1]) : q;
        }
        float fv = g_f0s[left_v];
        float fm = fv > 60.f ? fv : 60.f;
        int period = floor_div_22050(fm);
        int left_w = period/2, right_w = period/2;
        if (p > 0) {
            long d = (long)g_peaks[p] - g_peaks[p-1];
            if (dmul_le_maxw(d, minpos)) left_w = min((int)d, left_w);
        }
        if (p < npk-1) {
            long d = (long)g_peaks[p+1] - g_peaks[p];
            if (dmul_le_maxw(d, minpos)) right_w = min((int)d, right_w);
        }
        int left_i = g_peaks[p] - left_w; if (left_i < 0) left_i = 0;
        int right_i = g_peaks[p] + right_w;
        int ival = (right_i - left_i) / 2;
        if (ival <= 0) break;
        long a = (long)left_v - ival;
        int seglen = min(pyslen(a, (long)left_v + ival, T),
                         pyslen(left_i, (long)left_i + 2L*ival, T));
        int Ld = pyslen(a, a + seglen, T);
        int Ls = pyslen(left_i, (long)left_i + seglen, T);
        int L = min(min(Ld, Ls), seglen);
        if (write && base+cnt < MAXOPS) {
            long as_ = a < 0 ? a + T : a;
            g_opd[base+cnt] = (int)as_; g_opsrc[base+cnt] = left_i;
            g_opl[base+cnt] = L; g_opn[base+cnt] = 2*ival;
        }
        cnt++;
        left_v += ival * 2;
    }
    return cnt;
}

__global__ void K_plan(int T) {
    __shared__ int s_cnt[MAXRUNS];
    __shared__ float s_minpos;
    int tid = threadIdx.x;
    if (tid == 0) {
        g_copy = (!g_anygate || g_npk == 0) ? 1 : 0;
        s_minpos = __uint_as_float(g_minbits);
        g_tail = 0; g_nops = 0;
    }
    __syncthreads();
    if (g_copy) return;
    int nr = g_nruns1;
    if (tid == 0 && nr > 0) g_tail = g_runR1[nr-1];
    if (tid < nr) s_cnt[tid] = plan_run(tid, T, s_minpos, 0, 0);
    __syncthreads();
    if (tid == 0) {
        int acc = 0;
        for (int r = 0; r < nr; r++) { int c = s_cnt[r]; s_cnt[r] = acc; acc += c; }
        g_nops = min(acc, MAXOPS);
    }
    __syncthreads();
    if (tid < nr) plan_run(tid, T, s_minpos, 1, s_cnt[tid]);
}

// all-f32 window application (windows never feed decisions; err ~1e-7 << 1e-3)
__global__ void K_apply(const float* __restrict__ snd, float* __restrict__ out, int T) {
    for (int b = blockIdx.x; b < g_nops; b += gridDim.x) {
        int d0 = g_opd[b], s0 = g_opsrc[b], L = g_opl[b], n = g_opn[b];
        float invn = 6.2831853071795864f / (float)n;
        for (int k = threadIdx.x; k < L; k += blockDim.x) {
            float wf = 0.5f - 0.5f * cosf((float)k * invn);
            atomicAdd(out + d0 + k, wf * snd[s0 + k]);
        }
    }
}

__global__ void K_tail(const float* __restrict__ snd, float* __restrict__ out, int T) {
    int t = blockIdx.x*blockDim.x + threadIdx.x;
    if (t >= T) return;
    if (g_copy || t >= g_tail) out[t] = snd[t];
}

extern "C" void kernel_launch(void* const* d_in, const int* in_sizes, int n_in,
                              void* d_out, int out_size) {
    const float* snd   = (const float*)d_in[0];
    const float* pitch = (const float*)d_in[1];
    const int*   steps = (const int*)d_in[2];
    const float* prng  = (const float*)d_in[3];
    float* out = (float*)d_out;
    int T = in_sizes[0];
    int S = in_sizes[1];

    K_init<<<1,256>>>(S, T);
    K_zero<<<GRID(T,256),256>>>(out, T);
    K_absmax<<<512,256>>>(snd, T);
    K_median<<<1,512>>>(pitch, S, steps);
    K_interp<<<GRID(T,256),256>>>(pitch, S, T);
    K_shift<<<GRID(T,256),256>>>(prng, T);
    K_mark<<<GRID(T,256),256>>>(T);
    K_sortruns<<<1,1>>>();
    K_backup<<<MAXRUNS,1>>>(snd, T);
    K_walk<<<NWALK,WTW>>>(snd, T);
    K_filter<<<1,64>>>();
    K_collect<<<1,256>>>();
    K_rank<<<64,256>>>(T);
    K_plan<<<1,64>>>(T);
    K_apply<<<2048,128>>>(snd, out, T);
    K_tail<<<GRID(T,256),256>>>(snd, out, T);
}

// round 14
// speedup vs baseline: 1.3711x; 1.3399x over previous
#include <cuda_runtime.h>
#include <math.h>
#include <limits.h>

#define MAXT 700000
#define MAXRUNS 64
#define NWALK (2*MAXRUNS)
#define CANDW 2048
#define MAXPK 16384
#define PCAP 11776
#define MAXOPS 8192
#define MAXC 256
#define MAXW 400
#define MS 4096
#define WIN 960
#define WTW 512
#define CEPS 1e-4f
#define GRID(n,b) (((n)+(b)-1)/(b))

__device__ float g_f0[MAXT];
__device__ float g_f0s[MAXT];
__device__ double g_scale;
__device__ unsigned g_absbits;
__device__ int g_anygate;
__device__ unsigned g_minbits;
__device__ float g_median;
__device__ float g_factor32, g_mshift32;

__device__ int g_st0[MAXRUNS], g_en0[MAXRUNS], g_st1[MAXRUNS], g_en1[MAXRUNS];
__device__ int g_cs0, g_ce0, g_cs1, g_ce1;
__device__ int g_runL0[MAXRUNS], g_runR0[MAXRUNS], g_nruns0;
__device__ int g_runL1[MAXRUNS], g_runR1[MAXRUNS], g_nruns1;
__device__ int g_tail, g_copy;
__device__ int g_backup[MAXRUNS];

__device__ int g_wci[NWALK*CANDW];
__device__ int g_wcw[NWALK*CANDW];
__device__ int g_wcnt[NWALK];
__device__ int g_lastApp[MAXRUNS];

__device__ int g_cand[MAXPK];
__device__ int g_ncand, g_npk;
__device__ int g_peaks[MAXPK];

__device__ int g_opd[MAXOPS], g_opsrc[MAXOPS], g_opl[MAXOPS], g_opn[MAXOPS];
__device__ int g_nops;

__device__ __forceinline__ int pyslen(long start, long stop, long n) {
    if (start < 0) start += n; if (start < 0) start = 0; if (start > n) start = n;
    if (stop  < 0) stop  += n; if (stop  < 0) stop  = 0; if (stop  > n) stop  = n;
    long L = stop - start; return L > 0 ? (int)L : 0;
}
__device__ __forceinline__ int dev_lb(const int* a, int n, int v) {
    int lo = 0, hi = n;
    while (lo < hi) { int m = (lo+hi)>>1; if (a[m] < v) lo = m+1; else hi = m; }
    return lo;
}

// exact test p*f <= 22050 (real arithmetic) via f32 TwoProd; p < 2^24
__device__ __forceinline__ bool pmul_le(int p, float f) {
    float pf = (float)p;
    float hi = __fmul_rn(pf, f);
    float lo = __fmaf_rn(pf, f, -hi);
    return (hi < 22050.f) || (hi == 22050.f && lo <= 0.f);
}
__device__ __forceinline__ int floor_div_22050(float fm) {
    int p = (int)(22050.f / fm);
    while (p > 0 && !pmul_le(p, fm)) p--;
    while (pmul_le(p + 1, fm)) p++;
    return p;
}
// exact test d * mp <= 27562.5 (real) via TwoProd; d < 2^24
__device__ __forceinline__ bool dmul_le_maxw(long d, float mp) {
    float df = (float)d;
    float hi = __fmul_rn(df, mp);
    float lo = __fmaf_rn(df, mp, -hi);
    return (hi < 27562.5f) || (hi == 27562.5f && lo <= 0.f);
}

// numpy FLOAT_pairwise_sum of squares, 4-lane cooperative, bit-exact.
__device__ float np_psq4(const float* a, int n, int lane) {
    if (n < 8) {
        float r = 0.f;
        for (int i = 0; i < n; i++) r = __fadd_rn(r, __fmul_rn(a[i], a[i]));
        return r;
    }
    if (n <= 128) {
        int nb = n - (n % 8);
        int c0 = 2*lane, c1 = 2*lane + 1;
        float ra = __fmul_rn(a[c0], a[c0]);
        float rb = __fmul_rn(a[c1], a[c1]);
        for (int i = 8; i < nb; i += 8) {
            ra = __fadd_rn(ra, __fmul_rn(a[i+c0], a[i+c0]));
            rb = __fadd_rn(rb, __fmul_rn(a[i+c1], a[i+c1]));
        }
        float u = __fadd_rn(ra, rb);
        float u1 = __shfl_down_sync(0xFFFFFFFFu, u, 1, 4);
        float t  = __fadd_rn(u, u1);
        float t2 = __shfl_down_sync(0xFFFFFFFFu, t, 2, 4);
        float res = __fadd_rn(t, t2);
        for (int i = nb; i < n; i++) res = __fadd_rn(res, __fmul_rn(a[i], a[i]));
        return res;
    }
    int n2 = n / 2; n2 -= n2 % 8;
    float L = np_psq4(a, n2, lane);
    float R = np_psq4(a + n2, n - n2, lane);
    return __fadd_rn(L, R);
}

__global__ void K_init(int S, int T) {
    int t = threadIdx.x;
    if (t == 0) {
        g_absbits = 0u; g_anygate = 0; g_minbits = 0xFFFFFFFFu; g_median = 0.f;
        g_cs0 = g_ce0 = g_cs1 = g_ce1 = 0; g_nruns0 = g_nruns1 = 0;
        g_tail = 0; g_copy = 0; g_ncand = 0; g_npk = 0; g_nops = 0;
        g_scale = __ddiv_rn((double)S, (double)T);
    }
    for (int i = t; i < NWALK; i += blockDim.x) g_wcnt[i] = 0;
    for (int i = t; i < MAXRUNS; i += blockDim.x) g_lastApp[i] = INT_MIN;
}

__global__ void K_zero(float* out, int T) {
    int t = blockIdx.x*blockDim.x + threadIdx.x;
    if (t < T) out[t] = 0.f;
}

__global__ void K_absmax(const float* __restrict__ x, int T) {
    float m = 0.f;
    for (int i = blockIdx.x*blockDim.x + threadIdx.x; i < T; i += gridDim.x*blockDim.x)
        m = fmaxf(m, fabsf(x[i]));
    for (int o = 16; o; o >>= 1) m = fmaxf(m, __shfl_down_sync(0xFFFFFFFFu, m, o));
    if ((threadIdx.x & 31) == 0) atomicMax(&g_absbits, __float_as_uint(m));
}

__global__ void K_median(const float* __restrict__ p, int S, const int* __restrict__ stepsPtr) {
    __shared__ float buf[MS];
    __shared__ int sh_np, sh_any;
    int tid = threadIdx.x;
    if (tid == 0) { sh_np = 0; sh_any = 0; }
    __syncthreads();
    int cany = 0;
    for (int j = tid; j < S && j < MS; j += 512) {
        float v = p[j];
        if (v > 0.f) { int idx = atomicAdd(&sh_np, 1); buf[idx] = v; }
        if (v > 1e-5f) cany = 1;
    }
    if (cany) atomicOr(&sh_any, 1);
    __syncthreads();
    int npos = sh_np;
    for (int i = npos + tid; i < MS; i += 512) buf[i] = INFINITY;
    __syncthreads();
    for (int k = 2; k <= MS; k <<= 1) {
        for (int j = k >> 1; j > 0; j >>= 1) {
            for (int i = tid; i < MS; i += 512) {
                int ixj = i ^ j;
                if (ixj > i) {
                    float a = buf[i], b = buf[ixj];
                    bool up = ((i & k) == 0);
                    if ((a > b) == up) { buf[i] = b; buf[ixj] = a; }
                }
            }
            __syncthreads();
        }
    }
    if (tid == 0) {
        g_anygate = sh_any;
        double fac = pow(2.0, (double)stepsPtr[0] / 12.0);
        g_factor32 = (float)fac;
        if (npos > 0) g_median = buf[(npos - 1) >> 1];
        g_mshift32 = (float)((double)g_median * fac);
    }
}

__global__ void K_interp(const float* __restrict__ p, int S, int T) {
    int t = blockIdx.x*blockDim.x + threadIdx.x;
    if (t >= T) return;
    double x = __dadd_rn(__dmul_rn(__dadd_rn((double)t, 0.5), g_scale), -0.5);
    if (x < 0.0) x = 0.0;
    double hi = (double)(S - 1);
    if (x > hi) x = hi;
    long i0 = (long)floor(x);
    long i1 = i0 + 1; if (i1 > (long)(S-1)) i1 = S - 1;
    float f = (float)__dsub_rn(x, (double)i0);
    g_f0[t] = __fadd_rn(__fmul_rn(p[i0], __fsub_rn(1.0f, f)), __fmul_rn(p[i1], f));
}

__global__ void K_shift(const float* __restrict__ prp, int T) {
    int t = blockIdx.x*blockDim.x + threadIdx.x;
    float res = 0.f;
    if (t < T) {
        float fs = __fmul_rn(g_f0[t], g_factor32);
        float m = g_mshift32;
        if (fs > 0.f) res = __fadd_rn(m, __fmul_rn(__fsub_rn(fs, m), prp[0]));
        g_f0s[t] = res;
    }
    unsigned mb = (t < T && res > 0.f) ? __float_as_uint(res) : 0xFFFFFFFFu;
    for (int o = 16; o; o >>= 1) mb = min(mb, __shfl_down_sync(0xFFFFFFFFu, mb, o));
    if ((threadIdx.x & 31) == 0 && mb != 0xFFFFFFFFu) atomicMin(&g_minbits, mb);
}

__global__ void K_mark(int T) {
    int t = blockIdx.x*blockDim.x + threadIdx.x;
    if (t >= T) return;
    if (g_f0[t] > 0.f) {
        bool pr = (t > 0) && (g_f0[t-1] > 0.f);
        bool nx = (t < T-1) && (g_f0[t+1] > 0.f);
        if (!pr) { int i = atomicAdd(&g_cs0,1); if (i < MAXRUNS) g_st0[i] = t; }
        if (!nx) { int i = atomicAdd(&g_ce0,1); if (i < MAXRUNS) g_en0[i] = t+1; }
    }
    if (g_f0s[t] > 0.f) {
        bool pr = (t > 0) && (g_f0s[t-1] > 0.f);
        bool nx = (t < T-1) && (g_f0s[t+1] > 0.f);
        if (!pr) { int i = atomicAdd(&g_cs1,1); if (i < MAXRUNS) g_st1[i] = t; }
        if (!nx) { int i = atomicAdd(&g_ce1,1); if (i < MAXRUNS) g_en1[i] = t+1; }
    }
}

__device__ void sort_small(int* a, int n) {
    for (int i = 1; i < n; i++) {
        int v = a[i], j = i-1;
        while (j >= 0 && a[j] > v) { a[j+1] = a[j]; j--; }
        a[j+1] = v;
    }
}

__global__ void K_sortruns() {
    if (threadIdx.x || blockIdx.x) return;
    {
        int ns = min(g_cs0, MAXRUNS), ne = min(g_ce0, MAXRUNS);
        sort_small(g_st0, ns); sort_small(g_en0, ne);
        int n = min(ns, ne), off = 0;
        if (n > 0 && g_st0[0] == 0) { g_st0[0] = 1; if (g_st0[0] >= g_en0[0]) off = 1; }
        int m = 0;
        for (int k = off; k < n; k++) { g_runL0[m] = g_st0[k]; g_runR0[m] = g_en0[k]; m++; }
        g_nruns0 = m;
    }
    {
        int ns = min(g_cs1, MAXRUNS), ne = min(g_ce1, MAXRUNS);
        sort_small(g_st1, ns); sort_small(g_en1, ne);
        int n = min(ns, ne), off = 0;
        if (n > 0 && g_st1[0] == 0) { g_st1[0] = 1; if (g_st1[0] >= g_en1[0]) off = 1; }
        int m = 0;
        for (int k = off; k < n; k++) { g_runL1[m] = g_st1[k]; g_runR1[m] = g_en1[k]; m++; }
        g_nruns1 = m;
    }
}

__global__ void K_backup(const float* __restrict__ sig, int T) {
    int run = blockIdx.x;
    if (run >= g_nruns0 || threadIdx.x != 0) return;
    int left = g_runL0[run], right = g_runR0[run];
    int middle = (left + right) / 2;
    double wd = __ddiv_rn(22050.0, (double)g_f0[middle]);
    long w = (wd > 2.0e9) ? 2000000000L : (long)wd;
    long s = (long)middle - w/2; if (s < 0) s = 0;
    long len = w; if (s + len > T) len = T - s;
    float mn = INFINITY, mx = -INFINITY; long imn = 0, imx = 0;
    for (long k = 0; k < len; k++) {
        float v = sig[s+k];
        if (v < mn) { mn = v; imn = k; }
        if (v > mx) { mx = v; imx = k; }
    }
    g_backup[run] = (mn == mx) ? middle
                  : (int)(s + ((fabs((double)mn) > fabs((double)mx)) ? imn : imx));
}

// Merged walk; geometry (f64) on thread 0 ONLY, broadcast via smem.
__global__ __launch_bounds__(WTW) void K_walk(const float* __restrict__ sig, int T) {
    __shared__ float win[WIN];
    __shared__ float s_b[MAXW];
    __shared__ float s_q[MAXC], s_ma[MAXC], s_na[MAXC];
    __shared__ int   s_cl[MAXC];
    __shared__ int   sM;
    __shared__ float s_pv[WTW/32];
    __shared__ int   s_pi[WTW/32];
    __shared__ float sBV;
    __shared__ int sGeo[8];
    int b = blockIdx.x;
    int dir = (b < MAXRUNS) ? 1 : 0;
    int run = dir ? b : (b - MAXRUNS);
    if (run >= g_nruns0) return;
    int tid = threadIdx.x, lane4 = tid & 3, grp = tid >> 2, wrp = tid >> 5, wl = tid & 31;
    int left = g_runL0[run], right = g_runR0[run];
    double gp = (double)__uint_as_float(g_absbits);
    long base = (long)b * CANDW;
    int cnt = 0, lastApp = INT_MIN;
    int i = 0;
    if (tid == 0) i = g_backup[run];
    while (true) {
        if (tid == 0) {
            double f0i = (double)g_f0[i];
            double fm = f0i > 60.0 ? f0i : 60.0;
            int w = (int)__ddiv_rn(22050.0, fm);
            int s = i - w/2; if (s < 0) s = 0;
            int cl, cr;
            if (dir) {
                cl = (int)__dadd_rn((double)i, __dmul_rn(0.3,  (double)w));
                cr = (int)__dadd_rn((double)i, __dmul_rn(0.75, (double)w));
            } else {
                int a1 = (int)__dsub_rn((double)i, __dmul_rn(1.75, (double)w)); cl = a1 > 0 ? a1 : 0;
                int a2 = (int)__dsub_rn((double)i, __dmul_rn(1.3,  (double)w)); cr = a2 > 0 ? a2 : 0;
            }
            int valid = 0, nc = 0, base0 = 0, WL = 0;
            if (!(cl == cr || (T - cl) < w)) {
                long hi = (long)cr + w; if (hi > T) hi = T;
                nc = (int)(hi - cl - w + 1);
                valid = (nc >= 1 && nc <= MAXC && w <= MAXW && s + w <= T);
            }
            if (valid) {
                base0 = min(s, cl);
                int e1 = s + w, e2 = cl + nc - 1 + w;
                WL = (e1 > e2 ? e1 : e2) - base0;
                if (WL > WIN) valid = 0;
            }
            sGeo[0]=w; sGeo[1]=s; sGeo[2]=cl; sGeo[3]=nc; sGeo[4]=valid;
            sGeo[5]=base0; sGeo[6]=WL;
            sM = 0;
        }
        __syncthreads();
        int w = sGeo[0], s = sGeo[1], cl = sGeo[2], nc = sGeo[3];
        int valid = sGeo[4], base0 = sGeo[5], WL = sGeo[6];
        if (valid) {
            for (int k = tid; k < WL; k += WTW) win[k] = sig[base0 + k];
            __syncthreads();
            if (wrp == 0) {
                const float* rp = win + (s - base0);
                float psq = np_psq4(rp, w, lane4);
                float nb = __shfl_sync(0xFFFFFFFFu, psq, 0);
                nb = fmaxf(__fsqrt_rn(nb), 1e-12f);
                for (int k = wl; k < w; k += 32) s_b[k] = __fdiv_rn(rp[k], nb);
            }
            __syncthreads();
            const float* cb = win + (cl - base0);
            int w4 = w & ~3;
            for (int c0 = 0; c0 < nc; c0 += WTW/4) {
                int c = c0 + grp;
                int cc = c < nc ? c : nc - 1;
                const float* ap = cb + cc;
                float psq = np_psq4(ap, w, lane4);
                float na = 0.f;
                if (lane4 == 0) na = fmaxf(__fsqrt_rn(psq), 1e-12f);
                float acc = 0.f, ma = 0.f;
                for (int k = lane4; k < w4; k += 4) {
                    float v = ap[k];
                    ma = fmaxf(ma, fabsf(v));
                    acc = fmaf(v, s_b[k], acc);
                }
                float a1 = __shfl_down_sync(0xFFFFFFFFu, acc, 1, 4);
                float ssum = __fadd_rn(acc, a1);
                float a2 = __shfl_down_sync(0xFFFFFFFFu, ssum, 2, 4);
                float res = __fadd_rn(ssum, a2);
                float m1 = __shfl_down_sync(0xFFFFFFFFu, ma, 1, 4);
                ma = fmaxf(ma, m1);
                float m2 = __shfl_down_sync(0xFFFFFFFFu, ma, 2, 4);
                ma = fmaxf(ma, m2);
                if (lane4 == 0 && c < nc) {
                    for (int k = w4; k < w; k++) {
                        float v = ap[k];
                        ma = fmaxf(ma, fabsf(v));
                        res = fmaf(v, s_b[k], res);
                    }
                    s_q[cc] = __fdiv_rn(res, na);
                    s_ma[cc] = ma; s_na[cc] = na;
                }
            }
            __syncthreads();
            {
                float v = (tid < nc) ? s_q[tid] : -INFINITY;
                for (int o = 16; o; o >>= 1)
                    v = fmaxf(v, __shfl_down_sync(0xFFFFFFFFu, v, o));
                if (wl == 0) s_pv[wrp] = v;
            }
            __syncthreads();
            if (tid == 0) {
                float bv = s_pv[0];
                for (int q = 1; q < WTW/32; q++) bv = fmaxf(bv, s_pv[q]);
                sBV = bv;
            }
            __syncthreads();
            for (int c = tid; c < nc; c += WTW) {
                if (s_q[c] >= sBV - CEPS) {
                    int sl = atomicAdd(&sM, 1);
                    s_cl[sl] = c;
                } else {
                    s_q[c] = -INFINITY;
                }
            }
            __syncthreads();
            int m = sM;
            for (int j0 = 0; j0 < m; j0 += WTW/4) {
                if (j0 + (wrp << 3) < m) {
                    int ji = j0 + grp;
                    int jj = ji < m ? ji : m - 1;
                    int c = s_cl[jj];
                    const float* ap = cb + c;
                    float na = s_na[c];
                    float acc = 0.f;
                    for (int k = lane4; k < w4; k += 4)
                        acc = fmaf(__fdiv_rn(ap[k], na), s_b[k], acc);
                    float a1 = __shfl_down_sync(0xFFFFFFFFu, acc, 1, 4);
                    float ssum = __fadd_rn(acc, a1);
                    float a2 = __shfl_down_sync(0xFFFFFFFFu, ssum, 2, 4);
                    float res = __fadd_rn(ssum, a2);
                    if (lane4 == 0 && ji < m) {
                        for (int k = w4; k < w; k++)
                            res = fmaf(__fdiv_rn(ap[k], na), s_b[k], res);
                        s_q[c] = res;
                    }
                }
            }
            __syncthreads();
            {
                float v = (tid < nc) ? s_q[tid] : -INFINITY;
                int idx = tid;
                for (int o = 16; o; o >>= 1) {
                    float vo = __shfl_down_sync(0xFFFFFFFFu, v, o);
                    int   io = __shfl_down_sync(0xFFFFFFFFu, idx, o);
                    if (vo > v || (vo == v && io < idx)) { v = vo; idx = io; }
                }
                if (wl == 0) { s_pv[wrp] = v; s_pi[wrp] = idx; }
            }
            __syncthreads();
        }
        if (tid == 0) {
            double corr = -1.0, peak = 0.0;
            int stop = 0;
            if (valid) {
                float bv = s_pv[0]; int br = s_pi[0];
                for (int q = 1; q < WTW/32; q++)
                    if (s_pv[q] > bv || (s_pv[q] == bv && s_pi[q] < br)) { bv = s_pv[q]; br = s_pi[q]; }
                corr = (double)s_q[br];
                peak = (double)s_ma[br];
                i = i + (br + cl) - s;
            }
            bool neg1 = (corr == -1.0);
            if (dir) {
                if (neg1) i += w;
                if (i >= right) {
                    if (corr > 0.7 && peak > __dmul_rn(0.023333, gp)) {
                        if (cnt < CANDW) g_wci[base+cnt] = i;
                        cnt++; lastApp = i;
                    }
                    stop = 1;
                } else if (corr > 0.3 && (peak == 0.0 || peak > __dmul_rn(0.01, gp))) {
                    if (cnt < CANDW) g_wci[base+cnt] = i;
                    cnt++; lastApp = i;
                }
            } else {
                if (neg1) i -= w;
                if (i < left) {
                    if (corr > 0.7 && peak > __dmul_rn(0.023333, gp)) {
                        if (cnt < CANDW) { g_wci[base+cnt] = i; g_wcw[base+cnt] = w; }
                        cnt++;
                    }
                    stop = 1;
                } else if (corr > 0.3 && (peak == 0.0 || peak > __dmul_rn(0.01, gp))) {
                    if (cnt < CANDW) { g_wci[base+cnt] = i; g_wcw[base+cnt] = w; }
                    cnt++;
                }
            }
            sGeo[7] = stop;
        }
        __syncthreads();
        if (sGeo[7]) break;
    }
    if (tid == 0) {
        g_wcnt[b] = min(cnt, CANDW);
        if (dir) g_lastApp[run] = lastApp;
    }
}

// integer-exact AR filter: i - AR > 0.8*w  <=>  5*(i-AR) > 4*w
__global__ void K_filter() {
    __shared__ long sAR[MAXRUNS];
    int tid = threadIdx.x;
    int nr = g_nruns0;
    if (tid == 0) {
        long cur = LONG_MIN / 4;
        for (int r = 0; r < nr; r++) {
            sAR[r] = cur;
            if (g_lastApp[r] != INT_MIN) cur = (long)g_lastApp[r];
        }
    }
    __syncthreads();
    if (tid < nr) {
        long base = (long)(MAXRUNS + tid) * CANDW;
        int c = g_wcnt[MAXRUNS + tid], m = 0;
        long AR = sAR[tid];
        for (int j = 0; j < c; j++) {
            int i = g_wci[base + j], w = g_wcw[base + j];
            bool pass;
            if (AR <= LONG_MIN / 8) pass = true;
            else pass = 5L * ((long)i - AR) > 4L * (long)w;
            if (pass) { g_wci[base + m] = i; m++; }
        }
        g_wcnt[MAXRUNS + tid] = m;
    }
}

__global__ void K_collect() {
    __shared__ int s_off[NWALK];
    int tid = threadIdx.x;
    if (tid == 0) {
        int acc = 0;
        for (int sl = 0; sl < NWALK; sl++) { s_off[sl] = acc; acc += g_wcnt[sl]; }
        g_ncand = min(acc, MAXPK);
    }
    __syncthreads();
    for (int sl = 0; sl < NWALK; sl++) {
        int c = g_wcnt[sl], o = s_off[sl];
        for (int j = tid; j < c; j += blockDim.x)
            if (o + j < MAXPK) g_cand[o+j] = g_wci[(long)sl*CANDW + j];
    }
}

__global__ void K_rank(int T) {
    int N = g_ncand;
    for (int j = blockIdx.x*blockDim.x + threadIdx.x; j < N; j += gridDim.x*blockDim.x) {
        int v = g_cand[j], rk = 0;
        for (int k = 0; k < N; k++) {
            int u = g_cand[k];
            rk += (u < v) || (u == v && k < j);
        }
        int cv = v; if (cv < 0) cv = 0; if (cv > T-1) cv = T-1;
        g_peaks[rk] = cv;
    }
    if (blockIdx.x == 0 && threadIdx.x == 0) g_npk = N;
}

// plan with smem-staged peaks + incremental lower-bound (identical decisions)
__device__ int plan_run2(const int* __restrict__ pk, int npk, int r, int T,
                         float minpos, int write, int base) {
    int left_v = g_runL1[r], right_v = g_runR1[r];
    int prevR = (r == 0) ? 0 : g_runR1[r-1];
    int cnt = 0;
    if (prevR < left_v) {
        if (write && base+cnt < MAXOPS) {
            g_opd[base+cnt] = prevR; g_opsrc[base+cnt] = prevR;
            g_opl[base+cnt] = left_v - prevR; g_opn[base+cnt] = left_v - prevR;
        }
        cnt++;
    }
    int q = dev_lb(pk, npk, left_v);
    while (left_v < right_v) {
        while (q < npk && pk[q] < left_v) q++;   // maintain lower-bound invariant
        int p;
        if (q == 0) p = 0;
        else if (q >= npk) {
            p = npk - 1;
            int v = pk[npk-1];
            while (p > 0 && pk[p-1] == v) p--;   // first occurrence
        } else {
            long d1 = (long)left_v - pk[q-1], d2 = (long)pk[q] - left_v;
            if (d1 <= d2) {
                p = q - 1;
                int v = pk[q-1];
                while (p > 0 && pk[p-1] == v) p--;
            } else p = q;
        }
        float fv = g_f0s[left_v];
        float fm = fv > 60.f ? fv : 60.f;
        int period = floor_div_22050(fm);
        int left_w = period/2, right_w = period/2;
        if (p > 0) {
            long d = (long)pk[p] - pk[p-1];
            if (dmul_le_maxw(d, minpos)) left_w = min((int)d, left_w);
        }
        if (p < npk-1) {
            long d = (long)pk[p+1] - pk[p];
            if (dmul_le_maxw(d, minpos)) right_w = min((int)d, right_w);
        }
        int left_i = pk[p] - left_w; if (left_i < 0) left_i = 0;
        int right_i = pk[p] + right_w;
        int ival = (right_i - left_i) / 2;
        if (ival <= 0) break;
        long a = (long)left_v - ival;
        int seglen = min(pyslen(a, (long)left_v + ival, T),
                         pyslen(left_i, (long)left_i + 2L*ival, T));
        int Ld = pyslen(a, a + seglen, T);
        int Ls = pyslen(left_i, (long)left_i + seglen, T);
        int L = min(min(Ld, Ls), seglen);
        if (write && base+cnt < MAXOPS) {
            long as_ = a < 0 ? a + T : a;
            g_opd[base+cnt] = (int)as_; g_opsrc[base+cnt] = left_i;
            g_opl[base+cnt] = L; g_opn[base+cnt] = 2*ival;
        }
        cnt++;
        left_v += ival * 2;
    }
    return cnt;
}

__global__ __launch_bounds__(256) void K_plan(int T) {
    __shared__ int s_pk[PCAP];
    __shared__ int s_cnt[MAXRUNS];
    __shared__ float s_minpos;
    int tid = threadIdx.x;
    if (tid == 0) {
        g_copy = (!g_anygate || g_npk == 0) ? 1 : 0;
        s_minpos = __uint_as_float(g_minbits);
        g_tail = 0; g_nops = 0;
    }
    __syncthreads();
    if (g_copy) return;
    int npk = g_npk;
    const int* pk = g_peaks;
    if (npk <= PCAP) {
        for (int i = tid; i < npk; i += 256) s_pk[i] = g_peaks[i];
        pk = s_pk;
    }
    __syncthreads();
    int nr = g_nruns1;
    if (tid == 0 && nr > 0) g_tail = g_runR1[nr-1];
    if (tid < nr) s_cnt[tid] = plan_run2(pk, npk, tid, T, s_minpos, 0, 0);
    __syncthreads();
    if (tid == 0) {
        int acc = 0;
        for (int r = 0; r < nr; r++) { int c = s_cnt[r]; s_cnt[r] = acc; acc += c; }
        g_nops = min(acc, MAXOPS);
    }
    __syncthreads();
    if (tid < nr) plan_run2(pk, npk, tid, T, s_minpos, 1, s_cnt[tid]);
}

// all-f32 window application (windows never feed decisions)
__global__ void K_apply(const float* __restrict__ snd, float* __restrict__ out, int T) {
    for (int b = blockIdx.x; b < g_nops; b += gridDim.x) {
        int d0 = g_opd[b], s0 = g_opsrc[b], L = g_opl[b], n = g_opn[b];
        float invn = 6.2831853071795864f / (float)n;
        for (int k = threadIdx.x; k < L; k += blockDim.x) {
            float wf = 0.5f - 0.5f * cosf((float)k * invn);
            atomicAdd(out + d0 + k, wf * snd[s0 + k]);
        }
    }
}

__global__ void K_tail(const float* __restrict__ snd, float* __restrict__ out, int T) {
    int t = blockIdx.x*blockDim.x + threadIdx.x;
    if (t >= T) return;
    if (g_copy || t >= g_tail) out[t] = snd[t];
}

extern "C" void kernel_launch(void* const* d_in, const int* in_sizes, int n_in,
                              void* d_out, int out_size) {
    const float* snd   = (const float*)d_in[0];
    const float* pitch = (const float*)d_in[1];
    const int*   steps = (const int*)d_in[2];
    const float* prng  = (const float*)d_in[3];
    float* out = (float*)d_out;
    int T = in_sizes[0];
    int S = in_sizes[1];

    K_init<<<1,256>>>(S, T);
    K_zero<<<GRID(T,256),256>>>(out, T);
    K_absmax<<<512,256>>>(snd, T);
    K_median<<<1,512>>>(pitch, S, steps);
    K_interp<<<GRID(T,256),256>>>(pitch, S, T);
    K_shift<<<GRID(T,256),256>>>(prng, T);
    K_mark<<<GRID(T,256),256>>>(T);
    K_sortruns<<<1,1>>>();
    K_backup<<<MAXRUNS,1>>>(snd, T);
    K_walk<<<NWALK,WTW>>>(snd, T);
    K_filter<<<1,64>>>();
    K_collect<<<1,256>>>();
    K_rank<<<64,256>>>(T);
    K_plan<<<1,256>>>(T);
    K_apply<<<2048,128>>>(snd, out, T);
    K_tail<<<GRID(T,256),256>>>(snd, out, T);
}

// round 15
// speedup vs baseline: 1.4995x; 1.0937x over previous
#include <cuda_runtime.h>
#include <math.h>
#include <limits.h>

#define MAXT 700000
#define MAXRUNS 64
#define NWALK (2*MAXRUNS)
#define CANDW 2048
#define MAXPK 16384
#define PCAP 11776
#define OPR 256
#define MAXC 256
#define MAXW 400
#define MS 4096
#define WIN 960
#define WTW 512
#define CEPS 1e-4f
#define GRID(n,b) (((n)+(b)-1)/(b))

__device__ float g_f0[MAXT];
__device__ float g_f0s[MAXT];
__device__ double g_scale;
__device__ unsigned g_absbits;
__device__ int g_anygate;
__device__ unsigned g_minbits;
__device__ float g_median;
__device__ float g_factor32, g_mshift32;

__device__ int g_st0[MAXRUNS], g_en0[MAXRUNS], g_st1[MAXRUNS], g_en1[MAXRUNS];
__device__ int g_cs0, g_ce0, g_cs1, g_ce1;
__device__ int g_runL0[MAXRUNS], g_runR0[MAXRUNS], g_nruns0;
__device__ int g_runL1[MAXRUNS], g_runR1[MAXRUNS], g_nruns1;
__device__ int g_tail, g_copy;
__device__ int g_backup[MAXRUNS];

__device__ int g_wci[NWALK*CANDW];
__device__ int g_wcw[NWALK*CANDW];
__device__ int g_wcnt[NWALK];
__device__ int g_lastApp[MAXRUNS];

__device__ int g_cand[MAXPK];
__device__ int g_ncand, g_npk;
__device__ int g_peaks[MAXPK];

__device__ int g_opd[MAXRUNS*OPR], g_opsrc[MAXRUNS*OPR], g_opl[MAXRUNS*OPR], g_opn[MAXRUNS*OPR];
__device__ int g_opcnt[MAXRUNS];

__device__ __forceinline__ int pyslen(long start, long stop, long n) {
    if (start < 0) start += n; if (start < 0) start = 0; if (start > n) start = n;
    if (stop  < 0) stop  += n; if (stop  < 0) stop  = 0; if (stop  > n) stop  = n;
    long L = stop - start; return L > 0 ? (int)L : 0;
}
__device__ __forceinline__ int dev_lb(const int* a, int n, int v) {
    int lo = 0, hi = n;
    while (lo < hi) { int m = (lo+hi)>>1; if (a[m] < v) lo = m+1; else hi = m; }
    return lo;
}
__device__ __forceinline__ unsigned fenc(float f) {
    unsigned b = __float_as_uint(f);
    return (b & 0x80000000u) ? ~b : (b | 0x80000000u);
}
__device__ __forceinline__ float fdec(unsigned u) {
    return (u & 0x80000000u) ? __uint_as_float(u & 0x7FFFFFFFu) : __uint_as_float(~u);
}

// exact test p*f <= 22050 via f32 TwoProd
__device__ __forceinline__ bool pmul_le(int p, float f) {
    float pf = (float)p;
    float hi = __fmul_rn(pf, f);
    float lo = __fmaf_rn(pf, f, -hi);
    return (hi < 22050.f) || (hi == 22050.f && lo <= 0.f);
}
__device__ __forceinline__ int floor_div_22050(float fm) {
    int p = (int)(22050.f / fm);
    while (p > 0 && !pmul_le(p, fm)) p--;
    while (pmul_le(p + 1, fm)) p++;
    return p;
}
__device__ __forceinline__ bool dmul_le_maxw(long d, float mp) {
    float df = (float)d;
    float hi = __fmul_rn(df, mp);
    float lo = __fmaf_rn(df, mp, -hi);
    return (hi < 27562.5f) || (hi == 27562.5f && lo <= 0.f);
}

// numpy FLOAT_pairwise_sum of squares, 4-lane cooperative, bit-exact.
__device__ float np_psq4(const float* a, int n, int lane) {
    if (n < 8) {
        float r = 0.f;
        for (int i = 0; i < n; i++) r = __fadd_rn(r, __fmul_rn(a[i], a[i]));
        return r;
    }
    if (n <= 128) {
        int nb = n - (n % 8);
        int c0 = 2*lane, c1 = 2*lane + 1;
        float ra = __fmul_rn(a[c0], a[c0]);
        float rb = __fmul_rn(a[c1], a[c1]);
        for (int i = 8; i < nb; i += 8) {
            ra = __fadd_rn(ra, __fmul_rn(a[i+c0], a[i+c0]));
            rb = __fadd_rn(rb, __fmul_rn(a[i+c1], a[i+c1]));
        }
        float u = __fadd_rn(ra, rb);
        float u1 = __shfl_down_sync(0xFFFFFFFFu, u, 1, 4);
        float t  = __fadd_rn(u, u1);
        float t2 = __shfl_down_sync(0xFFFFFFFFu, t, 2, 4);
        float res = __fadd_rn(t, t2);
        for (int i = nb; i < n; i++) res = __fadd_rn(res, __fmul_rn(a[i], a[i]));
        return res;
    }
    int n2 = n / 2; n2 -= n2 % 8;
    float L = np_psq4(a, n2, lane);
    float R = np_psq4(a + n2, n - n2, lane);
    return __fadd_rn(L, R);
}

__global__ void K_init(int S, int T) {
    int t = threadIdx.x;
    if (t == 0) {
        g_absbits = 0u; g_anygate = 0; g_minbits = 0xFFFFFFFFu; g_median = 0.f;
        g_cs0 = g_ce0 = g_cs1 = g_ce1 = 0; g_nruns0 = g_nruns1 = 0;
        g_tail = 0; g_copy = 0; g_ncand = 0; g_npk = 0;
        g_scale = __ddiv_rn((double)S, (double)T);
    }
    for (int i = t; i < NWALK; i += blockDim.x) g_wcnt[i] = 0;
    for (int i = t; i < MAXRUNS; i += blockDim.x) { g_lastApp[i] = INT_MIN; g_opcnt[i] = 0; }
}

__global__ void K_zero(float* out, int T) {
    int t = blockIdx.x*blockDim.x + threadIdx.x;
    if (t < T) out[t] = 0.f;
}

__global__ void K_absmax(const float* __restrict__ x, int T) {
    float m = 0.f;
    for (int i = blockIdx.x*blockDim.x + threadIdx.x; i < T; i += gridDim.x*blockDim.x)
        m = fmaxf(m, fabsf(x[i]));
    for (int o = 16; o; o >>= 1) m = fmaxf(m, __shfl_down_sync(0xFFFFFFFFu, m, o));
    if ((threadIdx.x & 31) == 0) atomicMax(&g_absbits, __float_as_uint(m));
}

__global__ void K_median(const float* __restrict__ p, int S, const int* __restrict__ stepsPtr) {
    __shared__ float buf[MS];
    __shared__ int sh_np, sh_any;
    int tid = threadIdx.x;
    if (tid == 0) { sh_np = 0; sh_any = 0; }
    __syncthreads();
    int cany = 0;
    for (int j = tid; j < S && j < MS; j += 512) {
        float v = p[j];
        if (v > 0.f) { int idx = atomicAdd(&sh_np, 1); buf[idx] = v; }
        if (v > 1e-5f) cany = 1;
    }
    if (cany) atomicOr(&sh_any, 1);
    __syncthreads();
    int npos = sh_np;
    for (int i = npos + tid; i < MS; i += 512) buf[i] = INFINITY;
    __syncthreads();
    for (int k = 2; k <= MS; k <<= 1) {
        for (int j = k >> 1; j > 0; j >>= 1) {
            for (int i = tid; i < MS; i += 512) {
                int ixj = i ^ j;
                if (ixj > i) {
                    float a = buf[i], b = buf[ixj];
                    bool up = ((i & k) == 0);
                    if ((a > b) == up) { buf[i] = b; buf[ixj] = a; }
                }
            }
            __syncthreads();
        }
    }
    if (tid == 0) {
        g_anygate = sh_any;
        double fac = pow(2.0, (double)stepsPtr[0] / 12.0);
        g_factor32 = (float)fac;
        if (npos > 0) g_median = buf[(npos - 1) >> 1];
        g_mshift32 = (float)((double)g_median * fac);
    }
}

// fused interp + shift + minbits
__global__ void K_interpshift(const float* __restrict__ p, const float* __restrict__ prp,
                              int S, int T) {
    int t = blockIdx.x*blockDim.x + threadIdx.x;
    float res = 0.f;
    if (t < T) {
        double x = __dadd_rn(__dmul_rn(__dadd_rn((double)t, 0.5), g_scale), -0.5);
        if (x < 0.0) x = 0.0;
        double hi = (double)(S - 1);
        if (x > hi) x = hi;
        long i0 = (long)floor(x);
        long i1 = i0 + 1; if (i1 > (long)(S-1)) i1 = S - 1;
        float f = (float)__dsub_rn(x, (double)i0);
        float f0v = __fadd_rn(__fmul_rn(p[i0], __fsub_rn(1.0f, f)), __fmul_rn(p[i1], f));
        g_f0[t] = f0v;
        float fs = __fmul_rn(f0v, g_factor32);
        float m = g_mshift32;
        if (fs > 0.f) res = __fadd_rn(m, __fmul_rn(__fsub_rn(fs, m), prp[0]));
        g_f0s[t] = res;
    }
    unsigned mb = (t < T && res > 0.f) ? __float_as_uint(res) : 0xFFFFFFFFu;
    for (int o = 16; o; o >>= 1) mb = min(mb, __shfl_down_sync(0xFFFFFFFFu, mb, o));
    if ((threadIdx.x & 31) == 0 && mb != 0xFFFFFFFFu) atomicMin(&g_minbits, mb);
}

__global__ void K_mark(int T) {
    int t = blockIdx.x*blockDim.x + threadIdx.x;
    if (t >= T) return;
    if (g_f0[t] > 0.f) {
        bool pr = (t > 0) && (g_f0[t-1] > 0.f);
        bool nx = (t < T-1) && (g_f0[t+1] > 0.f);
        if (!pr) { int i = atomicAdd(&g_cs0,1); if (i < MAXRUNS) g_st0[i] = t; }
        if (!nx) { int i = atomicAdd(&g_ce0,1); if (i < MAXRUNS) g_en0[i] = t+1; }
    }
    if (g_f0s[t] > 0.f) {
        bool pr = (t > 0) && (g_f0s[t-1] > 0.f);
        bool nx = (t < T-1) && (g_f0s[t+1] > 0.f);
        if (!pr) { int i = atomicAdd(&g_cs1,1); if (i < MAXRUNS) g_st1[i] = t; }
        if (!nx) { int i = atomicAdd(&g_ce1,1); if (i < MAXRUNS) g_en1[i] = t+1; }
    }
}

__device__ void sort_small(int* a, int n) {
    for (int i = 1; i < n; i++) {
        int v = a[i], j = i-1;
        while (j >= 0 && a[j] > v) { a[j+1] = a[j]; j--; }
        a[j+1] = v;
    }
}

__global__ void K_sortruns() {
    if (threadIdx.x || blockIdx.x) return;
    {
        int ns = min(g_cs0, MAXRUNS), ne = min(g_ce0, MAXRUNS);
        sort_small(g_st0, ns); sort_small(g_en0, ne);
        int n = min(ns, ne), off = 0;
        if (n > 0 && g_st0[0] == 0) { g_st0[0] = 1; if (g_st0[0] >= g_en0[0]) off = 1; }
        int m = 0;
        for (int k = off; k < n; k++) { g_runL0[m] = g_st0[k]; g_runR0[m] = g_en0[k]; m++; }
        g_nruns0 = m;
    }
    {
        int ns = min(g_cs1, MAXRUNS), ne = min(g_ce1, MAXRUNS);
        sort_small(g_st1, ns); sort_small(g_en1, ne);
        int n = min(ns, ne), off = 0;
        if (n > 0 && g_st1[0] == 0) { g_st1[0] = 1; if (g_st1[0] >= g_en1[0]) off = 1; }
        int m = 0;
        for (int k = off; k < n; k++) { g_runL1[m] = g_st1[k]; g_runR1[m] = g_en1[k]; m++; }
        g_nruns1 = m;
    }
}

// parallel backup: first-occurrence min/max (np.argmin/argmax semantics)
__global__ void K_backup(const float* __restrict__ sig, int T) {
    __shared__ float s_rv[2][8];
    __shared__ long  s_ri[2][8];
    int run = blockIdx.x;
    if (run >= g_nruns0) return;
    int tid = threadIdx.x, lane = tid & 31, wrp = tid >> 5;
    int left = g_runL0[run], right = g_runR0[run];
    int middle = (left + right) / 2;
    double wd = __ddiv_rn(22050.0, (double)g_f0[middle]);
    long w = (wd > 2.0e9) ? 2000000000L : (long)wd;
    long s = (long)middle - w/2; if (s < 0) s = 0;
    long len = w; if (s + len > T) len = T - s;
    float mn = INFINITY, mx = -INFINITY; long imn = LONG_MAX, imx = LONG_MAX;
    for (long k = tid; k < len; k += 256) {
        float v = sig[s+k];
        if (v < mn || (v == mn && k < imn)) { mn = v; imn = k; }
        if (v > mx || (v == mx && k < imx)) { mx = v; imx = k; }
    }
    for (int o = 16; o; o >>= 1) {
        float ov = __shfl_down_sync(0xFFFFFFFFu, mn, o);
        long  oi = __shfl_down_sync(0xFFFFFFFFu, imn, o);
        if (ov < mn || (ov == mn && oi < imn)) { mn = ov; imn = oi; }
        float ov2 = __shfl_down_sync(0xFFFFFFFFu, mx, o);
        long  oi2 = __shfl_down_sync(0xFFFFFFFFu, imx, o);
        if (ov2 > mx || (ov2 == mx && oi2 < imx)) { mx = ov2; imx = oi2; }
    }
    if (lane == 0) { s_rv[0][wrp] = mn; s_ri[0][wrp] = imn; s_rv[1][wrp] = mx; s_ri[1][wrp] = imx; }
    __syncthreads();
    if (tid == 0) {
        float bmn = INFINITY, bmx = -INFINITY; long bmni = LONG_MAX, bmxi = LONG_MAX;
        for (int q = 0; q < 8; q++) {
            float v = s_rv[0][q]; long i2 = s_ri[0][q];
            if (v < bmn || (v == bmn && i2 < bmni)) { bmn = v; bmni = i2; }
            float v2 = s_rv[1][q]; long i3 = s_ri[1][q];
            if (v2 > bmx || (v2 == bmx && i3 < bmxi)) { bmx = v2; bmxi = i3; }
        }
        g_backup[run] = (bmn == bmx) ? middle
                      : (int)(s + ((fabs((double)bmn) > fabs((double)bmx)) ? bmni : bmxi));
    }
}

// Merged walk; geometry thread-0 only; 8 barriers/step (bv via shared atomicMax encoding)
__global__ __launch_bounds__(WTW) void K_walk(const float* __restrict__ sig, int T) {
    __shared__ float win[WIN];
    __shared__ float s_b[MAXW];
    __shared__ float s_q[MAXC], s_ma[MAXC], s_na[MAXC];
    __shared__ int   s_cl[MAXC];
    __shared__ int   sM;
    __shared__ unsigned sEnc;
    __shared__ float s_pv[WTW/32];
    __shared__ int   s_pi[WTW/32];
    __shared__ int sGeo[8];
    int b = blockIdx.x;
    int dir = (b < MAXRUNS) ? 1 : 0;
    int run = dir ? b : (b - MAXRUNS);
    if (run >= g_nruns0) return;
    int tid = threadIdx.x, lane4 = tid & 3, grp = tid >> 2, wrp = tid >> 5, wl = tid & 31;
    int left = g_runL0[run], right = g_runR0[run];
    double gp = (double)__uint_as_float(g_absbits);
    long base = (long)b * CANDW;
    int cnt = 0, lastApp = INT_MIN;
    int i = 0;
    if (tid == 0) i = g_backup[run];
    while (true) {
        if (tid == 0) {
            double f0i = (double)g_f0[i];
            double fm = f0i > 60.0 ? f0i : 60.0;
            int w = (int)__ddiv_rn(22050.0, fm);
            int s = i - w/2; if (s < 0) s = 0;
            int cl, cr;
            if (dir) {
                cl = (int)__dadd_rn((double)i, __dmul_rn(0.3,  (double)w));
                cr = (int)__dadd_rn((double)i, __dmul_rn(0.75, (double)w));
            } else {
                int a1 = (int)__dsub_rn((double)i, __dmul_rn(1.75, (double)w)); cl = a1 > 0 ? a1 : 0;
                int a2 = (int)__dsub_rn((double)i, __dmul_rn(1.3,  (double)w)); cr = a2 > 0 ? a2 : 0;
            }
            int valid = 0, nc = 0, base0 = 0, WL = 0;
            if (!(cl == cr || (T - cl) < w)) {
                long hi = (long)cr + w; if (hi > T) hi = T;
                nc = (int)(hi - cl - w + 1);
                valid = (nc >= 1 && nc <= MAXC && w <= MAXW && s + w <= T);
            }
            if (valid) {
                base0 = min(s, cl);
                int e1 = s + w, e2 = cl + nc - 1 + w;
                WL = (e1 > e2 ? e1 : e2) - base0;
                if (WL > WIN) valid = 0;
            }
            sGeo[0]=w; sGeo[1]=s; sGeo[2]=cl; sGeo[3]=nc; sGeo[4]=valid;
            sGeo[5]=base0; sGeo[6]=WL;
            sM = 0; sEnc = fenc(-INFINITY);
        }
        __syncthreads();
        int w = sGeo[0], s = sGeo[1], cl = sGeo[2], nc = sGeo[3];
        int valid = sGeo[4], base0 = sGeo[5], WL = sGeo[6];
        if (valid) {
            for (int k = tid; k < WL; k += WTW) win[k] = sig[base0 + k];
            __syncthreads();
            if (wrp == 0) {
                const float* rp = win + (s - base0);
                float psq = np_psq4(rp, w, lane4);
                float nb = __shfl_sync(0xFFFFFFFFu, psq, 0);
                nb = fmaxf(__fsqrt_rn(nb), 1e-12f);
                for (int k = wl; k < w; k += 32) s_b[k] = __fdiv_rn(rp[k], nb);
            }
            __syncthreads();
            const float* cb = win + (cl - base0);
            int w4 = w & ~3;
            for (int c0 = 0; c0 < nc; c0 += WTW/4) {
                int c = c0 + grp;
                int cc = c < nc ? c : nc - 1;
                const float* ap = cb + cc;
                float psq = np_psq4(ap, w, lane4);
                float na = 0.f;
                if (lane4 == 0) na = fmaxf(__fsqrt_rn(psq), 1e-12f);
                float acc = 0.f, ma = 0.f;
                for (int k = lane4; k < w4; k += 4) {
                    float v = ap[k];
                    ma = fmaxf(ma, fabsf(v));
                    acc = fmaf(v, s_b[k], acc);
                }
                float a1 = __shfl_down_sync(0xFFFFFFFFu, acc, 1, 4);
                float ssum = __fadd_rn(acc, a1);
                float a2 = __shfl_down_sync(0xFFFFFFFFu, ssum, 2, 4);
                float res = __fadd_rn(ssum, a2);
                float m1 = __shfl_down_sync(0xFFFFFFFFu, ma, 1, 4);
                ma = fmaxf(ma, m1);
                float m2 = __shfl_down_sync(0xFFFFFFFFu, ma, 2, 4);
                ma = fmaxf(ma, m2);
                if (lane4 == 0 && c < nc) {
                    for (int k = w4; k < w; k++) {
                        float v = ap[k];
                        ma = fmaxf(ma, fabsf(v));
                        res = fmaf(v, s_b[k], res);
                    }
                    float qv = __fdiv_rn(res, na);
                    s_q[cc] = qv;
                    s_ma[cc] = ma; s_na[cc] = na;
                    atomicMax(&sEnc, fenc(qv));
                }
            }
            __syncthreads();
            float bv = fdec(sEnc);
            for (int c = tid; c < nc; c += WTW) {
                if (s_q[c] >= bv - CEPS) {
                    int sl = atomicAdd(&sM, 1);
                    s_cl[sl] = c;
                } else {
                    s_q[c] = -INFINITY;
                }
            }
            __syncthreads();
            int m = sM;
            for (int j0 = 0; j0 < m; j0 += WTW/4) {
                if (j0 + (wrp << 3) < m) {
                    int ji = j0 + grp;
                    int jj = ji < m ? ji : m - 1;
                    int c = s_cl[jj];
                    const float* ap = cb + c;
                    float na = s_na[c];
                    float acc = 0.f;
                    for (int k = lane4; k < w4; k += 4)
                        acc = fmaf(__fdiv_rn(ap[k], na), s_b[k], acc);
                    float a1 = __shfl_down_sync(0xFFFFFFFFu, acc, 1, 4);
                    float ssum = __fadd_rn(acc, a1);
                    float a2 = __shfl_down_sync(0xFFFFFFFFu, ssum, 2, 4);
                    float res = __fadd_rn(ssum, a2);
                    if (lane4 == 0 && ji < m) {
                        for (int k = w4; k < w; k++)
                            res = fmaf(__fdiv_rn(ap[k], na), s_b[k], res);
                        s_q[c] = res;
                    }
                }
            }
            __syncthreads();
            {
                float v = (tid < nc) ? s_q[tid] : -INFINITY;
                int idx = tid;
                for (int o = 16; o; o >>= 1) {
                    float vo = __shfl_down_sync(0xFFFFFFFFu, v, o);
                    int   io = __shfl_down_sync(0xFFFFFFFFu, idx, o);
                    if (vo > v || (vo == v && io < idx)) { v = vo; idx = io; }
                }
                if (wl == 0) { s_pv[wrp] = v; s_pi[wrp] = idx; }
            }
            __syncthreads();
        }
        if (tid == 0) {
            double corr = -1.0, peak = 0.0;
            int stop = 0;
            if (valid) {
                float bv2 = s_pv[0]; int br = s_pi[0];
                for (int q = 1; q < WTW/32; q++)
                    if (s_pv[q] > bv2 || (s_pv[q] == bv2 && s_pi[q] < br)) { bv2 = s_pv[q]; br = s_pi[q]; }
                corr = (double)s_q[br];
                peak = (double)s_ma[br];
                i = i + (br + cl) - s;
            }
            bool neg1 = (corr == -1.0);
            if (dir) {
                if (neg1) i += w;
                if (i >= right) {
                    if (corr > 0.7 && peak > __dmul_rn(0.023333, gp)) {
                        if (cnt < CANDW) g_wci[base+cnt] = i;
                        cnt++; lastApp = i;
                    }
                    stop = 1;
                } else if (corr > 0.3 && (peak == 0.0 || peak > __dmul_rn(0.01, gp))) {
                    if (cnt < CANDW) g_wci[base+cnt] = i;
                    cnt++; lastApp = i;
                }
            } else {
                if (neg1) i -= w;
                if (i < left) {
                    if (corr > 0.7 && peak > __dmul_rn(0.023333, gp)) {
                        if (cnt < CANDW) { g_wci[base+cnt] = i; g_wcw[base+cnt] = w; }
                        cnt++;
                    }
                    stop = 1;
                } else if (corr > 0.3 && (peak == 0.0 || peak > __dmul_rn(0.01, gp))) {
                    if (cnt < CANDW) { g_wci[base+cnt] = i; g_wcw[base+cnt] = w; }
                    cnt++;
                }
            }
            sGeo[7] = stop;
        }
        __syncthreads();
        if (sGeo[7]) break;
    }
    if (tid == 0) {
        g_wcnt[b] = min(cnt, CANDW);
        if (dir) g_lastApp[run] = lastApp;
    }
}

__global__ void K_filter() {
    __shared__ long sAR[MAXRUNS];
    int tid = threadIdx.x;
    int nr = g_nruns0;
    if (tid == 0) {
        long cur = LONG_MIN / 4;
        for (int r = 0; r < nr; r++) {
            sAR[r] = cur;
            if (g_lastApp[r] != INT_MIN) cur = (long)g_lastApp[r];
        }
    }
    __syncthreads();
    if (tid < nr) {
        long base = (long)(MAXRUNS + tid) * CANDW;
        int c = g_wcnt[MAXRUNS + tid], m = 0;
        long AR = sAR[tid];
        for (int j = 0; j < c; j++) {
            int i = g_wci[base + j], w = g_wcw[base + j];
            bool pass;
            if (AR <= LONG_MIN / 8) pass = true;
            else pass = 5L * ((long)i - AR) > 4L * (long)w;
            if (pass) { g_wci[base + m] = i; m++; }
        }
        g_wcnt[MAXRUNS + tid] = m;
    }
}

__global__ void K_collect() {
    __shared__ int s_off[NWALK];
    int tid = threadIdx.x;
    if (tid == 0) {
        int acc = 0;
        for (int sl = 0; sl < NWALK; sl++) { s_off[sl] = acc; acc += g_wcnt[sl]; }
        g_ncand = min(acc, MAXPK);
    }
    __syncthreads();
    for (int sl = 0; sl < NWALK; sl++) {
        int c = g_wcnt[sl], o = s_off[sl];
        for (int j = tid; j < c; j += blockDim.x)
            if (o + j < MAXPK) g_cand[o+j] = g_wci[(long)sl*CANDW + j];
    }
}

__global__ void K_rank(int T) {
    int N = g_ncand;
    for (int j = blockIdx.x*blockDim.x + threadIdx.x; j < N; j += gridDim.x*blockDim.x) {
        int v = g_cand[j], rk = 0;
        for (int k = 0; k < N; k++) {
            int u = g_cand[k];
            rk += (u < v) || (u == v && k < j);
        }
        int cv = v; if (cv < 0) cv = 0; if (cv > T-1) cv = T-1;
        g_peaks[rk] = cv;
    }
    if (blockIdx.x == 0 && threadIdx.x == 0) g_npk = N;
}

// single-pass plan (ops order-independent under atomicAdd apply)
__device__ void plan_run3(const int* __restrict__ pk, int npk, int r, int T, float minpos) {
    int left_v = g_runL1[r], right_v = g_runR1[r];
    int prevR = (r == 0) ? 0 : g_runR1[r-1];
    int cnt = 0, base = r * OPR;
    if (prevR < left_v) {
        if (cnt < OPR) {
            g_opd[base+cnt] = prevR; g_opsrc[base+cnt] = prevR;
            g_opl[base+cnt] = left_v - prevR; g_opn[base+cnt] = left_v - prevR;
        }
        cnt++;
    }
    int q = dev_lb(pk, npk, left_v);
    while (left_v < right_v) {
        while (q < npk && pk[q] < left_v) q++;
        int p;
        if (q == 0) p = 0;
        else if (q >= npk) {
            p = npk - 1;
            int v = pk[npk-1];
            while (p > 0 && pk[p-1] == v) p--;
        } else {
            long d1 = (long)left_v - pk[q-1], d2 = (long)pk[q] - left_v;
            if (d1 <= d2) {
                p = q - 1;
                int v = pk[q-1];
                while (p > 0 && pk[p-1] == v) p--;
            } else p = q;
        }
        float fv = g_f0s[left_v];
        float fm = fv > 60.f ? fv : 60.f;
        int period = floor_div_22050(fm);
        int left_w = period/2, right_w = period/2;
        if (p > 0) {
            long d = (long)pk[p] - pk[p-1];
            if (dmul_le_maxw(d, minpos)) left_w = min((int)d, left_w);
        }
        if (p < npk-1) {
            long d = (long)pk[p+1] - pk[p];
            if (dmul_le_maxw(d, minpos)) right_w = min((int)d, right_w);
        }
        int left_i = pk[p] - left_w; if (left_i < 0) left_i = 0;
        int right_i = pk[p] + right_w;
        int ival = (right_i - left_i) / 2;
        if (ival <= 0) break;
        long a = (long)left_v - ival;
        int seglen = min(pyslen(a, (long)left_v + ival, T),
                         pyslen(left_i, (long)left_i + 2L*ival, T));
        int Ld = pyslen(a, a + seglen, T);
        int Ls = pyslen(left_i, (long)left_i + seglen, T);
        int L = min(min(Ld, Ls), seglen);
        if (cnt < OPR) {
            long as_ = a < 0 ? a + T : a;
            g_opd[base+cnt] = (int)as_; g_opsrc[base+cnt] = left_i;
            g_opl[base+cnt] = L; g_opn[base+cnt] = 2*ival;
        }
        cnt++;
        left_v += ival * 2;
    }
    g_opcnt[r] = min(cnt, OPR);
}

__global__ __launch_bounds__(256) void K_plan(int T) {
    __shared__ int s_pk[PCAP];
    __shared__ float s_minpos;
    int tid = threadIdx.x;
    if (tid == 0) {
        g_copy = (!g_anygate || g_npk == 0) ? 1 : 0;
        s_minpos = __uint_as_float(g_minbits);
        g_tail = 0;
    }
    __syncthreads();
    if (g_copy) return;
    int npk = g_npk;
    const int* pk = g_peaks;
    if (npk <= PCAP) {
        for (int i = tid; i < npk; i += 256) s_pk[i] = g_peaks[i];
        pk = s_pk;
    }
    __syncthreads();
    int nr = g_nruns1;
    if (tid == 0 && nr > 0) g_tail = g_runR1[nr-1];
    if (tid < nr) plan_run3(pk, npk, tid, T, s_minpos);
}

__global__ void K_apply(const float* __restrict__ snd, float* __restrict__ out, int T) {
    int nr = g_nruns1;
    if (g_copy) return;
    for (int b = blockIdx.x; b < nr * OPR; b += gridDim.x) {
        int r = b / OPR, j = b % OPR;
        if (j >= g_opcnt[r]) continue;
        int o = r * OPR + j;
        int d0 = g_opd[o], s0 = g_opsrc[o], L = g_opl[o], n = g_opn[o];
        float invn = 6.2831853071795864f / (float)n;
        for (int k = threadIdx.x; k < L; k += blockDim.x) {
            float wf = 0.5f - 0.5f * cosf((float)k * invn);
            atomicAdd(out + d0 + k, wf * snd[s0 + k]);
        }
    }
}

__global__ void K_tail(const float* __restrict__ snd, float* __restrict__ out, int T) {
    int t = blockIdx.x*blockDim.x + threadIdx.x;
    if (t >= T) return;
    if (g_copy || t >= g_tail) out[t] = snd[t];
}

extern "C" void kernel_launch(void* const* d_in, const int* in_sizes, int n_in,
                              void* d_out, int out_size) {
    const float* snd   = (const float*)d_in[0];
    const float* pitch = (const float*)d_in[1];
    const int*   steps = (const int*)d_in[2];
    const float* prng  = (const float*)d_in[3];
    float* out = (float*)d_out;
    int T = in_sizes[0];
    int S = in_sizes[1];

    K_init<<<1,256>>>(S, T);
    K_zero<<<GRID(T,256),256>>>(out, T);
    K_absmax<<<512,256>>>(snd, T);
    K_median<<<1,512>>>(pitch, S, steps);
    K_interpshift<<<GRID(T,256),256>>>(pitch, prng, S, T);
    K_mark<<<GRID(T,256),256>>>(T);
    K_sortruns<<<1,1>>>();
    K_backup<<<MAXRUNS,256>>>(snd, T);
    K_walk<<<NWALK,WTW>>>(snd, T);
    K_filter<<<1,64>>>();
    K_collect<<<1,256>>>();
    K_rank<<<64,256>>>(T);
    K_plan<<<1,256>>>(T);
    K_apply<<<2048,128>>>(snd, out, T);
    K_tail<<<GRID(T,256),256>>>(snd, out, T);
}

// round 16
// speedup vs baseline: 1.5708x; 1.0475x over previous
#include <cuda_runtime.h>
#include <math.h>
#include <limits.h>

#define MAXT 700000
#define MAXRUNS 64
#define NWALK (2*MAXRUNS)
#define CANDW 2048
#define MAXPK 16384
#define PCAP 11776
#define OPR 256
#define MAXC 256
#define MAXW 400
#define MS 4096
#define CACHE 4096
#define WTW 512
#define CEPS 1e-4f
#define GRID(n,b) (((n)+(b)-1)/(b))

__device__ float g_f0[MAXT];
__device__ float g_f0s[MAXT];
__device__ double g_scale;
__device__ unsigned g_absbits;
__device__ int g_anygate;
__device__ unsigned g_minbits;
__device__ float g_median;
__device__ float g_factor32, g_mshift32;

__device__ int g_st0[MAXRUNS], g_en0[MAXRUNS], g_st1[MAXRUNS], g_en1[MAXRUNS];
__device__ int g_cs0, g_ce0, g_cs1, g_ce1;
__device__ int g_runL0[MAXRUNS], g_runR0[MAXRUNS], g_nruns0;
__device__ int g_runL1[MAXRUNS], g_runR1[MAXRUNS], g_nruns1;
__device__ int g_tail, g_copy;
__device__ int g_backup[MAXRUNS];

__device__ int g_wci[NWALK*CANDW];
__device__ int g_wcw[NWALK*CANDW];
__device__ int g_wcnt[NWALK];
__device__ int g_lastApp[MAXRUNS];

__device__ int g_cand[MAXPK];
__device__ int g_ncand, g_npk;
__device__ int g_peaks[MAXPK];

__device__ int g_opd[MAXRUNS*OPR], g_opsrc[MAXRUNS*OPR], g_opl[MAXRUNS*OPR], g_opn[MAXRUNS*OPR];
__device__ int g_opcnt[MAXRUNS];

__device__ __forceinline__ int pyslen(long start, long stop, long n) {
    if (start < 0) start += n; if (start < 0) start = 0; if (start > n) start = n;
    if (stop  < 0) stop  += n; if (stop  < 0) stop  = 0; if (stop  > n) stop  = n;
    long L = stop - start; return L > 0 ? (int)L : 0;
}
__device__ __forceinline__ int dev_lb(const int* a, int n, int v) {
    int lo = 0, hi = n;
    while (lo < hi) { int m = (lo+hi)>>1; if (a[m] < v) lo = m+1; else hi = m; }
    return lo;
}
__device__ __forceinline__ unsigned fenc(float f) {
    unsigned b = __float_as_uint(f);
    return (b & 0x80000000u) ? ~b : (b | 0x80000000u);
}
__device__ __forceinline__ float fdec(unsigned u) {
    return (u & 0x80000000u) ? __uint_as_float(u & 0x7FFFFFFFu) : __uint_as_float(~u);
}

__device__ __forceinline__ bool pmul_le(int p, float f) {
    float pf = (float)p;
    float hi = __fmul_rn(pf, f);
    float lo = __fmaf_rn(pf, f, -hi);
    return (hi < 22050.f) || (hi == 22050.f && lo <= 0.f);
}
__device__ __forceinline__ int floor_div_22050(float fm) {
    int p = (int)(22050.f / fm);
    while (p > 0 && !pmul_le(p, fm)) p--;
    while (pmul_le(p + 1, fm)) p++;
    return p;
}
__device__ __forceinline__ bool dmul_le_maxw(long d, float mp) {
    float df = (float)d;
    float hi = __fmul_rn(df, mp);
    float lo = __fmaf_rn(df, mp, -hi);
    return (hi < 27562.5f) || (hi == 27562.5f && lo <= 0.f);
}

// bit-exact interp (matches reference _interp_linear elementwise)
__device__ __forceinline__ float interpv(const float* __restrict__ p, int S, int t) {
    double x = __dadd_rn(__dmul_rn(__dadd_rn((double)t, 0.5), g_scale), -0.5);
    if (x < 0.0) x = 0.0;
    double hi = (double)(S - 1);
    if (x > hi) x = hi;
    long i0 = (long)floor(x);
    long i1 = i0 + 1; if (i1 > (long)(S-1)) i1 = S - 1;
    float f = (float)__dsub_rn(x, (double)i0);
    return __fadd_rn(__fmul_rn(p[i0], __fsub_rn(1.0f, f)), __fmul_rn(p[i1], f));
}
__device__ __forceinline__ float shiftv(float f0v, float pr) {
    float fs = __fmul_rn(f0v, g_factor32);
    float m = g_mshift32;
    if (fs > 0.f) return __fadd_rn(m, __fmul_rn(__fsub_rn(fs, m), pr));
    return 0.f;
}

// numpy FLOAT_pairwise_sum of squares, 4-lane cooperative, bit-exact.
__device__ float np_psq4(const float* a, int n, int lane) {
    if (n < 8) {
        float r = 0.f;
        for (int i = 0; i < n; i++) r = __fadd_rn(r, __fmul_rn(a[i], a[i]));
        return r;
    }
    if (n <= 128) {
        int nb = n - (n % 8);
        int c0 = 2*lane, c1 = 2*lane + 1;
        float ra = __fmul_rn(a[c0], a[c0]);
        float rb = __fmul_rn(a[c1], a[c1]);
        for (int i = 8; i < nb; i += 8) {
            ra = __fadd_rn(ra, __fmul_rn(a[i+c0], a[i+c0]));
            rb = __fadd_rn(rb, __fmul_rn(a[i+c1], a[i+c1]));
        }
        float u = __fadd_rn(ra, rb);
        float u1 = __shfl_down_sync(0xFFFFFFFFu, u, 1, 4);
        float t  = __fadd_rn(u, u1);
        float t2 = __shfl_down_sync(0xFFFFFFFFu, t, 2, 4);
        float res = __fadd_rn(t, t2);
        for (int i = nb; i < n; i++) res = __fadd_rn(res, __fmul_rn(a[i], a[i]));
        return res;
    }
    int n2 = n / 2; n2 -= n2 % 8;
    float L = np_psq4(a, n2, lane);
    float R = np_psq4(a + n2, n - n2, lane);
    return __fadd_rn(L, R);
}

__global__ void K_init(int S, int T) {
    int t = threadIdx.x;
    if (t == 0) {
        g_absbits = 0u; g_anygate = 0; g_minbits = 0xFFFFFFFFu; g_median = 0.f;
        g_cs0 = g_ce0 = g_cs1 = g_ce1 = 0; g_nruns0 = g_nruns1 = 0;
        g_tail = 0; g_copy = 0; g_ncand = 0; g_npk = 0;
        g_scale = __ddiv_rn((double)S, (double)T);
    }
    for (int i = t; i < NWALK; i += blockDim.x) g_wcnt[i] = 0;
    for (int i = t; i < MAXRUNS; i += blockDim.x) { g_lastApp[i] = INT_MIN; g_opcnt[i] = 0; }
}

__global__ void K_absmax(const float* __restrict__ x, int T) {
    float m = 0.f;
    for (int i = blockIdx.x*blockDim.x + threadIdx.x; i < T; i += gridDim.x*blockDim.x)
        m = fmaxf(m, fabsf(x[i]));
    for (int o = 16; o; o >>= 1) m = fmaxf(m, __shfl_down_sync(0xFFFFFFFFu, m, o));
    if ((threadIdx.x & 31) == 0) atomicMax(&g_absbits, __float_as_uint(m));
}

__global__ void K_median(const float* __restrict__ p, int S, const int* __restrict__ stepsPtr) {
    __shared__ float buf[MS];
    __shared__ int sh_np, sh_any;
    int tid = threadIdx.x;
    if (tid == 0) { sh_np = 0; sh_any = 0; }
    __syncthreads();
    int cany = 0;
    for (int j = tid; j < S && j < MS; j += 1024) {
        float v = p[j];
        if (v > 0.f) { int idx = atomicAdd(&sh_np, 1); buf[idx] = v; }
        if (v > 1e-5f) cany = 1;
    }
    if (cany) atomicOr(&sh_any, 1);
    __syncthreads();
    int npos = sh_np;
    for (int i = npos + tid; i < MS; i += 1024) buf[i] = INFINITY;
    __syncthreads();
    for (int k = 2; k <= MS; k <<= 1) {
        for (int j = k >> 1; j > 0; j >>= 1) {
            for (int i = tid; i < MS; i += 1024) {
                int ixj = i ^ j;
                if (ixj > i) {
                    float a = buf[i], b = buf[ixj];
                    bool up = ((i & k) == 0);
                    if ((a > b) == up) { buf[i] = b; buf[ixj] = a; }
                }
            }
            __syncthreads();
        }
    }
    if (tid == 0) {
        g_anygate = sh_any;
        double fac = pow(2.0, (double)stepsPtr[0] / 12.0);
        g_factor32 = (float)fac;
        if (npos > 0) g_median = buf[(npos - 1) >> 1];
        g_mshift32 = (float)((double)g_median * fac);
    }
}

// fused: out-zero + interp + shift + minbits + mark (neighbors recomputed bit-exact)
__global__ void K_pre(const float* __restrict__ p, const float* __restrict__ prp,
                      float* __restrict__ out, int S, int T) {
    int t = blockIdx.x*blockDim.x + threadIdx.x;
    float res = 0.f;
    if (t < T) {
        out[t] = 0.f;
        float pr = prp[0];
        float f0c = interpv(p, S, t);
        g_f0[t] = f0c;
        float fsc = shiftv(f0c, pr);
        g_f0s[t] = fsc;
        res = fsc;
        float f0m = (t > 0)     ? interpv(p, S, t-1) : 0.f;
        float f0p = (t < T-1)   ? interpv(p, S, t+1) : 0.f;
        if (f0c > 0.f) {
            bool prb = (t > 0) && (f0m > 0.f);
            bool nxb = (t < T-1) && (f0p > 0.f);
            if (!prb) { int i = atomicAdd(&g_cs0,1); if (i < MAXRUNS) g_st0[i] = t; }
            if (!nxb) { int i = atomicAdd(&g_ce0,1); if (i < MAXRUNS) g_en0[i] = t+1; }
        }
        if (fsc > 0.f) {
            float fsm = (t > 0)   ? shiftv(f0m, pr) : 0.f;
            float fsp = (t < T-1) ? shiftv(f0p, pr) : 0.f;
            bool prb = (t > 0) && (fsm > 0.f);
            bool nxb = (t < T-1) && (fsp > 0.f);
            if (!prb) { int i = atomicAdd(&g_cs1,1); if (i < MAXRUNS) g_st1[i] = t; }
            if (!nxb) { int i = atomicAdd(&g_ce1,1); if (i < MAXRUNS) g_en1[i] = t+1; }
        }
    }
    unsigned mb = (t < T && res > 0.f) ? __float_as_uint(res) : 0xFFFFFFFFu;
    for (int o = 16; o; o >>= 1) mb = min(mb, __shfl_down_sync(0xFFFFFFFFu, mb, o));
    if ((threadIdx.x & 31) == 0 && mb != 0xFFFFFFFFu) atomicMin(&g_minbits, mb);
}

__device__ void sort_small(int* a, int n) {
    for (int i = 1; i < n; i++) {
        int v = a[i], j = i-1;
        while (j >= 0 && a[j] > v) { a[j+1] = a[j]; j--; }
        a[j+1] = v;
    }
}

__global__ void K_sortruns() {
    if (threadIdx.x || blockIdx.x) return;
    {
        int ns = min(g_cs0, MAXRUNS), ne = min(g_ce0, MAXRUNS);
        sort_small(g_st0, ns); sort_small(g_en0, ne);
        int n = min(ns, ne), off = 0;
        if (n > 0 && g_st0[0] == 0) { g_st0[0] = 1; if (g_st0[0] >= g_en0[0]) off = 1; }
        int m = 0;
        for (int k = off; k < n; k++) { g_runL0[m] = g_st0[k]; g_runR0[m] = g_en0[k]; m++; }
        g_nruns0 = m;
    }
    {
        int ns = min(g_cs1, MAXRUNS), ne = min(g_ce1, MAXRUNS);
        sort_small(g_st1, ns); sort_small(g_en1, ne);
        int n = min(ns, ne), off = 0;
        if (n > 0 && g_st1[0] == 0) { g_st1[0] = 1; if (g_st1[0] >= g_en1[0]) off = 1; }
        int m = 0;
        for (int k = off; k < n; k++) { g_runL1[m] = g_st1[k]; g_runR1[m] = g_en1[k]; m++; }
        g_nruns1 = m;
    }
}

__global__ void K_backup(const float* __restrict__ sig, int T) {
    __shared__ float s_rv[2][8];
    __shared__ long  s_ri[2][8];
    int run = blockIdx.x;
    if (run >= g_nruns0) return;
    int tid = threadIdx.x, lane = tid & 31, wrp = tid >> 5;
    int left = g_runL0[run], right = g_runR0[run];
    int middle = (left + right) / 2;
    double wd = __ddiv_rn(22050.0, (double)g_f0[middle]);
    long w = (wd > 2.0e9) ? 2000000000L : (long)wd;
    long s = (long)middle - w/2; if (s < 0) s = 0;
    long len = w; if (s + len > T) len = T - s;
    float mn = INFINITY, mx = -INFINITY; long imn = LONG_MAX, imx = LONG_MAX;
    for (long k = tid; k < len; k += 256) {
        float v = sig[s+k];
        if (v < mn || (v == mn && k < imn)) { mn = v; imn = k; }
        if (v > mx || (v == mx && k < imx)) { mx = v; imx = k; }
    }
    for (int o = 16; o; o >>= 1) {
        float ov = __shfl_down_sync(0xFFFFFFFFu, mn, o);
        long  oi = __shfl_down_sync(0xFFFFFFFFu, imn, o);
        if (ov < mn || (ov == mn && oi < imn)) { mn = ov; imn = oi; }
        float ov2 = __shfl_down_sync(0xFFFFFFFFu, mx, o);
        long  oi2 = __shfl_down_sync(0xFFFFFFFFu, imx, o);
        if (ov2 > mx || (ov2 == mx && oi2 < imx)) { mx = ov2; imx = oi2; }
    }
    if (lane == 0) { s_rv[0][wrp] = mn; s_ri[0][wrp] = imn; s_rv[1][wrp] = mx; s_ri[1][wrp] = imx; }
    __syncthreads();
    if (tid == 0) {
        float bmn = INFINITY, bmx = -INFINITY; long bmni = LONG_MAX, bmxi = LONG_MAX;
        for (int q = 0; q < 8; q++) {
            float v = s_rv[0][q]; long i2 = s_ri[0][q];
            if (v < bmn || (v == bmn && i2 < bmni)) { bmn = v; bmni = i2; }
            float v2 = s_rv[1][q]; long i3 = s_ri[1][q];
            if (v2 > bmx || (v2 == bmx && i3 < bmxi)) { bmx = v2; bmxi = i3; }
        }
        g_backup[run] = (bmn == bmx) ? middle
                      : (int)(s + ((fabs((double)bmn) > fabs((double)bmx)) ? bmni : bmxi));
    }
}

// Merged walk; multi-step smem window cache; per-warp max pre-reduce.
__global__ __launch_bounds__(WTW) void K_walk(const float* __restrict__ sig, int T) {
    __shared__ float win[CACHE];
    __shared__ float s_b[MAXW];
    __shared__ float s_q[MAXC], s_ma[MAXC], s_na[MAXC];
    __shared__ int   s_cl[MAXC];
    __shared__ int   sM;
    __shared__ unsigned sEnc;
    __shared__ float s_pv[WTW/32];
    __shared__ int   s_pi[WTW/32];
    __shared__ int sGeo[12];  // 0:w 1:s 2:cl 3:nc 4:valid 5:base0 6:WL 7:stop 8:need 9:cb 10:clen
    int b = blockIdx.x;
    int dir = (b < MAXRUNS) ? 1 : 0;
    int run = dir ? b : (b - MAXRUNS);
    if (run >= g_nruns0) return;
    int tid = threadIdx.x, lane4 = tid & 3, grp = tid >> 2, wrp = tid >> 5, wl = tid & 31;
    int left = g_runL0[run], right = g_runR0[run];
    double gp = (double)__uint_as_float(g_absbits);
    long base = (long)b * CANDW;
    int cnt = 0, lastApp = INT_MIN;
    int i = 0;
    int cacheB = -1, cacheL = 0;   // thread0's authoritative cache state
    if (tid == 0) i = g_backup[run];
    while (true) {
        if (tid == 0) {
            double f0i = (double)g_f0[i];
            double fm = f0i > 60.0 ? f0i : 60.0;
            int w = (int)__ddiv_rn(22050.0, fm);
            int s = i - w/2; if (s < 0) s = 0;
            int cl, cr;
            if (dir) {
                cl = (int)__dadd_rn((double)i, __dmul_rn(0.3,  (double)w));
                cr = (int)__dadd_rn((double)i, __dmul_rn(0.75, (double)w));
            } else {
                int a1 = (int)__dsub_rn((double)i, __dmul_rn(1.75, (double)w)); cl = a1 > 0 ? a1 : 0;
                int a2 = (int)__dsub_rn((double)i, __dmul_rn(1.3,  (double)w)); cr = a2 > 0 ? a2 : 0;
            }
            int valid = 0, nc = 0, base0 = 0, WL = 0, need = 0;
            if (!(cl == cr || (T - cl) < w)) {
                long hi = (long)cr + w; if (hi > T) hi = T;
                nc = (int)(hi - cl - w + 1);
                valid = (nc >= 1 && nc <= MAXC && w <= MAXW && s + w <= T);
            }
            if (valid) {
                base0 = min(s, cl);
                int e1 = s + w, e2 = cl + nc - 1 + w;
                WL = (e1 > e2 ? e1 : e2) - base0;
                if (WL > CACHE) valid = 0;
                else {
                    need = !(cacheB >= 0 && base0 >= cacheB && base0 + WL <= cacheB + cacheL);
                    if (need) {
                        int nb2;
                        if (dir) nb2 = base0;
                        else { long q0 = (long)base0 + WL - CACHE; nb2 = q0 > 0 ? (int)q0 : 0; }
                        int nl = T - nb2; if (nl > CACHE) nl = CACHE;
                        cacheB = nb2; cacheL = nl;
                    }
                }
            }
            sGeo[0]=w; sGeo[1]=s; sGeo[2]=cl; sGeo[3]=nc; sGeo[4]=valid;
            sGeo[5]=base0; sGeo[6]=WL; sGeo[8]=need; sGeo[9]=cacheB; sGeo[10]=cacheL;
            sM = 0; sEnc = fenc(-INFINITY);
        }
        __syncthreads();
        int w = sGeo[0], s = sGeo[1], cl = sGeo[2], nc = sGeo[3];
        int valid = sGeo[4];
        int cb0 = sGeo[9], clen = sGeo[10];
        if (valid) {
            if (sGeo[8]) {
                for (int k = tid; k < clen; k += WTW) win[k] = sig[cb0 + k];
                __syncthreads();
            }
            if (wrp == 0) {
                const float* rp = win + (s - cb0);
                float psq = np_psq4(rp, w, lane4);
                float nb = __shfl_sync(0xFFFFFFFFu, psq, 0);
                nb = fmaxf(__fsqrt_rn(nb), 1e-12f);
                for (int k = wl; k < w; k += 32) s_b[k] = __fdiv_rn(rp[k], nb);
            }
            __syncthreads();
            const float* cbp = win + (cl - cb0);
            int w4 = w & ~3;
            for (int c0 = 0; c0 < nc; c0 += WTW/4) {
                int c = c0 + grp;
                int cc = c < nc ? c : nc - 1;
                const float* ap = cbp + cc;
                float psq = np_psq4(ap, w, lane4);
                float na = 0.f;
                if (lane4 == 0) na = fmaxf(__fsqrt_rn(psq), 1e-12f);
                float acc = 0.f, ma = 0.f;
                for (int k = lane4; k < w4; k += 4) {
                    float v = ap[k];
                    ma = fmaxf(ma, fabsf(v));
                    acc = fmaf(v, s_b[k], acc);
                }
                float a1 = __shfl_down_sync(0xFFFFFFFFu, acc, 1, 4);
                float ssum = __fadd_rn(acc, a1);
                float a2 = __shfl_down_sync(0xFFFFFFFFu, ssum, 2, 4);
                float res = __fadd_rn(ssum, a2);
                float m1 = __shfl_down_sync(0xFFFFFFFFu, ma, 1, 4);
                ma = fmaxf(ma, m1);
                float m2 = __shfl_down_sync(0xFFFFFFFFu, ma, 2, 4);
                ma = fmaxf(ma, m2);
                float contrib = -INFINITY;
                if (lane4 == 0 && c < nc) {
                    for (int k = w4; k < w; k++) {
                        float v = ap[k];
                        ma = fmaxf(ma, fabsf(v));
                        res = fmaf(v, s_b[k], res);
                    }
                    float qv = __fdiv_rn(res, na);
                    s_q[cc] = qv;
                    s_ma[cc] = ma; s_na[cc] = na;
                    contrib = qv;
                }
                // per-warp max, single atomic per warp
                for (int o = 16; o; o >>= 1)
                    contrib = fmaxf(contrib, __shfl_down_sync(0xFFFFFFFFu, contrib, o));
                if (wl == 0) atomicMax(&sEnc, fenc(contrib));
            }
            __syncthreads();
            float bv = fdec(sEnc);
            for (int c = tid; c < nc; c += WTW) {
                if (s_q[c] >= bv - CEPS) {
                    int sl = atomicAdd(&sM, 1);
                    s_cl[sl] = c;
                } else {
                    s_q[c] = -INFINITY;
                }
            }
            __syncthreads();
            int m = sM;
            for (int j0 = 0; j0 < m; j0 += WTW/4) {
                if (j0 + (wrp << 3) < m) {
                    int ji = j0 + grp;
                    int jj = ji < m ? ji : m - 1;
                    int c = s_cl[jj];
                    const float* ap = cbp + c;
                    float na = s_na[c];
                    float acc = 0.f;
                    for (int k = lane4; k < w4; k += 4)
                        acc = fmaf(__fdiv_rn(ap[k], na), s_b[k], acc);
                    float a1 = __shfl_down_sync(0xFFFFFFFFu, acc, 1, 4);
                    float ssum = __fadd_rn(acc, a1);
                    float a2 = __shfl_down_sync(0xFFFFFFFFu, ssum, 2, 4);
                    float res = __fadd_rn(ssum, a2);
                    if (lane4 == 0 && ji < m) {
                        for (int k = w4; k < w; k++)
                            res = fmaf(__fdiv_rn(ap[k], na), s_b[k], res);
                        s_q[c] = res;
                    }
                }
            }
            __syncthreads();
            {
                float v = (tid < nc) ? s_q[tid] : -INFINITY;
                int idx = tid;
                for (int o = 16; o; o >>= 1) {
                    float vo = __shfl_down_sync(0xFFFFFFFFu, v, o);
                    int   io = __shfl_down_sync(0xFFFFFFFFu, idx, o);
                    if (vo > v || (vo == v && io < idx)) { v = vo; idx = io; }
                }
                if (wl == 0) { s_pv[wrp] = v; s_pi[wrp] = idx; }
            }
            __syncthreads();
        }
        if (tid == 0) {
            double corr = -1.0, peak = 0.0;
            int stop = 0;
            if (valid) {
                float bv2 = s_pv[0]; int br = s_pi[0];
                for (int q = 1; q < WTW/32; q++)
                    if (s_pv[q] > bv2 || (s_pv[q] == bv2 && s_pi[q] < br)) { bv2 = s_pv[q]; br = s_pi[q]; }
                corr = (double)s_q[br];
                peak = (double)s_ma[br];
                i = i + (br + cl) - s;
            }
            bool neg1 = (corr == -1.0);
            if (dir) {
                if (neg1) i += w;
                if (i >= right) {
                    if (corr > 0.7 && peak > __dmul_rn(0.023333, gp)) {
                        if (cnt < CANDW) g_wci[base+cnt] = i;
                        cnt++; lastApp = i;
                    }
                    stop = 1;
                } else if (corr > 0.3 && (peak == 0.0 || peak > __dmul_rn(0.01, gp))) {
                    if (cnt < CANDW) g_wci[base+cnt] = i;
                    cnt++; lastApp = i;
                }
            } else {
                if (neg1) i -= w;
                if (i < left) {
                    if (corr > 0.7 && peak > __dmul_rn(0.023333, gp)) {
                        if (cnt < CANDW) { g_wci[base+cnt] = i; g_wcw[base+cnt] = w; }
                        cnt++;
                    }
                    stop = 1;
                } else if (corr > 0.3 && (peak == 0.0 || peak > __dmul_rn(0.01, gp))) {
                    if (cnt < CANDW) { g_wci[base+cnt] = i; g_wcw[base+cnt] = w; }
                    cnt++;
                }
            }
            sGeo[7] = stop;
        }
        __syncthreads();
        if (sGeo[7]) break;
    }
    if (tid == 0) {
        g_wcnt[b] = min(cnt, CANDW);
        if (dir) g_lastApp[run] = lastApp;
    }
}

// merged filter + collect (single block)
__global__ void K_filtcollect() {
    __shared__ long sAR[MAXRUNS];
    __shared__ int s_off[NWALK];
    int tid = threadIdx.x;
    int nr = g_nruns0;
    if (tid == 0) {
        long cur = LONG_MIN / 4;
        for (int r = 0; r < nr; r++) {
            sAR[r] = cur;
            if (g_lastApp[r] != INT_MIN) cur = (long)g_lastApp[r];
        }
    }
    __syncthreads();
    if (tid < nr) {
        long base = (long)(MAXRUNS + tid) * CANDW;
        int c = g_wcnt[MAXRUNS + tid], m = 0;
        long AR = sAR[tid];
        for (int j = 0; j < c; j++) {
            int i = g_wci[base + j], w = g_wcw[base + j];
            bool pass;
            if (AR <= LONG_MIN / 8) pass = true;
            else pass = 5L * ((long)i - AR) > 4L * (long)w;
            if (pass) { g_wci[base + m] = i; m++; }
        }
        g_wcnt[MAXRUNS + tid] = m;
    }
    __syncthreads();
    if (tid == 0) {
        int acc = 0;
        for (int sl = 0; sl < NWALK; sl++) { s_off[sl] = acc; acc += g_wcnt[sl]; }
        g_ncand = min(acc, MAXPK);
    }
    __syncthreads();
    for (int sl = 0; sl < NWALK; sl++) {
        int c = g_wcnt[sl], o = s_off[sl];
        for (int j = tid; j < c; j += blockDim.x)
            if (o + j < MAXPK) g_cand[o+j] = g_wci[(long)sl*CANDW + j];
    }
}

__global__ void K_rank(int T) {
    int N = g_ncand;
    for (int j = blockIdx.x*blockDim.x + threadIdx.x; j < N; j += gridDim.x*blockDim.x) {
        int v = g_cand[j], rk = 0;
        for (int k = 0; k < N; k++) {
            int u = g_cand[k];
            rk += (u < v) || (u == v && k < j);
        }
        int cv = v; if (cv < 0) cv = 0; if (cv > T-1) cv = T-1;
        g_peaks[rk] = cv;
    }
    if (blockIdx.x == 0 && threadIdx.x == 0) g_npk = N;
}

__device__ void plan_run3(const int* __restrict__ pk, int npk, int r, int T, float minpos) {
    int left_v = g_runL1[r], right_v = g_runR1[r];
    int prevR = (r == 0) ? 0 : g_runR1[r-1];
    int cnt = 0, base = r * OPR;
    if (prevR < left_v) {
        if (cnt < OPR) {
            g_opd[base+cnt] = prevR; g_opsrc[base+cnt] = prevR;
            g_opl[base+cnt] = left_v - prevR; g_opn[base+cnt] = left_v - prevR;
        }
        cnt++;
    }
    int q = dev_lb(pk, npk, left_v);
    while (left_v < right_v) {
        while (q < npk && pk[q] < left_v) q++;
        int p;
        if (q == 0) p = 0;
        else if (q >= npk) {
            p = npk - 1;
            int v = pk[npk-1];
            while (p > 0 && pk[p-1] == v) p--;
        } else {
            long d1 = (long)left_v - pk[q-1], d2 = (long)pk[q] - left_v;
            if (d1 <= d2) {
                p = q - 1;
                int v = pk[q-1];
                while (p > 0 && pk[p-1] == v) p--;
            } else p = q;
        }
        float fv = g_f0s[left_v];
        float fm = fv > 60.f ? fv : 60.f;
        int period = floor_div_22050(fm);
        int left_w = period/2, right_w = period/2;
        if (p > 0) {
            long d = (long)pk[p] - pk[p-1];
            if (dmul_le_maxw(d, minpos)) left_w = min((int)d, left_w);
        }
        if (p < npk-1) {
            long d = (long)pk[p+1] - pk[p];
            if (dmul_le_maxw(d, minpos)) right_w = min((int)d, right_w);
        }
        int left_i = pk[p] - left_w; if (left_i < 0) left_i = 0;
        int right_i = pk[p] + right_w;
        int ival = (right_i - left_i) / 2;
        if (ival <= 0) break;
        long a = (long)left_v - ival;
        int seglen = min(pyslen(a, (long)left_v + ival, T),
                         pyslen(left_i, (long)left_i + 2L*ival, T));
        int Ld = pyslen(a, a + seglen, T);
        int Ls = pyslen(left_i, (long)left_i + seglen, T);
        int L = min(min(Ld, Ls), seglen);
        if (cnt < OPR) {
            long as_ = a < 0 ? a + T : a;
            g_opd[base+cnt] = (int)as_; g_opsrc[base+cnt] = left_i;
            g_opl[base+cnt] = L; g_opn[base+cnt] = 2*ival;
        }
        cnt++;
        left_v += ival * 2;
    }
    g_opcnt[r] = min(cnt, OPR);
}

__global__ __launch_bounds__(256) void K_plan(int T) {
    __shared__ int s_pk[PCAP];
    __shared__ float s_minpos;
    int tid = threadIdx.x;
    if (tid == 0) {
        g_copy = (!g_anygate || g_npk == 0) ? 1 : 0;
        s_minpos = __uint_as_float(g_minbits);
        g_tail = 0;
    }
    __syncthreads();
    if (g_copy) return;
    int npk = g_npk;
    const int* pk = g_peaks;
    if (npk <= PCAP) {
        for (int i = tid; i < npk; i += 256) s_pk[i] = g_peaks[i];
        pk = s_pk;
    }
    __syncthreads();
    int nr = g_nruns1;
    if (tid == 0 && nr > 0) g_tail = g_runR1[nr-1];
    if (tid < nr) plan_run3(pk, npk, tid, T, s_minpos);
}

__global__ void K_apply(const float* __restrict__ snd, float* __restrict__ out, int T) {
    int nr = g_nruns1;
    if (g_copy) return;
    for (int b = blockIdx.x; b < nr * OPR; b += gridDim.x) {
        int r = b / OPR, j = b % OPR;
        if (j >= g_opcnt[r]) continue;
        int o = r * OPR + j;
        int d0 = g_opd[o], s0 = g_opsrc[o], L = g_opl[o], n = g_opn[o];
        float invn = 6.2831853071795864f / (float)n;
        for (int k = threadIdx.x; k < L; k += blockDim.x) {
            float wf = 0.5f - 0.5f * cosf((float)k * invn);
            atomicAdd(out + d0 + k, wf * snd[s0 + k]);
        }
    }
}

__global__ void K_tail(const float* __restrict__ snd, float* __restrict__ out, int T) {
    int t = blockIdx.x*blockDim.x + threadIdx.x;
    if (t >= T) return;
    if (g_copy || t >= g_tail) out[t] = snd[t];
}

extern "C" void kernel_launch(void* const* d_in, const int* in_sizes, int n_in,
                              void* d_out, int out_size) {
    const float* snd   = (const float*)d_in[0];
    const float* pitch = (const float*)d_in[1];
    const int*   steps = (const int*)d_in[2];
    const float* prng  = (const float*)d_in[3];
    float* out = (float*)d_out;
    int T = in_sizes[0];
    int S = in_sizes[1];

    K_init<<<1,256>>>(S, T);
    K_absmax<<<512,256>>>(snd, T);
    K_median<<<1,1024>>>(pitch, S, steps);
    K_pre<<<GRID(T,256),256>>>(pitch, prng, out, S, T);
    K_sortruns<<<1,1>>>();
    K_backup<<<MAXRUNS,256>>>(snd, T);
    K_walk<<<NWALK,WTW>>>(snd, T);
    K_filtcollect<<<1,256>>>();
    K_rank<<<64,256>>>(T);
    K_plan<<<1,256>>>(T);
    K_apply<<<2048,128>>>(snd, out, T);
    K_tail<<<GRID(T,256),256>>>(snd, out, T);
}

// round 17
// speedup vs baseline: 1.7028x; 1.0840x over previous
#include <cuda_runtime.h>
#include <math.h>
#include <limits.h>

#define MAXT 700000
#define MAXRUNS 64
#define NWALK (2*MAXRUNS)
#define WGRID 192
#define CANDW 2048
#define MAXPK 16384
#define PCAP 11776
#define OPR 256
#define MAXC 256
#define MAXW 400
#define CACHE 4096
#define WTW 512
#define CEPS 1e-4f
#define GRID(n,b) (((n)+(b)-1)/(b))

__device__ float g_f0[MAXT];
__device__ float g_f0s[MAXT];
__device__ double g_scale;
__device__ unsigned g_absbits;
__device__ int g_anygate;
__device__ unsigned g_minbits;
__device__ float g_median;
__device__ float g_factor32, g_mshift32;

__device__ int g_st0[MAXRUNS], g_en0[MAXRUNS], g_st1[MAXRUNS], g_en1[MAXRUNS];
__device__ int g_cs0, g_ce0, g_cs1, g_ce1;
__device__ int g_runL0[MAXRUNS], g_runR0[MAXRUNS], g_nruns0;
__device__ int g_runL1[MAXRUNS], g_runR1[MAXRUNS], g_nruns1;
__device__ int g_tail, g_copy;
__device__ int g_backup[MAXRUNS];

__device__ int g_wci[NWALK*CANDW];
__device__ int g_wcw[NWALK*CANDW];
__device__ int g_wcnt[NWALK];
__device__ int g_lastApp[MAXRUNS];

__device__ int g_cand[MAXPK];
__device__ int g_ncand, g_npk;
__device__ int g_peaks[MAXPK];

__device__ int g_opd[MAXRUNS*OPR], g_opsrc[MAXRUNS*OPR], g_opl[MAXRUNS*OPR], g_opn[MAXRUNS*OPR];
__device__ int g_opcnt[MAXRUNS];

__device__ __forceinline__ int pyslen(long start, long stop, long n) {
    if (start < 0) start += n; if (start < 0) start = 0; if (start > n) start = n;
    if (stop  < 0) stop  += n; if (stop  < 0) stop  = 0; if (stop  > n) stop  = n;
    long L = stop - start; return L > 0 ? (int)L : 0;
}
__device__ __forceinline__ int dev_lb(const int* a, int n, int v) {
    int lo = 0, hi = n;
    while (lo < hi) { int m = (lo+hi)>>1; if (a[m] < v) lo = m+1; else hi = m; }
    return lo;
}
__device__ __forceinline__ unsigned fenc(float f) {
    unsigned b = __float_as_uint(f);
    return (b & 0x80000000u) ? ~b : (b | 0x80000000u);
}
__device__ __forceinline__ float fdec(unsigned u) {
    return (u & 0x80000000u) ? __uint_as_float(u & 0x7FFFFFFFu) : __uint_as_float(~u);
}

__device__ __forceinline__ bool pmul_le(int p, float f) {
    float pf = (float)p;
    float hi = __fmul_rn(pf, f);
    float lo = __fmaf_rn(pf, f, -hi);
    return (hi < 22050.f) || (hi == 22050.f && lo <= 0.f);
}
__device__ __forceinline__ int floor_div_22050(float fm) {
    int p = (int)(22050.f / fm);
    while (p > 0 && !pmul_le(p, fm)) p--;
    while (pmul_le(p + 1, fm)) p++;
    return p;
}
__device__ __forceinline__ bool dmul_le_maxw(long d, float mp) {
    float df = (float)d;
    float hi = __fmul_rn(df, mp);
    float lo = __fmaf_rn(df, mp, -hi);
    return (hi < 27562.5f) || (hi == 27562.5f && lo <= 0.f);
}

__device__ __forceinline__ float interpv(const float* __restrict__ p, int S, int t) {
    double x = __dadd_rn(__dmul_rn(__dadd_rn((double)t, 0.5), g_scale), -0.5);
    if (x < 0.0) x = 0.0;
    double hi = (double)(S - 1);
    if (x > hi) x = hi;
    long i0 = (long)floor(x);
    long i1 = i0 + 1; if (i1 > (long)(S-1)) i1 = S - 1;
    float f = (float)__dsub_rn(x, (double)i0);
    return __fadd_rn(__fmul_rn(p[i0], __fsub_rn(1.0f, f)), __fmul_rn(p[i1], f));
}
__device__ __forceinline__ float shiftv(float f0v, float pr) {
    float fs = __fmul_rn(f0v, g_factor32);
    float m = g_mshift32;
    if (fs > 0.f) return __fadd_rn(m, __fmul_rn(__fsub_rn(fs, m), pr));
    return 0.f;
}

// numpy pairwise sum of squares, 4-lane cooperative, bit-exact. noinline to shrink K_walk body (I$).
__device__ __noinline__ float np_psq4(const float* a, int n, int lane) {
    if (n < 8) {
        float r = 0.f;
        for (int i = 0; i < n; i++) r = __fadd_rn(r, __fmul_rn(a[i], a[i]));
        return r;
    }
    if (n <= 128) {
        int nb = n - (n % 8);
        int c0 = 2*lane, c1 = 2*lane + 1;
        float ra = __fmul_rn(a[c0], a[c0]);
        float rb = __fmul_rn(a[c1], a[c1]);
        for (int i = 8; i < nb; i += 8) {
            ra = __fadd_rn(ra, __fmul_rn(a[i+c0], a[i+c0]));
            rb = __fadd_rn(rb, __fmul_rn(a[i+c1], a[i+c1]));
        }
        float u = __fadd_rn(ra, rb);
        float u1 = __shfl_down_sync(0xFFFFFFFFu, u, 1, 4);
        float t  = __fadd_rn(u, u1);
        float t2 = __shfl_down_sync(0xFFFFFFFFu, t, 2, 4);
        float res = __fadd_rn(t, t2);
        for (int i = nb; i < n; i++) res = __fadd_rn(res, __fmul_rn(a[i], a[i]));
        return res;
    }
    int n2 = n / 2; n2 -= n2 % 8;
    float L = np_psq4(a, n2, lane);
    float R = np_psq4(a + n2, n - n2, lane);
    return __fadd_rn(L, R);
}

__global__ void K_init(int S, int T) {
    int t = threadIdx.x;
    if (t == 0) {
        g_absbits = 0u; g_anygate = 0; g_minbits = 0xFFFFFFFFu; g_median = 0.f;
        g_cs0 = g_ce0 = g_cs1 = g_ce1 = 0; g_nruns0 = g_nruns1 = 0;
        g_tail = 0; g_copy = 0; g_ncand = 0; g_npk = 0;
        g_scale = __ddiv_rn((double)S, (double)T);
    }
    for (int i = t; i < NWALK; i += blockDim.x) g_wcnt[i] = 0;
    for (int i = t; i < MAXRUNS; i += blockDim.x) { g_lastApp[i] = INT_MIN; g_opcnt[i] = 0; }
}

__global__ void K_absmax(const float* __restrict__ x, int T) {
    float m = 0.f;
    for (int i = blockIdx.x*blockDim.x + threadIdx.x; i < T; i += gridDim.x*blockDim.x)
        m = fmaxf(m, fabsf(x[i]));
    for (int o = 16; o; o >>= 1) m = fmaxf(m, __shfl_down_sync(0xFFFFFFFFu, m, o));
    if ((threadIdx.x & 31) == 0) atomicMax(&g_absbits, __float_as_uint(m));
}

// median of positives via 4-pass radix select (positive float bits are order-isomorphic to uint)
__global__ void K_median(const float* __restrict__ p, int S, const int* __restrict__ stepsPtr) {
    __shared__ int hist[256];
    __shared__ int sh_np, sh_any, sh_k;
    __shared__ unsigned sh_prefix;
    int tid = threadIdx.x;
    if (tid == 0) { sh_np = 0; sh_any = 0; }
    __syncthreads();
    int cnp = 0, cany = 0;
    for (int j = tid; j < S; j += 1024) {
        float v = p[j];
        if (v > 0.f) cnp++;
        if (v > 1e-5f) cany = 1;
    }
    for (int o = 16; o; o >>= 1) cnp += __shfl_down_sync(0xFFFFFFFFu, cnp, o);
    if ((tid & 31) == 0 && cnp) atomicAdd(&sh_np, cnp);
    if (cany) atomicOr(&sh_any, 1);
    __syncthreads();
    int npos = sh_np;
    if (npos > 0) {
        int k = (npos - 1) >> 1;
        unsigned prefix = 0, mask = 0;
        for (int by = 3; by >= 0; by--) {
            for (int i = tid; i < 256; i += 1024) hist[i] = 0;
            __syncthreads();
            for (int j = tid; j < S; j += 1024) {
                float v = p[j];
                if (v > 0.f) {
                    unsigned u = __float_as_uint(v);
                    if ((u & mask) == prefix)
                        atomicAdd(&hist[(u >> (8*by)) & 255], 1);
                }
            }
            __syncthreads();
            if (tid == 0) {
                int acc = 0, bsel = 0;
                for (; bsel < 256; bsel++) { int h = hist[bsel]; if (acc + h > k) break; acc += h; }
                sh_k = k - acc;
                sh_prefix = prefix | ((unsigned)bsel << (8*by));
            }
            __syncthreads();
            k = sh_k; prefix = sh_prefix; mask |= (255u << (8*by));
            __syncthreads();
        }
        if (tid == 0) g_median = __uint_as_float(prefix);
    }
    __syncthreads();
    if (tid == 0) {
        g_anygate = sh_any;
        double fac = pow(2.0, (double)stepsPtr[0] / 12.0);
        g_factor32 = (float)fac;
        g_mshift32 = (float)((double)g_median * fac);
    }
}

// fused: out-zero + interp + shift + minbits + mark
__global__ void K_pre(const float* __restrict__ p, const float* __restrict__ prp,
                      float* __restrict__ out, int S, int T) {
    int t = blockIdx.x*blockDim.x + threadIdx.x;
    float res = 0.f;
    if (t < T) {
        out[t] = 0.f;
        float pr = prp[0];
        float f0c = interpv(p, S, t);
        g_f0[t] = f0c;
        float fsc = shiftv(f0c, pr);
        g_f0s[t] = fsc;
        res = fsc;
        float f0m = (t > 0)     ? interpv(p, S, t-1) : 0.f;
        float f0p = (t < T-1)   ? interpv(p, S, t+1) : 0.f;
        if (f0c > 0.f) {
            bool prb = (t > 0) && (f0m > 0.f);
            bool nxb = (t < T-1) && (f0p > 0.f);
            if (!prb) { int i = atomicAdd(&g_cs0,1); if (i < MAXRUNS) g_st0[i] = t; }
            if (!nxb) { int i = atomicAdd(&g_ce0,1); if (i < MAXRUNS) g_en0[i] = t+1; }
        }
        if (fsc > 0.f) {
            float fsm = (t > 0)   ? shiftv(f0m, pr) : 0.f;
            float fsp = (t < T-1) ? shiftv(f0p, pr) : 0.f;
            bool prb = (t > 0) && (fsm > 0.f);
            bool nxb = (t < T-1) && (fsp > 0.f);
            if (!prb) { int i = atomicAdd(&g_cs1,1); if (i < MAXRUNS) g_st1[i] = t; }
            if (!nxb) { int i = atomicAdd(&g_ce1,1); if (i < MAXRUNS) g_en1[i] = t+1; }
        }
    }
    unsigned mb = (t < T && res > 0.f) ? __float_as_uint(res) : 0xFFFFFFFFu;
    for (int o = 16; o; o >>= 1) mb = min(mb, __shfl_down_sync(0xFFFFFFFFu, mb, o));
    if ((threadIdx.x & 31) == 0 && mb != 0xFFFFFFFFu) atomicMin(&g_minbits, mb);
}

__device__ void sort_small(int* a, int n) {
    for (int i = 1; i < n; i++) {
        int v = a[i], j = i-1;
        while (j >= 0 && a[j] > v) { a[j+1] = a[j]; j--; }
        a[j+1] = v;
    }
}

// sort runs in smem (fast L1-speed accesses), two independent lanes
__global__ void K_sortruns() {
    __shared__ int a0[MAXRUNS], b0[MAXRUNS], a1[MAXRUNS], b1[MAXRUNS];
    int tid = threadIdx.x;
    int ns0 = min(g_cs0, MAXRUNS), ne0 = min(g_ce0, MAXRUNS);
    int ns1 = min(g_cs1, MAXRUNS), ne1 = min(g_ce1, MAXRUNS);
    if (tid < ns0) a0[tid] = g_st0[tid];
    if (tid < ne0) b0[tid] = g_en0[tid];
    if (tid < ns1) a1[tid] = g_st1[tid];
    if (tid < ne1) b1[tid] = g_en1[tid];
    __syncthreads();
    if (tid == 0) {
        sort_small(a0, ns0); sort_small(b0, ne0);
        int n = min(ns0, ne0), off = 0;
        if (n > 0 && a0[0] == 0) { a0[0] = 1; if (a0[0] >= b0[0]) off = 1; }
        int m = 0;
        for (int k = off; k < n; k++) { g_runL0[m] = a0[k]; g_runR0[m] = b0[k]; m++; }
        g_nruns0 = m;
    } else if (tid == 32) {
        sort_small(a1, ns1); sort_small(b1, ne1);
        int n = min(ns1, ne1), off = 0;
        if (n > 0 && a1[0] == 0) { a1[0] = 1; if (a1[0] >= b1[0]) off = 1; }
        int m = 0;
        for (int k = off; k < n; k++) { g_runL1[m] = a1[k]; g_runR1[m] = b1[k]; m++; }
        g_nruns1 = m;
    }
}

__global__ void K_backup(const float* __restrict__ sig, int T) {
    __shared__ float s_rv[2][8];
    __shared__ long  s_ri[2][8];
    int run = blockIdx.x;
    if (run >= g_nruns0) return;
    int tid = threadIdx.x, lane = tid & 31, wrp = tid >> 5;
    int left = g_runL0[run], right = g_runR0[run];
    int middle = (left + right) / 2;
    double wd = __ddiv_rn(22050.0, (double)g_f0[middle]);
    long w = (wd > 2.0e9) ? 2000000000L : (long)wd;
    long s = (long)middle - w/2; if (s < 0) s = 0;
    long len = w; if (s + len > T) len = T - s;
    float mn = INFINITY, mx = -INFINITY; long imn = LONG_MAX, imx = LONG_MAX;
    for (long k = tid; k < len; k += 256) {
        float v = sig[s+k];
        if (v < mn || (v == mn && k < imn)) { mn = v; imn = k; }
        if (v > mx || (v == mx && k < imx)) { mx = v; imx = k; }
    }
    for (int o = 16; o; o >>= 1) {
        float ov = __shfl_down_sync(0xFFFFFFFFu, mn, o);
        long  oi = __shfl_down_sync(0xFFFFFFFFu, imn, o);
        if (ov < mn || (ov == mn && oi < imn)) { mn = ov; imn = oi; }
        float ov2 = __shfl_down_sync(0xFFFFFFFFu, mx, o);
        long  oi2 = __shfl_down_sync(0xFFFFFFFFu, imx, o);
        if (ov2 > mx || (ov2 == mx && oi2 < imx)) { mx = ov2; imx = oi2; }
    }
    if (lane == 0) { s_rv[0][wrp] = mn; s_ri[0][wrp] = imn; s_rv[1][wrp] = mx; s_ri[1][wrp] = imx; }
    __syncthreads();
    if (tid == 0) {
        float bmn = INFINITY, bmx = -INFINITY; long bmni = LONG_MAX, bmxi = LONG_MAX;
        for (int q = 0; q < 8; q++) {
            float v = s_rv[0][q]; long i2 = s_ri[0][q];
            if (v < bmn || (v == bmn && i2 < bmni)) { bmn = v; bmni = i2; }
            float v2 = s_rv[1][q]; long i3 = s_ri[1][q];
            if (v2 > bmx || (v2 == bmx && i3 < bmxi)) { bmx = v2; bmxi = i3; }
        }
        g_backup[run] = (bmn == bmx) ? middle
                      : (int)(s + ((fabs((double)bmn) > fabs((double)bmx)) ? bmni : bmxi));
    }
}

// Merged walk; smem window cache; per-warp max pre-reduce. Grid padded >=148 (I$ throttle).
__global__ __launch_bounds__(WTW) void K_walk(const float* __restrict__ sig, int T) {
    __shared__ float win[CACHE];
    __shared__ float s_b[MAXW];
    __shared__ float s_q[MAXC], s_ma[MAXC], s_na[MAXC];
    __shared__ int   s_cl[MAXC];
    __shared__ int   sM;
    __shared__ unsigned sEnc;
    __shared__ float s_pv[WTW/32];
    __shared__ int   s_pi[WTW/32];
    __shared__ int sGeo[12];
    int b = blockIdx.x;
    if (b >= NWALK) return;
    int dir = (b < MAXRUNS) ? 1 : 0;
    int run = dir ? b : (b - MAXRUNS);
    if (run >= g_nruns0) return;
    int tid = threadIdx.x, lane4 = tid & 3, grp = tid >> 2, wrp = tid >> 5, wl = tid & 31;
    int left = g_runL0[run], right = g_runR0[run];
    double gp = (double)__uint_as_float(g_absbits);
    long base = (long)b * CANDW;
    int cnt = 0, lastApp = INT_MIN;
    int i = 0;
    int cacheB = -1, cacheL = 0;
    if (tid == 0) i = g_backup[run];
    while (true) {
        if (tid == 0) {
            double f0i = (double)g_f0[i];
            double fm = f0i > 60.0 ? f0i : 60.0;
            int w = (int)__ddiv_rn(22050.0, fm);
            int s = i - w/2; if (s < 0) s = 0;
            int cl, cr;
            if (dir) {
                cl = (int)__dadd_rn((double)i, __dmul_rn(0.3,  (double)w));
                cr = (int)__dadd_rn((double)i, __dmul_rn(0.75, (double)w));
            } else {
                int a1 = (int)__dsub_rn((double)i, __dmul_rn(1.75, (double)w)); cl = a1 > 0 ? a1 : 0;
                int a2 = (int)__dsub_rn((double)i, __dmul_rn(1.3,  (double)w)); cr = a2 > 0 ? a2 : 0;
            }
            int valid = 0, nc = 0, base0 = 0, WL = 0, need = 0;
            if (!(cl == cr || (T - cl) < w)) {
                long hi = (long)cr + w; if (hi > T) hi = T;
                nc = (int)(hi - cl - w + 1);
                valid = (nc >= 1 && nc <= MAXC && w <= MAXW && s + w <= T);
            }
            if (valid) {
                base0 = min(s, cl);
                int e1 = s + w, e2 = cl + nc - 1 + w;
                WL = (e1 > e2 ? e1 : e2) - base0;
                if (WL > CACHE) valid = 0;
                else {
                    need = !(cacheB >= 0 && base0 >= cacheB && base0 + WL <= cacheB + cacheL);
                    if (need) {
                        int nb2;
                        if (dir) nb2 = base0;
                        else { long q0 = (long)base0 + WL - CACHE; nb2 = q0 > 0 ? (int)q0 : 0; }
                        int nl = T - nb2; if (nl > CACHE) nl = CACHE;
                        cacheB = nb2; cacheL = nl;
                    }
                }
            }
            sGeo[0]=w; sGeo[1]=s; sGeo[2]=cl; sGeo[3]=nc; sGeo[4]=valid;
            sGeo[5]=base0; sGeo[6]=WL; sGeo[8]=need; sGeo[9]=cacheB; sGeo[10]=cacheL;
            sM = 0; sEnc = fenc(-INFINITY);
        }
        __syncthreads();
        int w = sGeo[0], s = sGeo[1], cl = sGeo[2], nc = sGeo[3];
        int valid = sGeo[4];
        int cb0 = sGeo[9], clen = sGeo[10];
        if (valid) {
            if (sGeo[8]) {
                for (int k = tid; k < clen; k += WTW) win[k] = sig[cb0 + k];
                __syncthreads();
            }
            if (wrp == 0) {
                const float* rp = win + (s - cb0);
                float psq = np_psq4(rp, w, lane4);
                float nb = __shfl_sync(0xFFFFFFFFu, psq, 0);
                nb = fmaxf(__fsqrt_rn(nb), 1e-12f);
                for (int k = wl; k < w; k += 32) s_b[k] = __fdiv_rn(rp[k], nb);
            }
            __syncthreads();
            const float* cbp = win + (cl - cb0);
            int w4 = w & ~3;
            for (int c0 = 0; c0 < nc; c0 += WTW/4) {
                int c = c0 + grp;
                int cc = c < nc ? c : nc - 1;
                const float* ap = cbp + cc;
                float psq = np_psq4(ap, w, lane4);
                float na = 0.f;
                if (lane4 == 0) na = fmaxf(__fsqrt_rn(psq), 1e-12f);
                float acc = 0.f, ma = 0.f;
                for (int k = lane4; k < w4; k += 4) {
                    float v = ap[k];
                    ma = fmaxf(ma, fabsf(v));
                    acc = fmaf(v, s_b[k], acc);
                }
                float a1 = __shfl_down_sync(0xFFFFFFFFu, acc, 1, 4);
                float ssum = __fadd_rn(acc, a1);
                float a2 = __shfl_down_sync(0xFFFFFFFFu, ssum, 2, 4);
                float res = __fadd_rn(ssum, a2);
                float m1 = __shfl_down_sync(0xFFFFFFFFu, ma, 1, 4);
                ma = fmaxf(ma, m1);
                float m2 = __shfl_down_sync(0xFFFFFFFFu, ma, 2, 4);
                ma = fmaxf(ma, m2);
                float contrib = -INFINITY;
                if (lane4 == 0 && c < nc) {
                    for (int k = w4; k < w; k++) {
                        float v = ap[k];
                        ma = fmaxf(ma, fabsf(v));
                        res = fmaf(v, s_b[k], res);
                    }
                    float qv = __fdiv_rn(res, na);
                    s_q[cc] = qv;
                    s_ma[cc] = ma; s_na[cc] = na;
                    contrib = qv;
                }
                for (int o = 16; o; o >>= 1)
                    contrib = fmaxf(contrib, __shfl_down_sync(0xFFFFFFFFu, contrib, o));
                if (wl == 0) atomicMax(&sEnc, fenc(contrib));
            }
            __syncthreads();
            float bv = fdec(sEnc);
            for (int c = tid; c < nc; c += WTW) {
                if (s_q[c] >= bv - CEPS) {
                    int sl = atomicAdd(&sM, 1);
                    s_cl[sl] = c;
                } else {
                    s_q[c] = -INFINITY;
                }
            }
            __syncthreads();
            int m = sM;
            for (int j0 = 0; j0 < m; j0 += WTW/4) {
                if (j0 + (wrp << 3) < m) {
                    int ji = j0 + grp;
                    int jj = ji < m ? ji : m - 1;
                    int c = s_cl[jj];
                    const float* ap = cbp + c;
                    float na = s_na[c];
                    float acc = 0.f;
                    for (int k = lane4; k < w4; k += 4)
                        acc = fmaf(__fdiv_rn(ap[k], na), s_b[k], acc);
                    float a1 = __shfl_down_sync(0xFFFFFFFFu, acc, 1, 4);
                    float ssum = __fadd_rn(acc, a1);
                    float a2 = __shfl_down_sync(0xFFFFFFFFu, ssum, 2, 4);
                    float res = __fadd_rn(ssum, a2);
                    if (lane4 == 0 && ji < m) {
                        for (int k = w4; k < w; k++)
                            res = fmaf(__fdiv_rn(ap[k], na), s_b[k], res);
                        s_q[c] = res;
                    }
                }
            }
            __syncthreads();
            {
                float v = (tid < nc) ? s_q[tid] : -INFINITY;
                int idx = tid;
                for (int o = 16; o; o >>= 1) {
                    float vo = __shfl_down_sync(0xFFFFFFFFu, v, o);
                    int   io = __shfl_down_sync(0xFFFFFFFFu, idx, o);
                    if (vo > v || (vo == v && io < idx)) { v = vo; idx = io; }
                }
                if (wl == 0) { s_pv[wrp] = v; s_pi[wrp] = idx; }
            }
            __syncthreads();
        }
        if (tid == 0) {
            double corr = -1.0, peak = 0.0;
            int stop = 0;
            if (valid) {
                float bv2 = s_pv[0]; int br = s_pi[0];
                for (int q = 1; q < WTW/32; q++)
                    if (s_pv[q] > bv2 || (s_pv[q] == bv2 && s_pi[q] < br)) { bv2 = s_pv[q]; br = s_pi[q]; }
                corr = (double)s_q[br];
                peak = (double)s_ma[br];
                i = i + (br + cl) - s;
            }
            bool neg1 = (corr == -1.0);
            if (dir) {
                if (neg1) i += w;
                if (i >= right) {
                    if (corr > 0.7 && peak > __dmul_rn(0.023333, gp)) {
                        if (cnt < CANDW) g_wci[base+cnt] = i;
                        cnt++; lastApp = i;
                    }
                    stop = 1;
                } else if (corr > 0.3 && (peak == 0.0 || peak > __dmul_rn(0.01, gp))) {
                    if (cnt < CANDW) g_wci[base+cnt] = i;
                    cnt++; lastApp = i;
                }
            } else {
                if (neg1) i -= w;
                if (i < left) {
                    if (corr > 0.7 && peak > __dmul_rn(0.023333, gp)) {
                        if (cnt < CANDW) { g_wci[base+cnt] = i; g_wcw[base+cnt] = w; }
                        cnt++;
                    }
                    stop = 1;
                } else if (corr > 0.3 && (peak == 0.0 || peak > __dmul_rn(0.01, gp))) {
                    if (cnt < CANDW) { g_wci[base+cnt] = i; g_wcw[base+cnt] = w; }
                    cnt++;
                }
            }
            sGeo[7] = stop;
        }
        __syncthreads();
        if (sGeo[7]) break;
    }
    if (tid == 0) {
        g_wcnt[b] = min(cnt, CANDW);
        if (dir) g_lastApp[run] = lastApp;
    }
}

// merged filter + collect; warp-per-slot parallel copy
__global__ void K_filtcollect() {
    __shared__ long sAR[MAXRUNS];
    __shared__ int s_cnt[NWALK], s_off[NWALK];
    int tid = threadIdx.x, wrp = tid >> 5, wl = tid & 31;
    int nr = g_nruns0;
    if (tid == 0) {
        long cur = LONG_MIN / 4;
        for (int r = 0; r < nr; r++) {
            sAR[r] = cur;
            if (g_lastApp[r] != INT_MIN) cur = (long)g_lastApp[r];
        }
    }
    __syncthreads();
    if (tid < nr) {
        long base = (long)(MAXRUNS + tid) * CANDW;
        int c = g_wcnt[MAXRUNS + tid], m = 0;
        long AR = sAR[tid];
        for (int j = 0; j < c; j++) {
            int i = g_wci[base + j], w = g_wcw[base + j];
            bool pass;
            if (AR <= LONG_MIN / 8) pass = true;
            else pass = 5L * ((long)i - AR) > 4L * (long)w;
            if (pass) { g_wci[base + m] = i; m++; }
        }
        g_wcnt[MAXRUNS + tid] = m;
    }
    __syncthreads();
    for (int i = tid; i < NWALK; i += 256) s_cnt[i] = g_wcnt[i];
    __syncthreads();
    if (tid == 0) {
        int acc = 0;
        for (int sl = 0; sl < NWALK; sl++) { s_off[sl] = acc; acc += s_cnt[sl]; }
        g_ncand = min(acc, MAXPK);
    }
    __syncthreads();
    for (int sl = wrp; sl < NWALK; sl += 8) {
        int c = s_cnt[sl], o = s_off[sl];
        for (int j = wl; j < c; j += 32)
            if (o + j < MAXPK) g_cand[o+j] = g_wci[(long)sl*CANDW + j];
    }
}

__global__ void K_rank(int T) {
    int N = g_ncand;
    for (int j = blockIdx.x*blockDim.x + threadIdx.x; j < N; j += gridDim.x*blockDim.x) {
        int v = g_cand[j], rk = 0;
        for (int k = 0; k < N; k++) {
            int u = g_cand[k];
            rk += (u < v) || (u == v && k < j);
        }
        int cv = v; if (cv < 0) cv = 0; if (cv > T-1) cv = T-1;
        g_peaks[rk] = cv;
    }
    if (blockIdx.x == 0 && threadIdx.x == 0) g_npk = N;
}

__device__ void plan_run3(const int* __restrict__ pk, int npk, int r, int T, float minpos) {
    int left_v = g_runL1[r], right_v = g_runR1[r];
    int prevR = (r == 0) ? 0 : g_runR1[r-1];
    int cnt = 0, base = r * OPR;
    if (prevR < left_v) {
        if (cnt < OPR) {
            g_opd[base+cnt] = prevR; g_opsrc[base+cnt] = prevR;
            g_opl[base+cnt] = left_v - prevR; g_opn[base+cnt] = left_v - prevR;
        }
        cnt++;
    }
    int q = dev_lb(pk, npk, left_v);
    while (left_v < right_v) {
        while (q < npk && pk[q] < left_v) q++;
        int p;
        if (q == 0) p = 0;
        else if (q >= npk) {
            p = npk - 1;
            int v = pk[npk-1];
            while (p > 0 && pk[p-1] == v) p--;
        } else {
            long d1 = (long)left_v - pk[q-1], d2 = (long)pk[q] - left_v;
            if (d1 <= d2) {
                p = q - 1;
                int v = pk[q-1];
                while (p > 0 && pk[p-1] == v) p--;
            } else p = q;
        }
        float fv = g_f0s[left_v];
        float fm = fv > 60.f ? fv : 60.f;
        int period = floor_div_22050(fm);
        int left_w = period/2, right_w = period/2;
        if (p > 0) {
            long d = (long)pk[p] - pk[p-1];
            if (dmul_le_maxw(d, minpos)) left_w = min((int)d, left_w);
        }
        if (p < npk-1) {
            long d = (long)pk[p+1] - pk[p];
            if (dmul_le_maxw(d, minpos)) right_w = min((int)d, right_w);
        }
        int left_i = pk[p] - left_w; if (left_i < 0) left_i = 0;
        int right_i = pk[p] + right_w;
        int ival = (right_i - left_i) / 2;
        if (ival <= 0) break;
        long a = (long)left_v - ival;
        int seglen = min(pyslen(a, (long)left_v + ival, T),
                         pyslen(left_i, (long)left_i + 2L*ival, T));
        int Ld = pyslen(a, a + seglen, T);
        int Ls = pyslen(left_i, (long)left_i + seglen, T);
        int L = min(min(Ld, Ls), seglen);
        if (cnt < OPR) {
            long as_ = a < 0 ? a + T : a;
            g_opd[base+cnt] = (int)as_; g_opsrc[base+cnt] = left_i;
            g_opl[base+cnt] = L; g_opn[base+cnt] = 2*ival;
        }
        cnt++;
        left_v += ival * 2;
    }
    g_opcnt[r] = min(cnt, OPR);
}

__global__ __launch_bounds__(256) void K_plan(int T) {
    __shared__ int s_pk[PCAP];
    __shared__ float s_minpos;
    int tid = threadIdx.x;
    if (tid == 0) {
        g_copy = (!g_anygate || g_npk == 0) ? 1 : 0;
        s_minpos = __uint_as_float(g_minbits);
        g_tail = 0;
    }
    __syncthreads();
    if (g_copy) return;
    int npk = g_npk;
    const int* pk = g_peaks;
    if (npk <= PCAP) {
        for (int i = tid; i < npk; i += 256) s_pk[i] = g_peaks[i];
        pk = s_pk;
    }
    __syncthreads();
    int nr = g_nruns1;
    if (tid == 0 && nr > 0) g_tail = g_runR1[nr-1];
    if (tid < nr) plan_run3(pk, npk, tid, T, s_minpos);
}

__global__ void K_apply(const float* __restrict__ snd, float* __restrict__ out, int T) {
    int nr = g_nruns1;
    if (g_copy) return;
    for (int b = blockIdx.x; b < nr * OPR; b += gridDim.x) {
        int r = b / OPR, j = b % OPR;
        if (j >= g_opcnt[r]) continue;
        int o = r * OPR + j;
        int d0 = g_opd[o], s0 = g_opsrc[o], L = g_opl[o], n = g_opn[o];
        float invn = 6.2831853071795864f / (float)n;
        for (int k = threadIdx.x; k < L; k += blockDim.x) {
            float wf = 0.5f - 0.5f * cosf((float)k * invn);
            atomicAdd(out + d0 + k, wf * snd[s0 + k]);
        }
    }
}

__global__ void K_tail(const float* __restrict__ snd, float* __restrict__ out, int T) {
    int t = blockIdx.x*blockDim.x + threadIdx.x;
    if (t >= T) return;
    if (g_copy || t >= g_tail) out[t] = snd[t];
}

extern "C" void kernel_launch(void* const* d_in, const int* in_sizes, int n_in,
                              void* d_out, int out_size) {
    const float* snd   = (const float*)d_in[0];
    const float* pitch = (const float*)d_in[1];
    const int*   steps = (const int*)d_in[2];
    const float* prng  = (const float*)d_in[3];
    float* out = (float*)d_out;
    int T = in_sizes[0];
    int S = in_sizes[1];

    K_init<<<1,256>>>(S, T);
    K_absmax<<<512,256>>>(snd, T);
    K_median<<<1,1024>>>(pitch, S, steps);
    K_pre<<<GRID(T,256),256>>>(pitch, prng, out, S, T);
    K_sortruns<<<1,64>>>();
    K_backup<<<MAXRUNS,256>>>(snd, T);
    K_walk<<<WGRID,WTW>>>(snd, T);
    K_filtcollect<<<1,256>>>();
    K_rank<<<64,256>>>(T);
    K_plan<<<1,256>>>(T);
    K_apply<<<2048,128>>>(snd, out, T);
    K_tail<<<GRID(T,256),256>>>(snd, out, T);
}